// round 9
// baseline (speedup 1.0000x reference)
#include <cuda_runtime.h>
#include <cuda_bf16.h>
#include <math.h>
#include <cstdint>

// ---------------------------------------------------------------------------
// Problem constants: B=2, S=2048, D=2048, H=16, DH=128
// ---------------------------------------------------------------------------
#define BB 2
#define SS 2048
#define DD 2048
#define HH 16
#define DHH 128
#define NTOK (BB * SS)          // 4096
#define QKV_N (3 * DD)          // 6144
#define LN_EPS 1e-5f

// ---------------------------------------------------------------------------
// Scratch (device globals; allocation forbidden)
// ---------------------------------------------------------------------------
__device__ __nv_bfloat16 g_xln_hi[(size_t)NTOK * DD];
__device__ __nv_bfloat16 g_xln_lo[(size_t)NTOK * DD];
__device__ float         g_qkv[(size_t)NTOK * QKV_N];     // 100.7 MB
__device__ __nv_bfloat16 g_wqkvT_hi[(size_t)QKV_N * DD];
__device__ __nv_bfloat16 g_wqkvT_lo[(size_t)QKV_N * DD];
__device__ __nv_bfloat16 g_woutT_hi[(size_t)DD * DD];
__device__ __nv_bfloat16 g_woutT_lo[(size_t)DD * DD];
__device__ __nv_bfloat16 g_attn_hi[(size_t)NTOK * DD];
__device__ __nv_bfloat16 g_attn_lo[(size_t)NTOK * DD];
// pre-split attention operands, per-head layouts
__device__ __nv_bfloat16 g_qh[(size_t)NTOK * DD];   // [b][h][s][d]
__device__ __nv_bfloat16 g_ql[(size_t)NTOK * DD];
__device__ __nv_bfloat16 g_kh[(size_t)NTOK * DD];
__device__ __nv_bfloat16 g_kl[(size_t)NTOK * DD];
__device__ __nv_bfloat16 g_vth[(size_t)NTOK * DD];  // [b][h][d][s]
__device__ __nv_bfloat16 g_vtl[(size_t)NTOK * DD];

// ---------------------------------------------------------------------------
// helpers
// ---------------------------------------------------------------------------
__device__ __forceinline__ uint32_t smem_u32(const void* p) {
    uint32_t a;
    asm("{ .reg .u64 t; cvta.to.shared.u64 t, %1; cvt.u32.u64 %0, t; }"
        : "=r"(a) : "l"(p));
    return a;
}

__device__ __forceinline__ void cpa16(uint32_t dst, const void* src) {
    asm volatile("cp.async.cg.shared.global [%0], [%1], 16;" :: "r"(dst), "l"(src) : "memory");
}
#define CP_COMMIT() asm volatile("cp.async.commit_group;" ::: "memory")
#define CP_WAIT1()  asm volatile("cp.async.wait_group 1;" ::: "memory")
#define CP_WAIT0()  asm volatile("cp.async.wait_group 0;" ::: "memory")

__device__ __forceinline__ void mma_bf16(float* c, const uint32_t* a, const uint32_t* b) {
    asm volatile(
        "mma.sync.aligned.m16n8k16.row.col.f32.bf16.bf16.f32 "
        "{%0,%1,%2,%3}, {%4,%5,%6,%7}, {%8,%9}, {%0,%1,%2,%3};"
        : "+f"(c[0]), "+f"(c[1]), "+f"(c[2]), "+f"(c[3])
        : "r"(a[0]), "r"(a[1]), "r"(a[2]), "r"(a[3]), "r"(b[0]), "r"(b[1]));
}

__device__ __forceinline__ void ldm_x4(uint32_t* r, uint32_t addr) {
    asm volatile("ldmatrix.sync.aligned.m8n8.x4.shared.b16 {%0,%1,%2,%3}, [%4];"
        : "=r"(r[0]), "=r"(r[1]), "=r"(r[2]), "=r"(r[3]) : "r"(addr));
}

__device__ __forceinline__ void split2(float v, __nv_bfloat16& h, __nv_bfloat16& l) {
    h = __float2bfloat16(v);
    l = __float2bfloat16(v - __bfloat162float(h));
}

__device__ __forceinline__ uint32_t packbf(__nv_bfloat16 a, __nv_bfloat16 b) {
    __nv_bfloat162 t(a, b);   // a = low element
    return *(uint32_t*)&t;
}

// ---------------------------------------------------------------------------
// LayerNorm -> bf16 hi/lo split outputs
// ---------------------------------------------------------------------------
__global__ __launch_bounds__(256) void ln_kernel(const float* __restrict__ x,
                                                 __nv_bfloat16* __restrict__ yh,
                                                 __nv_bfloat16* __restrict__ yl) {
    __shared__ float red_s[8], red_ss[8];
    __shared__ float sh_mu, sh_rstd;
    const int row = blockIdx.x;
    const int tid = threadIdx.x;
    const float* xr = x + (size_t)row * DD;

    float4 a = *(const float4*)(xr + tid * 4);
    float4 b = *(const float4*)(xr + 1024 + tid * 4);
    float s  = a.x + a.y + a.z + a.w + b.x + b.y + b.z + b.w;
    float ss = a.x*a.x + a.y*a.y + a.z*a.z + a.w*a.w
             + b.x*b.x + b.y*b.y + b.z*b.z + b.w*b.w;
    #pragma unroll
    for (int o = 16; o > 0; o >>= 1) {
        s  += __shfl_xor_sync(0xffffffffu, s, o);
        ss += __shfl_xor_sync(0xffffffffu, ss, o);
    }
    const int wid = tid >> 5, lane = tid & 31;
    if (lane == 0) { red_s[wid] = s; red_ss[wid] = ss; }
    __syncthreads();
    if (tid == 0) {
        float S = 0.f, SSq = 0.f;
        #pragma unroll
        for (int w = 0; w < 8; w++) { S += red_s[w]; SSq += red_ss[w]; }
        float mu = S * (1.0f / DD);
        float var = SSq * (1.0f / DD) - mu * mu;
        sh_mu = mu;
        sh_rstd = rsqrtf(var + LN_EPS);
    }
    __syncthreads();
    const float mu = sh_mu, rstd = sh_rstd;
    float va[8] = {a.x, a.y, a.z, a.w, b.x, b.y, b.z, b.w};
    #pragma unroll
    for (int e = 0; e < 8; e++) {
        float v = (va[e] - mu) * rstd;
        __nv_bfloat16 h, l;
        split2(v, h, l);
        size_t col = (e < 4) ? (tid * 4 + e) : (1024 + tid * 4 + e - 4);
        yh[(size_t)row * DD + col] = h;
        yl[(size_t)row * DD + col] = l;
    }
}

// ---------------------------------------------------------------------------
// Transpose + split: W[K][N] fp32 -> hi/lo bf16 [N][K]
// ---------------------------------------------------------------------------
__global__ __launch_bounds__(256) void transpose_split(const float* __restrict__ W,
                                                       __nv_bfloat16* __restrict__ hi,
                                                       __nv_bfloat16* __restrict__ lo,
                                                       int K, int N) {
    __shared__ float t[32][33];
    int n = blockIdx.x * 32 + threadIdx.x;
    int k = blockIdx.y * 32 + threadIdx.y;
    #pragma unroll
    for (int i = 0; i < 4; i++)
        t[threadIdx.y + 8 * i][threadIdx.x] = W[(size_t)(k + 8 * i) * N + n];
    __syncthreads();
    int ko = blockIdx.y * 32 + threadIdx.x;
    int no = blockIdx.x * 32 + threadIdx.y;
    #pragma unroll
    for (int i = 0; i < 4; i++) {
        float v = t[threadIdx.x][threadIdx.y + 8 * i];
        __nv_bfloat16 h, l;
        split2(v, h, l);
        size_t o = (size_t)(no + 8 * i) * K + ko;
        hi[o] = h;
        lo[o] = l;
    }
}

// ---------------------------------------------------------------------------
// mma.sync split-bf16 GEMM v3 (unchanged — proven)
// ---------------------------------------------------------------------------
#define BM 128
#define BN 256
#define BKC 32
#define ROWB 80
#define A_TILE (128 * ROWB)
#define B_TILE (256 * ROWB)
#define STAGE_B (2 * A_TILE + 2 * B_TILE)
#define NSTAGE 3
#define GEMM_SMEM (NSTAGE * STAGE_B)

__global__ __launch_bounds__(256, 1) void gemm_mma(
    const __nv_bfloat16* __restrict__ Ahi, const __nv_bfloat16* __restrict__ Alo,
    const __nv_bfloat16* __restrict__ Bhi, const __nv_bfloat16* __restrict__ Blo,
    float* __restrict__ C, int M, int N, int K)
{
    extern __shared__ __align__(16) char smem[];
    const uint32_t sb = smem_u32(smem);
    const int tid = threadIdx.x;
    const int wid = tid >> 5;
    const int lane = tid & 31;
    const int m0 = blockIdx.y * BM;
    const int n0 = blockIdx.x * BN;
    const int wm = (wid & 1) * 64;
    const int wn = (wid >> 1) * 64;

    float acc[4][8][4];
    #pragma unroll
    for (int mi = 0; mi < 4; mi++)
        #pragma unroll
        for (int ni = 0; ni < 8; ni++)
            #pragma unroll
            for (int e = 0; e < 4; e++) acc[mi][ni][e] = 0.f;

    auto fill = [&](int stage, int k0) {
        const uint32_t sbase = sb + stage * STAGE_B;
        #pragma unroll
        for (int it = 0; it < 12; it++) {
            int i = it * 256 + tid;
            const __nv_bfloat16* src;
            uint32_t dst;
            if (i < 1024) {
                int op = i >> 9, r = (i >> 2) & 127, c = i & 3;
                src = (op ? Alo : Ahi) + (size_t)(m0 + r) * K + k0 + c * 8;
                dst = sbase + op * A_TILE + r * ROWB + c * 16;
            } else {
                int j = i - 1024;
                int op = j >> 10, r = (j >> 2) & 255, c = j & 3;
                src = (op ? Blo : Bhi) + (size_t)(n0 + r) * K + k0 + c * 8;
                dst = sbase + 2 * A_TILE + op * B_TILE + r * ROWB + c * 16;
            }
            cpa16(dst, src);
        }
        CP_COMMIT();
    };

    const int nch = K / BKC;
    fill(0, 0);
    fill(1, BKC);

    const int lg = lane >> 3;
    const int lr = lane & 7;

    for (int c = 0; c < nch; c++) {
        if (c + 1 < nch) CP_WAIT1(); else CP_WAIT0();
        __syncthreads();

        if (c + 2 < nch) fill((c + 2) % NSTAGE, (c + 2) * BKC);

        const uint32_t sbase = sb + (c % NSTAGE) * STAGE_B;
        const uint32_t aHi = sbase;
        const uint32_t aLo = sbase + A_TILE;
        const uint32_t bHi = sbase + 2 * A_TILE;
        const uint32_t bLo = sbase + 2 * A_TILE + B_TILE;

        #pragma unroll
        for (int ks = 0; ks < 2; ks++) {
            const uint32_t koff = ks * 32;

            const uint32_t aoff = (lg & 1) * 8 * ROWB + (lg >> 1) * 16 + lr * ROWB + koff;
            uint32_t ah[4][4], al[4][4];
            #pragma unroll
            for (int mi = 0; mi < 4; mi++) {
                uint32_t ro = (wm + mi * 16) * ROWB + aoff;
                ldm_x4(ah[mi], aHi + ro);
                ldm_x4(al[mi], aLo + ro);
            }
            const uint32_t boff = (lg >> 1) * 8 * ROWB + (lg & 1) * 16 + lr * ROWB + koff;
            uint32_t bh[8][2], bl[8][2];
            #pragma unroll
            for (int np = 0; np < 4; np++) {
                uint32_t ro = (wn + np * 16) * ROWB + boff;
                uint32_t t4[4];
                ldm_x4(t4, bHi + ro);
                bh[2 * np][0] = t4[0]; bh[2 * np][1] = t4[1];
                bh[2 * np + 1][0] = t4[2]; bh[2 * np + 1][1] = t4[3];
                ldm_x4(t4, bLo + ro);
                bl[2 * np][0] = t4[0]; bl[2 * np][1] = t4[1];
                bl[2 * np + 1][0] = t4[2]; bl[2 * np + 1][1] = t4[3];
            }

            #pragma unroll
            for (int mi = 0; mi < 4; mi++)
                #pragma unroll
                for (int ni = 0; ni < 8; ni++)
                    mma_bf16(acc[mi][ni], ah[mi], bh[ni]);
            #pragma unroll
            for (int mi = 0; mi < 4; mi++)
                #pragma unroll
                for (int ni = 0; ni < 8; ni++)
                    mma_bf16(acc[mi][ni], ah[mi], bl[ni]);
            #pragma unroll
            for (int mi = 0; mi < 4; mi++)
                #pragma unroll
                for (int ni = 0; ni < 8; ni++)
                    mma_bf16(acc[mi][ni], al[mi], bh[ni]);
        }
    }

    const int r4 = lane >> 2;
    const int k4 = lane & 3;
    #pragma unroll
    for (int mi = 0; mi < 4; mi++) {
        int r0 = m0 + wm + mi * 16 + r4;
        #pragma unroll
        for (int ni = 0; ni < 8; ni++) {
            int cc = n0 + wn + ni * 8 + k4 * 2;
            float2 v0 = {acc[mi][ni][0], acc[mi][ni][1]};
            float2 v1 = {acc[mi][ni][2], acc[mi][ni][3]};
            *(float2*)(C + (size_t)r0 * N + cc) = v0;
            *(float2*)(C + (size_t)(r0 + 8) * N + cc) = v1;
        }
    }
}

// ---------------------------------------------------------------------------
// RoPE + split for Q,K: fp32 qkv -> per-head K-major bf16 hi/lo [b][h][s][d]
// ---------------------------------------------------------------------------
__global__ __launch_bounds__(256) void rope_split(const float* __restrict__ qkv,
                                                  __nv_bfloat16* __restrict__ qh,
                                                  __nv_bfloat16* __restrict__ ql,
                                                  __nv_bfloat16* __restrict__ kh,
                                                  __nv_bfloat16* __restrict__ kl) {
    const int t = blockIdx.x;            // token
    const int b = t / SS, s = t % SS;
    const int tid = threadIdx.x;

    #pragma unroll
    for (int w = 0; w < 4; w++) {
        int idx = w * 256 + tid;          // (h, dpair)
        int h = idx >> 6, dp = idx & 63;

        float inv_freq = powf(10000.0f, -(float)dp * (1.0f / 64.0f));
        float ang = (float)s * inv_freq;
        float c = cosf(ang), sn = sinf(ang);

        const float* src = qkv + (size_t)t * QKV_N + h * DHH;
        size_t obase = ((size_t)(b * HH + h) * SS + s) * DHH;
        __nv_bfloat16 hh, ll;

        // q
        float x1 = src[dp], x2 = src[dp + 64];
        float r1 = x1 * c - x2 * sn;
        float r2 = x2 * c + x1 * sn;
        split2(r1, hh, ll); qh[obase + dp] = hh;      ql[obase + dp] = ll;
        split2(r2, hh, ll); qh[obase + dp + 64] = hh; ql[obase + dp + 64] = ll;

        // k
        x1 = src[DD + dp]; x2 = src[DD + dp + 64];
        r1 = x1 * c - x2 * sn;
        r2 = x2 * c + x1 * sn;
        split2(r1, hh, ll); kh[obase + dp] = hh;      kl[obase + dp] = ll;
        split2(r2, hh, ll); kh[obase + dp + 64] = hh; kl[obase + dp + 64] = ll;
    }
}

// ---------------------------------------------------------------------------
// V transpose + split: fp32 qkv v-slice -> [b][h][d][s] bf16 hi/lo
// ---------------------------------------------------------------------------
__global__ __launch_bounds__(256) void v_split_transpose(const float* __restrict__ qkv,
                                                         __nv_bfloat16* __restrict__ vth,
                                                         __nv_bfloat16* __restrict__ vtl) {
    __shared__ float sm[64 * 132];
    const int s0 = blockIdx.x * 64;
    const int h  = blockIdx.y;
    const int b  = blockIdx.z;
    const int tid = threadIdx.x;

    #pragma unroll
    for (int i = 0; i < 32; i++) {
        int idx = i * 256 + tid;
        int sl = idx >> 7, d = idx & 127;
        sm[sl * 132 + d] = qkv[((size_t)(b * SS + s0 + sl)) * QKV_N + 2 * DD + h * DHH + d];
    }
    __syncthreads();

    const int d = tid >> 1;
    const int sh = (tid & 1) * 32;
    size_t row = ((size_t)(b * HH + h) * DHH + d) * SS + s0 + sh;
    #pragma unroll
    for (int j = 0; j < 32; j += 2) {
        float v0 = sm[(sh + j) * 132 + d];
        float v1 = sm[(sh + j + 1) * 132 + d];
        __nv_bfloat16 h0, l0, h1, l1;
        split2(v0, h0, l0); split2(v1, h1, l1);
        *(uint32_t*)(vth + row + j) = packbf(h0, h1);
        *(uint32_t*)(vtl + row + j) = packbf(l0, l1);
    }
}

// ---------------------------------------------------------------------------
// Flash attention v5: 128-row Q tile, double-buffered K/V with conservative
// wait discipline, plain smem addressing. Compute core identical to flash3.
// ---------------------------------------------------------------------------
#define QROW 272
#define VROW 144
#define F5_QH 0
#define F5_QL (128 * QROW)                 // 34816
#define F5_ST0 (2 * 128 * QROW)            // 69632
#define F5_KH_OFF 0
#define F5_KL_OFF (64 * QROW)              // 17408
#define F5_VH_OFF (2 * 64 * QROW)          // 34816
#define F5_VL_OFF (F5_VH_OFF + 128 * VROW) // 53248
#define F5_STG (F5_VL_OFF + 128 * VROW)    // 71680
#define FLASH5_SMEM (F5_ST0 + 2 * F5_STG)  // 212992 bytes

__global__ __launch_bounds__(256) void flash5_kernel(
    const __nv_bfloat16* __restrict__ qh, const __nv_bfloat16* __restrict__ ql,
    const __nv_bfloat16* __restrict__ kh, const __nv_bfloat16* __restrict__ kl,
    const __nv_bfloat16* __restrict__ vth, const __nv_bfloat16* __restrict__ vtl,
    __nv_bfloat16* __restrict__ attn_hi, __nv_bfloat16* __restrict__ attn_lo)
{
    extern __shared__ __align__(16) char smem[];
    const uint32_t sb = smem_u32(smem);

    const int qb = blockIdx.x;         // 128-row q block
    const int h  = blockIdx.y;
    const int b  = blockIdx.z;
    const int tid = threadIdx.x;
    const int wid = tid >> 5;          // 0..7
    const int lane = tid & 31;
    const int r4 = lane >> 2;
    const int k4 = lane & 3;

    const size_t bh = (size_t)(b * HH + h);
    const __nv_bfloat16* qhp = qh + (bh * SS + qb * 128) * DHH;
    const __nv_bfloat16* qlp = ql + (bh * SS + qb * 128) * DHH;

    // ---- load Q tile (128 x 128, pre-split hi/lo), plain stores ----
    for (int i = tid; i < 4096; i += 256) {
        int op = i >> 11, j = i & 2047;
        int row = j >> 4, c = j & 15;
        const __nv_bfloat16* src = (op ? qlp : qhp) + row * DHH + c * 8;
        uint4 v = *(const uint4*)src;
        *(uint4*)(smem + (op ? F5_QL : F5_QH) + row * QROW + c * 16) = v;
    }

    // K/V stage fill via cp.async (one commit group per call)
    auto fillkv = [&](int s, int kt) {
        const __nv_bfloat16* khp = kh + (bh * SS + kt * 64) * DHH;
        const __nv_bfloat16* klp = kl + (bh * SS + kt * 64) * DHH;
        const __nv_bfloat16* vhp = vth + bh * DHH * SS + kt * 64;
        const __nv_bfloat16* vlp = vtl + bh * DHH * SS + kt * 64;
        const uint32_t kbase = sb + F5_ST0 + s * F5_STG;
        #pragma unroll
        for (int it = 0; it < 16; it++) {
            int i = it * 256 + tid;       // 4096 x 16B chunks
            if (i < 2048) {
                int op = i >> 10, j = i & 1023;
                int row = j >> 4, c = j & 15;
                cpa16(kbase + (op ? F5_KL_OFF : F5_KH_OFF) + row * QROW + c * 16,
                      (op ? klp : khp) + row * DHH + c * 8);
            } else {
                int i2 = i - 2048;
                int op = i2 >> 10, j = i2 & 1023;
                int d = j >> 3, c = j & 7;
                cpa16(kbase + (op ? F5_VL_OFF : F5_VH_OFF) + d * VROW + c * 16,
                      (op ? vlp : vhp) + (size_t)d * SS + c * 8);
            }
        }
        CP_COMMIT();
    };

    float oacc[16][4];
    #pragma unroll
    for (int n = 0; n < 16; n++)
        #pragma unroll
        for (int e = 0; e < 4; e++) oacc[n][e] = 0.f;

    float m0 = -1e30f, m1 = -1e30f, l0 = 0.f, l1 = 0.f;
    const float scale = 0.088388347648318447f;
    const int arow = wid * 16 + r4;
    const int nkt = 2 * qb + 2;

    fillkv(0, 0);

    for (int kt = 0; kt < nkt; kt++) {
        // Issue next tile's fill first (its stage was released by the trailing
        // barrier of iteration kt-1), then wait so that the OLDEST pending
        // group (tile kt) is complete. Final iteration: drain everything.
        if (kt + 1 < nkt) {
            fillkv((kt + 1) & 1, kt + 1);
            CP_WAIT1();
        } else {
            CP_WAIT0();
        }
        __syncthreads();   // tile kt visible to all warps (and Q on iter 0)

        const char* stp = smem + F5_ST0 + (kt & 1) * F5_STG;

        // ---- S = Q K^T (split 3-term) ----
        float sacc[8][4];
        #pragma unroll
        for (int n = 0; n < 8; n++)
            #pragma unroll
            for (int e = 0; e < 4; e++) sacc[n][e] = 0.f;

        #pragma unroll
        for (int kb = 0; kb < 8; kb++) {
            const uint32_t koff = kb * 32 + k4 * 4;
            uint32_t ah[4], al[4];
            ah[0] = *(const uint32_t*)(smem + F5_QH + arow * QROW + koff);
            ah[1] = *(const uint32_t*)(smem + F5_QH + (arow + 8) * QROW + koff);
            ah[2] = *(const uint32_t*)(smem + F5_QH + arow * QROW + koff + 16);
            ah[3] = *(const uint32_t*)(smem + F5_QH + (arow + 8) * QROW + koff + 16);
            al[0] = *(const uint32_t*)(smem + F5_QL + arow * QROW + koff);
            al[1] = *(const uint32_t*)(smem + F5_QL + (arow + 8) * QROW + koff);
            al[2] = *(const uint32_t*)(smem + F5_QL + arow * QROW + koff + 16);
            al[3] = *(const uint32_t*)(smem + F5_QL + (arow + 8) * QROW + koff + 16);
            #pragma unroll
            for (int ng = 0; ng < 8; ng++) {
                const uint32_t bro = (ng * 8 + r4) * QROW + koff;
                uint32_t bh2[2], bl2[2];
                bh2[0] = *(const uint32_t*)(stp + F5_KH_OFF + bro);
                bh2[1] = *(const uint32_t*)(stp + F5_KH_OFF + bro + 16);
                bl2[0] = *(const uint32_t*)(stp + F5_KL_OFF + bro);
                bl2[1] = *(const uint32_t*)(stp + F5_KL_OFF + bro + 16);
                mma_bf16(sacc[ng], ah, bh2);
                mma_bf16(sacc[ng], ah, bl2);
                mma_bf16(sacc[ng], al, bh2);
            }
        }

        const int row0 = qb * 128 + wid * 16 + r4;
        if (kt >= 2 * qb) {
            #pragma unroll
            for (int ng = 0; ng < 8; ng++) {
                int colb = kt * 64 + ng * 8 + k4 * 2;
                sacc[ng][0] = (colb     > row0)     ? -1e30f : sacc[ng][0] * scale;
                sacc[ng][1] = (colb + 1 > row0)     ? -1e30f : sacc[ng][1] * scale;
                sacc[ng][2] = (colb     > row0 + 8) ? -1e30f : sacc[ng][2] * scale;
                sacc[ng][3] = (colb + 1 > row0 + 8) ? -1e30f : sacc[ng][3] * scale;
            }
        } else {
            #pragma unroll
            for (int ng = 0; ng < 8; ng++)
                #pragma unroll
                for (int e = 0; e < 4; e++) sacc[ng][e] *= scale;
        }

        float mx0 = -1e30f, mx1 = -1e30f;
        #pragma unroll
        for (int ng = 0; ng < 8; ng++) {
            mx0 = fmaxf(mx0, fmaxf(sacc[ng][0], sacc[ng][1]));
            mx1 = fmaxf(mx1, fmaxf(sacc[ng][2], sacc[ng][3]));
        }
        mx0 = fmaxf(mx0, __shfl_xor_sync(0xffffffffu, mx0, 1));
        mx0 = fmaxf(mx0, __shfl_xor_sync(0xffffffffu, mx0, 2));
        mx1 = fmaxf(mx1, __shfl_xor_sync(0xffffffffu, mx1, 1));
        mx1 = fmaxf(mx1, __shfl_xor_sync(0xffffffffu, mx1, 2));

        float mn0 = fmaxf(m0, mx0), mn1 = fmaxf(m1, mx1);
        float c0 = __expf(m0 - mn0), c1 = __expf(m1 - mn1);
        m0 = mn0; m1 = mn1;

        float sum0 = 0.f, sum1 = 0.f;
        uint32_t ph2[8][2], pl2[8][2];
        #pragma unroll
        for (int ng = 0; ng < 8; ng++) {
            float p0 = __expf(sacc[ng][0] - m0);
            float p1 = __expf(sacc[ng][1] - m0);
            float p2 = __expf(sacc[ng][2] - m1);
            float p3 = __expf(sacc[ng][3] - m1);
            sum0 += p0 + p1; sum1 += p2 + p3;
            __nv_bfloat16 a, bq, cc, dd2, la, lb, lc, ld;
            split2(p0, a, la); split2(p1, bq, lb);
            split2(p2, cc, lc); split2(p3, dd2, ld);
            ph2[ng][0] = packbf(a, bq);  ph2[ng][1] = packbf(cc, dd2);
            pl2[ng][0] = packbf(la, lb); pl2[ng][1] = packbf(lc, ld);
        }
        sum0 += __shfl_xor_sync(0xffffffffu, sum0, 1);
        sum0 += __shfl_xor_sync(0xffffffffu, sum0, 2);
        sum1 += __shfl_xor_sync(0xffffffffu, sum1, 1);
        sum1 += __shfl_xor_sync(0xffffffffu, sum1, 2);
        l0 = l0 * c0 + sum0;
        l1 = l1 * c1 + sum1;

        #pragma unroll
        for (int n = 0; n < 16; n++) {
            oacc[n][0] *= c0; oacc[n][1] *= c0;
            oacc[n][2] *= c1; oacc[n][3] *= c1;
        }

        #pragma unroll
        for (int kb = 0; kb < 4; kb++) {
            uint32_t pa[4] = {ph2[2*kb][0], ph2[2*kb][1], ph2[2*kb+1][0], ph2[2*kb+1][1]};
            uint32_t pb[4] = {pl2[2*kb][0], pl2[2*kb][1], pl2[2*kb+1][0], pl2[2*kb+1][1]};
            const uint32_t koff = kb * 32 + k4 * 4;
            #pragma unroll
            for (int ng = 0; ng < 16; ng++) {
                const uint32_t vro = (ng * 8 + r4) * VROW + koff;
                uint32_t vh[2], vl[2];
                vh[0] = *(const uint32_t*)(stp + F5_VH_OFF + vro);
                vh[1] = *(const uint32_t*)(stp + F5_VH_OFF + vro + 16);
                vl[0] = *(const uint32_t*)(stp + F5_VL_OFF + vro);
                vl[1] = *(const uint32_t*)(stp + F5_VL_OFF + vro + 16);
                mma_bf16(oacc[ng], pa, vh);
                mma_bf16(oacc[ng], pa, vl);
                mma_bf16(oacc[ng], pb, vh);
            }
        }

        __syncthreads();   // all warps done reading stage kt&1 before the
                           // next iteration's fill overwrites it
    }

    const float inv0 = 1.0f / l0, inv1 = 1.0f / l1;
    const int grow0 = b * SS + qb * 128 + wid * 16 + r4;
    #pragma unroll
    for (int ng = 0; ng < 16; ng++) {
        size_t o0 = (size_t)grow0 * DD + h * DHH + ng * 8 + k4 * 2;
        size_t o1 = o0 + (size_t)8 * DD;
        float v0 = oacc[ng][0] * inv0, v1 = oacc[ng][1] * inv0;
        float v2 = oacc[ng][2] * inv1, v3 = oacc[ng][3] * inv1;
        __nv_bfloat16 h0, l0b, h1, l1b, h2, l2b, h3, l3b;
        split2(v0, h0, l0b); split2(v1, h1, l1b);
        split2(v2, h2, l2b); split2(v3, h3, l3b);
        *(uint32_t*)(attn_hi + o0) = packbf(h0, h1);
        *(uint32_t*)(attn_lo + o0) = packbf(l0b, l1b);
        *(uint32_t*)(attn_hi + o1) = packbf(h2, h3);
        *(uint32_t*)(attn_lo + o1) = packbf(l2b, l3b);
    }
}

// ---------------------------------------------------------------------------
// kernel_launch: inputs = [positions, hidden_states, w_qkv, w_out]
// ---------------------------------------------------------------------------
extern "C" void kernel_launch(void* const* d_in, const int* in_sizes, int n_in,
                              void* d_out, int out_size) {
    const float* hidden = (const float*)d_in[1];
    const float* w_qkv  = (const float*)d_in[2];
    const float* w_out  = (const float*)d_in[3];
    float* out = (float*)d_out;

    __nv_bfloat16 *xh, *xl, *wqh, *wql, *woh, *wol, *ah, *al;
    __nv_bfloat16 *qh, *ql, *kh, *kl, *vth, *vtl;
    float* qkv;
    cudaGetSymbolAddress((void**)&xh,  g_xln_hi);
    cudaGetSymbolAddress((void**)&xl,  g_xln_lo);
    cudaGetSymbolAddress((void**)&qkv, g_qkv);
    cudaGetSymbolAddress((void**)&wqh, g_wqkvT_hi);
    cudaGetSymbolAddress((void**)&wql, g_wqkvT_lo);
    cudaGetSymbolAddress((void**)&woh, g_woutT_hi);
    cudaGetSymbolAddress((void**)&wol, g_woutT_lo);
    cudaGetSymbolAddress((void**)&ah,  g_attn_hi);
    cudaGetSymbolAddress((void**)&al,  g_attn_lo);
    cudaGetSymbolAddress((void**)&qh,  g_qh);
    cudaGetSymbolAddress((void**)&ql,  g_ql);
    cudaGetSymbolAddress((void**)&kh,  g_kh);
    cudaGetSymbolAddress((void**)&kl,  g_kl);
    cudaGetSymbolAddress((void**)&vth, g_vth);
    cudaGetSymbolAddress((void**)&vtl, g_vtl);

    // 1) LayerNorm -> split bf16
    ln_kernel<<<NTOK, 256>>>(hidden, xh, xl);

    // 2) Weight transpose+split
    dim3 tb(32, 8);
    transpose_split<<<dim3(QKV_N / 32, DD / 32), tb>>>(w_qkv, wqh, wql, DD, QKV_N);
    transpose_split<<<dim3(DD / 32, DD / 32), tb>>>(w_out, woh, wol, DD, DD);

    // 3) QKV projection (tensor cores via mma.sync)
    cudaFuncSetAttribute(gemm_mma, cudaFuncAttributeMaxDynamicSharedMemorySize, GEMM_SMEM);
    gemm_mma<<<dim3(QKV_N / BN, NTOK / BM), 256, GEMM_SMEM>>>(
        xh, xl, wqh, wql, qkv, NTOK, QKV_N, DD);

    // 4) RoPE + split Q,K; transpose + split V
    rope_split<<<NTOK, 256>>>(qkv, qh, ql, kh, kl);
    v_split_transpose<<<dim3(SS / 64, HH, BB), 256>>>(qkv, vth, vtl);

    // 5) Causal flash attention v5 (128-row q tile, double-buffered K/V)
    cudaFuncSetAttribute(flash5_kernel, cudaFuncAttributeMaxDynamicSharedMemorySize,
                         FLASH5_SMEM);
    flash5_kernel<<<dim3(SS / 128, HH, BB), 256, FLASH5_SMEM>>>(
        qh, ql, kh, kl, vth, vtl, ah, al);

    // 6) Output projection (tensor cores via mma.sync)
    gemm_mma<<<dim3(DD / BN, NTOK / BM), 256, GEMM_SMEM>>>(
        ah, al, woh, wol, out, NTOK, DD, DD);
}

// round 10
// speedup vs baseline: 1.0581x; 1.0581x over previous
#include <cuda_runtime.h>
#include <cuda_bf16.h>
#include <math.h>
#include <cstdint>

// ---------------------------------------------------------------------------
// Problem constants: B=2, S=2048, D=2048, H=16, DH=128
// ---------------------------------------------------------------------------
#define BB 2
#define SS 2048
#define DD 2048
#define HH 16
#define DHH 128
#define NTOK (BB * SS)          // 4096
#define QKV_N (3 * DD)          // 6144
#define LN_EPS 1e-5f

// ---------------------------------------------------------------------------
// Scratch (device globals; allocation forbidden)
// ---------------------------------------------------------------------------
__device__ __nv_bfloat16 g_xln_hi[(size_t)NTOK * DD];
__device__ __nv_bfloat16 g_xln_lo[(size_t)NTOK * DD];
__device__ float         g_qkv[(size_t)NTOK * QKV_N];     // 100.7 MB
__device__ __nv_bfloat16 g_wqkvT_hi[(size_t)QKV_N * DD];
__device__ __nv_bfloat16 g_wqkvT_lo[(size_t)QKV_N * DD];
__device__ __nv_bfloat16 g_woutT_hi[(size_t)DD * DD];
__device__ __nv_bfloat16 g_woutT_lo[(size_t)DD * DD];
__device__ __nv_bfloat16 g_attn_hi[(size_t)NTOK * DD];
__device__ __nv_bfloat16 g_attn_lo[(size_t)NTOK * DD];
// pre-split attention operands, per-head layouts
__device__ __nv_bfloat16 g_qh[(size_t)NTOK * DD];   // [b][h][s][d]
__device__ __nv_bfloat16 g_ql[(size_t)NTOK * DD];
__device__ __nv_bfloat16 g_kh[(size_t)NTOK * DD];
__device__ __nv_bfloat16 g_kl[(size_t)NTOK * DD];
__device__ __nv_bfloat16 g_vth[(size_t)NTOK * DD];  // [b][h][d][s]
__device__ __nv_bfloat16 g_vtl[(size_t)NTOK * DD];

// ---------------------------------------------------------------------------
// helpers
// ---------------------------------------------------------------------------
__device__ __forceinline__ uint32_t smem_u32(const void* p) {
    uint32_t a;
    asm("{ .reg .u64 t; cvta.to.shared.u64 t, %1; cvt.u32.u64 %0, t; }"
        : "=r"(a) : "l"(p));
    return a;
}

__device__ __forceinline__ void cpa16(uint32_t dst, const void* src) {
    asm volatile("cp.async.cg.shared.global [%0], [%1], 16;" :: "r"(dst), "l"(src) : "memory");
}
#define CP_COMMIT() asm volatile("cp.async.commit_group;" ::: "memory")
#define CP_WAIT1()  asm volatile("cp.async.wait_group 1;" ::: "memory")
#define CP_WAIT0()  asm volatile("cp.async.wait_group 0;" ::: "memory")

__device__ __forceinline__ void mma_bf16(float* c, const uint32_t* a, const uint32_t* b) {
    asm volatile(
        "mma.sync.aligned.m16n8k16.row.col.f32.bf16.bf16.f32 "
        "{%0,%1,%2,%3}, {%4,%5,%6,%7}, {%8,%9}, {%0,%1,%2,%3};"
        : "+f"(c[0]), "+f"(c[1]), "+f"(c[2]), "+f"(c[3])
        : "r"(a[0]), "r"(a[1]), "r"(a[2]), "r"(a[3]), "r"(b[0]), "r"(b[1]));
}

__device__ __forceinline__ void ldm_x4(uint32_t* r, uint32_t addr) {
    asm volatile("ldmatrix.sync.aligned.m8n8.x4.shared.b16 {%0,%1,%2,%3}, [%4];"
        : "=r"(r[0]), "=r"(r[1]), "=r"(r[2]), "=r"(r[3]) : "r"(addr));
}

__device__ __forceinline__ void split2(float v, __nv_bfloat16& h, __nv_bfloat16& l) {
    h = __float2bfloat16(v);
    l = __float2bfloat16(v - __bfloat162float(h));
}

__device__ __forceinline__ uint32_t packbf(__nv_bfloat16 a, __nv_bfloat16 b) {
    __nv_bfloat162 t(a, b);   // a = low element
    return *(uint32_t*)&t;
}

// ---------------------------------------------------------------------------
// LayerNorm -> bf16 hi/lo split outputs
// ---------------------------------------------------------------------------
__global__ __launch_bounds__(256) void ln_kernel(const float* __restrict__ x,
                                                 __nv_bfloat16* __restrict__ yh,
                                                 __nv_bfloat16* __restrict__ yl) {
    __shared__ float red_s[8], red_ss[8];
    __shared__ float sh_mu, sh_rstd;
    const int row = blockIdx.x;
    const int tid = threadIdx.x;
    const float* xr = x + (size_t)row * DD;

    float4 a = *(const float4*)(xr + tid * 4);
    float4 b = *(const float4*)(xr + 1024 + tid * 4);
    float s  = a.x + a.y + a.z + a.w + b.x + b.y + b.z + b.w;
    float ss = a.x*a.x + a.y*a.y + a.z*a.z + a.w*a.w
             + b.x*b.x + b.y*b.y + b.z*b.z + b.w*b.w;
    #pragma unroll
    for (int o = 16; o > 0; o >>= 1) {
        s  += __shfl_xor_sync(0xffffffffu, s, o);
        ss += __shfl_xor_sync(0xffffffffu, ss, o);
    }
    const int wid = tid >> 5, lane = tid & 31;
    if (lane == 0) { red_s[wid] = s; red_ss[wid] = ss; }
    __syncthreads();
    if (tid == 0) {
        float S = 0.f, SSq = 0.f;
        #pragma unroll
        for (int w = 0; w < 8; w++) { S += red_s[w]; SSq += red_ss[w]; }
        float mu = S * (1.0f / DD);
        float var = SSq * (1.0f / DD) - mu * mu;
        sh_mu = mu;
        sh_rstd = rsqrtf(var + LN_EPS);
    }
    __syncthreads();
    const float mu = sh_mu, rstd = sh_rstd;
    float va[8] = {a.x, a.y, a.z, a.w, b.x, b.y, b.z, b.w};
    #pragma unroll
    for (int e = 0; e < 8; e++) {
        float v = (va[e] - mu) * rstd;
        __nv_bfloat16 h, l;
        split2(v, h, l);
        size_t col = (e < 4) ? (tid * 4 + e) : (1024 + tid * 4 + e - 4);
        yh[(size_t)row * DD + col] = h;
        yl[(size_t)row * DD + col] = l;
    }
}

// ---------------------------------------------------------------------------
// Transpose + split: W[K][N] fp32 -> hi/lo bf16 [N][K]
// ---------------------------------------------------------------------------
__global__ __launch_bounds__(256) void transpose_split(const float* __restrict__ W,
                                                       __nv_bfloat16* __restrict__ hi,
                                                       __nv_bfloat16* __restrict__ lo,
                                                       int K, int N) {
    __shared__ float t[32][33];
    int n = blockIdx.x * 32 + threadIdx.x;
    int k = blockIdx.y * 32 + threadIdx.y;
    #pragma unroll
    for (int i = 0; i < 4; i++)
        t[threadIdx.y + 8 * i][threadIdx.x] = W[(size_t)(k + 8 * i) * N + n];
    __syncthreads();
    int ko = blockIdx.y * 32 + threadIdx.x;
    int no = blockIdx.x * 32 + threadIdx.y;
    #pragma unroll
    for (int i = 0; i < 4; i++) {
        float v = t[threadIdx.x][threadIdx.y + 8 * i];
        __nv_bfloat16 h, l;
        split2(v, h, l);
        size_t o = (size_t)(no + 8 * i) * K + ko;
        hi[o] = h;
        lo[o] = l;
    }
}

// ---------------------------------------------------------------------------
// mma.sync split-bf16 GEMM v3 (unchanged — proven)
// ---------------------------------------------------------------------------
#define BM 128
#define BN 256
#define BKC 32
#define ROWB 80
#define A_TILE (128 * ROWB)
#define B_TILE (256 * ROWB)
#define STAGE_B (2 * A_TILE + 2 * B_TILE)
#define NSTAGE 3
#define GEMM_SMEM (NSTAGE * STAGE_B)

__global__ __launch_bounds__(256, 1) void gemm_mma(
    const __nv_bfloat16* __restrict__ Ahi, const __nv_bfloat16* __restrict__ Alo,
    const __nv_bfloat16* __restrict__ Bhi, const __nv_bfloat16* __restrict__ Blo,
    float* __restrict__ C, int M, int N, int K)
{
    extern __shared__ __align__(16) char smem[];
    const uint32_t sb = smem_u32(smem);
    const int tid = threadIdx.x;
    const int wid = tid >> 5;
    const int lane = tid & 31;
    const int m0 = blockIdx.y * BM;
    const int n0 = blockIdx.x * BN;
    const int wm = (wid & 1) * 64;
    const int wn = (wid >> 1) * 64;

    float acc[4][8][4];
    #pragma unroll
    for (int mi = 0; mi < 4; mi++)
        #pragma unroll
        for (int ni = 0; ni < 8; ni++)
            #pragma unroll
            for (int e = 0; e < 4; e++) acc[mi][ni][e] = 0.f;

    auto fill = [&](int stage, int k0) {
        const uint32_t sbase = sb + stage * STAGE_B;
        #pragma unroll
        for (int it = 0; it < 12; it++) {
            int i = it * 256 + tid;
            const __nv_bfloat16* src;
            uint32_t dst;
            if (i < 1024) {
                int op = i >> 9, r = (i >> 2) & 127, c = i & 3;
                src = (op ? Alo : Ahi) + (size_t)(m0 + r) * K + k0 + c * 8;
                dst = sbase + op * A_TILE + r * ROWB + c * 16;
            } else {
                int j = i - 1024;
                int op = j >> 10, r = (j >> 2) & 255, c = j & 3;
                src = (op ? Blo : Bhi) + (size_t)(n0 + r) * K + k0 + c * 8;
                dst = sbase + 2 * A_TILE + op * B_TILE + r * ROWB + c * 16;
            }
            cpa16(dst, src);
        }
        CP_COMMIT();
    };

    const int nch = K / BKC;
    fill(0, 0);
    fill(1, BKC);

    const int lg = lane >> 3;
    const int lr = lane & 7;

    for (int c = 0; c < nch; c++) {
        if (c + 1 < nch) CP_WAIT1(); else CP_WAIT0();
        __syncthreads();

        if (c + 2 < nch) fill((c + 2) % NSTAGE, (c + 2) * BKC);

        const uint32_t sbase = sb + (c % NSTAGE) * STAGE_B;
        const uint32_t aHi = sbase;
        const uint32_t aLo = sbase + A_TILE;
        const uint32_t bHi = sbase + 2 * A_TILE;
        const uint32_t bLo = sbase + 2 * A_TILE + B_TILE;

        #pragma unroll
        for (int ks = 0; ks < 2; ks++) {
            const uint32_t koff = ks * 32;

            const uint32_t aoff = (lg & 1) * 8 * ROWB + (lg >> 1) * 16 + lr * ROWB + koff;
            uint32_t ah[4][4], al[4][4];
            #pragma unroll
            for (int mi = 0; mi < 4; mi++) {
                uint32_t ro = (wm + mi * 16) * ROWB + aoff;
                ldm_x4(ah[mi], aHi + ro);
                ldm_x4(al[mi], aLo + ro);
            }
            const uint32_t boff = (lg >> 1) * 8 * ROWB + (lg & 1) * 16 + lr * ROWB + koff;
            uint32_t bh[8][2], bl[8][2];
            #pragma unroll
            for (int np = 0; np < 4; np++) {
                uint32_t ro = (wn + np * 16) * ROWB + boff;
                uint32_t t4[4];
                ldm_x4(t4, bHi + ro);
                bh[2 * np][0] = t4[0]; bh[2 * np][1] = t4[1];
                bh[2 * np + 1][0] = t4[2]; bh[2 * np + 1][1] = t4[3];
                ldm_x4(t4, bLo + ro);
                bl[2 * np][0] = t4[0]; bl[2 * np][1] = t4[1];
                bl[2 * np + 1][0] = t4[2]; bl[2 * np + 1][1] = t4[3];
            }

            #pragma unroll
            for (int mi = 0; mi < 4; mi++)
                #pragma unroll
                for (int ni = 0; ni < 8; ni++)
                    mma_bf16(acc[mi][ni], ah[mi], bh[ni]);
            #pragma unroll
            for (int mi = 0; mi < 4; mi++)
                #pragma unroll
                for (int ni = 0; ni < 8; ni++)
                    mma_bf16(acc[mi][ni], ah[mi], bl[ni]);
            #pragma unroll
            for (int mi = 0; mi < 4; mi++)
                #pragma unroll
                for (int ni = 0; ni < 8; ni++)
                    mma_bf16(acc[mi][ni], al[mi], bh[ni]);
        }
    }

    const int r4 = lane >> 2;
    const int k4 = lane & 3;
    #pragma unroll
    for (int mi = 0; mi < 4; mi++) {
        int r0 = m0 + wm + mi * 16 + r4;
        #pragma unroll
        for (int ni = 0; ni < 8; ni++) {
            int cc = n0 + wn + ni * 8 + k4 * 2;
            float2 v0 = {acc[mi][ni][0], acc[mi][ni][1]};
            float2 v1 = {acc[mi][ni][2], acc[mi][ni][3]};
            *(float2*)(C + (size_t)r0 * N + cc) = v0;
            *(float2*)(C + (size_t)(r0 + 8) * N + cc) = v1;
        }
    }
}

// ---------------------------------------------------------------------------
// RoPE + split for Q,K: fp32 qkv -> per-head K-major bf16 hi/lo [b][h][s][d]
// ---------------------------------------------------------------------------
__global__ __launch_bounds__(256) void rope_split(const float* __restrict__ qkv,
                                                  __nv_bfloat16* __restrict__ qh,
                                                  __nv_bfloat16* __restrict__ ql,
                                                  __nv_bfloat16* __restrict__ kh,
                                                  __nv_bfloat16* __restrict__ kl) {
    const int t = blockIdx.x;            // token
    const int b = t / SS, s = t % SS;
    const int tid = threadIdx.x;

    #pragma unroll
    for (int w = 0; w < 4; w++) {
        int idx = w * 256 + tid;          // (h, dpair)
        int h = idx >> 6, dp = idx & 63;

        float inv_freq = powf(10000.0f, -(float)dp * (1.0f / 64.0f));
        float ang = (float)s * inv_freq;
        float c = cosf(ang), sn = sinf(ang);

        const float* src = qkv + (size_t)t * QKV_N + h * DHH;
        size_t obase = ((size_t)(b * HH + h) * SS + s) * DHH;
        __nv_bfloat16 hh, ll;

        // q
        float x1 = src[dp], x2 = src[dp + 64];
        float r1 = x1 * c - x2 * sn;
        float r2 = x2 * c + x1 * sn;
        split2(r1, hh, ll); qh[obase + dp] = hh;      ql[obase + dp] = ll;
        split2(r2, hh, ll); qh[obase + dp + 64] = hh; ql[obase + dp + 64] = ll;

        // k
        x1 = src[DD + dp]; x2 = src[DD + dp + 64];
        r1 = x1 * c - x2 * sn;
        r2 = x2 * c + x1 * sn;
        split2(r1, hh, ll); kh[obase + dp] = hh;      kl[obase + dp] = ll;
        split2(r2, hh, ll); kh[obase + dp + 64] = hh; kl[obase + dp + 64] = ll;
    }
}

// ---------------------------------------------------------------------------
// V transpose + split: fp32 qkv v-slice -> [b][h][d][s] bf16 hi/lo
// ---------------------------------------------------------------------------
__global__ __launch_bounds__(256) void v_split_transpose(const float* __restrict__ qkv,
                                                         __nv_bfloat16* __restrict__ vth,
                                                         __nv_bfloat16* __restrict__ vtl) {
    __shared__ float sm[64 * 132];
    const int s0 = blockIdx.x * 64;
    const int h  = blockIdx.y;
    const int b  = blockIdx.z;
    const int tid = threadIdx.x;

    #pragma unroll
    for (int i = 0; i < 32; i++) {
        int idx = i * 256 + tid;
        int sl = idx >> 7, d = idx & 127;
        sm[sl * 132 + d] = qkv[((size_t)(b * SS + s0 + sl)) * QKV_N + 2 * DD + h * DHH + d];
    }
    __syncthreads();

    const int d = tid >> 1;
    const int sh = (tid & 1) * 32;
    size_t row = ((size_t)(b * HH + h) * DHH + d) * SS + s0 + sh;
    #pragma unroll
    for (int j = 0; j < 32; j += 2) {
        float v0 = sm[(sh + j) * 132 + d];
        float v1 = sm[(sh + j + 1) * 132 + d];
        __nv_bfloat16 h0, l0, h1, l1;
        split2(v0, h0, l0); split2(v1, h1, l1);
        *(uint32_t*)(vth + row + j) = packbf(h0, h1);
        *(uint32_t*)(vtl + row + j) = packbf(l0, l1);
    }
}

// ---------------------------------------------------------------------------
// Flash attention v6: 64-row Q tile, Q fragments resident in REGISTERS,
// K double-buffered + V prefetched, 2 CTAs/SM. Compute core = flash3.
// ---------------------------------------------------------------------------
#define QROW 272
#define VROW 144
#define F6_KST(s) ((s) * 34816)            // K stage s: KH at +0, KL at +17408
#define F6_KL_OFF 17408
#define F6_VH (2 * 34816)                  // 69632
#define F6_VL (F6_VH + 128 * VROW)         // 88064
#define FLASH6_SMEM (F6_VL + 128 * VROW)   // 106496 bytes -> 2 CTAs/SM

__global__ __launch_bounds__(128) void flash6_kernel(
    const __nv_bfloat16* __restrict__ qh, const __nv_bfloat16* __restrict__ ql,
    const __nv_bfloat16* __restrict__ kh, const __nv_bfloat16* __restrict__ kl,
    const __nv_bfloat16* __restrict__ vth, const __nv_bfloat16* __restrict__ vtl,
    __nv_bfloat16* __restrict__ attn_hi, __nv_bfloat16* __restrict__ attn_lo)
{
    extern __shared__ __align__(16) char smem[];
    const uint32_t sb = smem_u32(smem);

    const int qb = blockIdx.x;
    const int h  = blockIdx.y;
    const int b  = blockIdx.z;
    const int tid = threadIdx.x;
    const int wid = tid >> 5;
    const int lane = tid & 31;
    const int r4 = lane >> 2;
    const int k4 = lane & 3;

    const size_t bh = (size_t)(b * HH + h);
    const __nv_bfloat16* qhp = qh + (bh * SS + qb * 64) * DHH;
    const __nv_bfloat16* qlp = ql + (bh * SS + qb * 64) * DHH;

    // ---- prologue: stage Q (64x128 hi/lo) into K-stage area, read frags ----
    // QH at smem[0..17408), QL at smem[17408..34816)
    for (int i = tid; i < 2048; i += 128) {
        int op = i >> 10, j = i & 1023;
        int row = j >> 4, c = j & 15;
        const __nv_bfloat16* src = (op ? qlp : qhp) + row * DHH + c * 8;
        uint4 v = *(const uint4*)src;
        *(uint4*)(smem + op * 17408 + row * QROW + c * 16) = v;
    }
    __syncthreads();

    const int arow = wid * 16 + r4;
    uint32_t qah[8][4], qal[8][4];
    #pragma unroll
    for (int kb = 0; kb < 8; kb++) {
        const uint32_t koff = kb * 32 + k4 * 4;
        qah[kb][0] = *(const uint32_t*)(smem + arow * QROW + koff);
        qah[kb][1] = *(const uint32_t*)(smem + (arow + 8) * QROW + koff);
        qah[kb][2] = *(const uint32_t*)(smem + arow * QROW + koff + 16);
        qah[kb][3] = *(const uint32_t*)(smem + (arow + 8) * QROW + koff + 16);
        qal[kb][0] = *(const uint32_t*)(smem + 17408 + arow * QROW + koff);
        qal[kb][1] = *(const uint32_t*)(smem + 17408 + (arow + 8) * QROW + koff);
        qal[kb][2] = *(const uint32_t*)(smem + 17408 + arow * QROW + koff + 16);
        qal[kb][3] = *(const uint32_t*)(smem + 17408 + (arow + 8) * QROW + koff + 16);
    }
    __syncthreads();   // Q fully consumed before cp.async overwrites the area

    // K stage fill (one commit group)
    auto fillK = [&](int s, int kt) {
        const __nv_bfloat16* khp = kh + (bh * SS + kt * 64) * DHH;
        const __nv_bfloat16* klp = kl + (bh * SS + kt * 64) * DHH;
        const uint32_t kbase = sb + F6_KST(s);
        #pragma unroll
        for (int it = 0; it < 16; it++) {
            int i = it * 128 + tid;       // 2048 x 16B
            int op = i >> 10, j = i & 1023;
            int row = j >> 4, c = j & 15;
            cpa16(kbase + op * F6_KL_OFF + row * QROW + c * 16,
                  (op ? klp : khp) + row * DHH + c * 8);
        }
        CP_COMMIT();
    };
    // V fill (one commit group)
    auto fillV = [&](int kt) {
        const __nv_bfloat16* vhp = vth + bh * DHH * SS + kt * 64;
        const __nv_bfloat16* vlp = vtl + bh * DHH * SS + kt * 64;
        #pragma unroll
        for (int it = 0; it < 16; it++) {
            int i = it * 128 + tid;       // 2048 x 16B
            int op = i >> 10, j = i & 1023;
            int d = j >> 3, c = j & 7;
            cpa16(sb + (op ? F6_VL : F6_VH) + d * VROW + c * 16,
                  (op ? vlp : vhp) + (size_t)d * SS + c * 8);
        }
        CP_COMMIT();
    };

    float oacc[16][4];
    #pragma unroll
    for (int n = 0; n < 16; n++)
        #pragma unroll
        for (int e = 0; e < 4; e++) oacc[n][e] = 0.f;

    float m0 = -1e30f, m1 = -1e30f, l0 = 0.f, l1 = 0.f;
    const float scale = 0.088388347648318447f;
    const int nkt = qb + 1;

    fillK(0, 0);
    fillV(0);

    for (int kt = 0; kt < nkt; kt++) {
        // Prefetch next K tile into the other stage (freed by last trailing
        // barrier), then wait until K(kt) and V(kt) groups are complete.
        if (kt + 1 < nkt) {
            fillK((kt + 1) & 1, kt + 1);
            CP_WAIT1();      // pending: only K(kt+1) may remain in flight
        } else {
            CP_WAIT0();
        }
        __syncthreads();

        const char* kst = smem + F6_KST(kt & 1);

        // ---- S = Q K^T (split 3-term), Q frags from registers ----
        float sacc[8][4];
        #pragma unroll
        for (int n = 0; n < 8; n++)
            #pragma unroll
            for (int e = 0; e < 4; e++) sacc[n][e] = 0.f;

        #pragma unroll
        for (int kb = 0; kb < 8; kb++) {
            const uint32_t koff = kb * 32 + k4 * 4;
            #pragma unroll
            for (int ng = 0; ng < 8; ng++) {
                const uint32_t bro = (ng * 8 + r4) * QROW + koff;
                uint32_t bh2[2], bl2[2];
                bh2[0] = *(const uint32_t*)(kst + bro);
                bh2[1] = *(const uint32_t*)(kst + bro + 16);
                bl2[0] = *(const uint32_t*)(kst + F6_KL_OFF + bro);
                bl2[1] = *(const uint32_t*)(kst + F6_KL_OFF + bro + 16);
                mma_bf16(sacc[ng], qah[kb], bh2);
                mma_bf16(sacc[ng], qah[kb], bl2);
                mma_bf16(sacc[ng], qal[kb], bh2);
            }
        }

        const int row0 = qb * 64 + wid * 16 + r4;
        if (kt == qb) {
            #pragma unroll
            for (int ng = 0; ng < 8; ng++) {
                int colb = kt * 64 + ng * 8 + k4 * 2;
                sacc[ng][0] = (colb     > row0)     ? -1e30f : sacc[ng][0] * scale;
                sacc[ng][1] = (colb + 1 > row0)     ? -1e30f : sacc[ng][1] * scale;
                sacc[ng][2] = (colb     > row0 + 8) ? -1e30f : sacc[ng][2] * scale;
                sacc[ng][3] = (colb + 1 > row0 + 8) ? -1e30f : sacc[ng][3] * scale;
            }
        } else {
            #pragma unroll
            for (int ng = 0; ng < 8; ng++)
                #pragma unroll
                for (int e = 0; e < 4; e++) sacc[ng][e] *= scale;
        }

        float mx0 = -1e30f, mx1 = -1e30f;
        #pragma unroll
        for (int ng = 0; ng < 8; ng++) {
            mx0 = fmaxf(mx0, fmaxf(sacc[ng][0], sacc[ng][1]));
            mx1 = fmaxf(mx1, fmaxf(sacc[ng][2], sacc[ng][3]));
        }
        mx0 = fmaxf(mx0, __shfl_xor_sync(0xffffffffu, mx0, 1));
        mx0 = fmaxf(mx0, __shfl_xor_sync(0xffffffffu, mx0, 2));
        mx1 = fmaxf(mx1, __shfl_xor_sync(0xffffffffu, mx1, 1));
        mx1 = fmaxf(mx1, __shfl_xor_sync(0xffffffffu, mx1, 2));

        float mn0 = fmaxf(m0, mx0), mn1 = fmaxf(m1, mx1);
        float c0 = __expf(m0 - mn0), c1 = __expf(m1 - mn1);
        m0 = mn0; m1 = mn1;

        float sum0 = 0.f, sum1 = 0.f;
        uint32_t ph2[8][2], pl2[8][2];
        #pragma unroll
        for (int ng = 0; ng < 8; ng++) {
            float p0 = __expf(sacc[ng][0] - m0);
            float p1 = __expf(sacc[ng][1] - m0);
            float p2 = __expf(sacc[ng][2] - m1);
            float p3 = __expf(sacc[ng][3] - m1);
            sum0 += p0 + p1; sum1 += p2 + p3;
            __nv_bfloat16 a, bq, cc, dd2, la, lb, lc, ld;
            split2(p0, a, la); split2(p1, bq, lb);
            split2(p2, cc, lc); split2(p3, dd2, ld);
            ph2[ng][0] = packbf(a, bq);  ph2[ng][1] = packbf(cc, dd2);
            pl2[ng][0] = packbf(la, lb); pl2[ng][1] = packbf(lc, ld);
        }
        sum0 += __shfl_xor_sync(0xffffffffu, sum0, 1);
        sum0 += __shfl_xor_sync(0xffffffffu, sum0, 2);
        sum1 += __shfl_xor_sync(0xffffffffu, sum1, 1);
        sum1 += __shfl_xor_sync(0xffffffffu, sum1, 2);
        l0 = l0 * c0 + sum0;
        l1 = l1 * c1 + sum1;

        #pragma unroll
        for (int n = 0; n < 16; n++) {
            oacc[n][0] *= c0; oacc[n][1] *= c0;
            oacc[n][2] *= c1; oacc[n][3] *= c1;
        }

        #pragma unroll
        for (int kb = 0; kb < 4; kb++) {
            uint32_t pa[4] = {ph2[2*kb][0], ph2[2*kb][1], ph2[2*kb+1][0], ph2[2*kb+1][1]};
            uint32_t pb[4] = {pl2[2*kb][0], pl2[2*kb][1], pl2[2*kb+1][0], pl2[2*kb+1][1]};
            const uint32_t koff = kb * 32 + k4 * 4;
            #pragma unroll
            for (int ng = 0; ng < 16; ng++) {
                const uint32_t vro = (ng * 8 + r4) * VROW + koff;
                uint32_t vh[2], vl[2];
                vh[0] = *(const uint32_t*)(smem + F6_VH + vro);
                vh[1] = *(const uint32_t*)(smem + F6_VH + vro + 16);
                vl[0] = *(const uint32_t*)(smem + F6_VL + vro);
                vl[1] = *(const uint32_t*)(smem + F6_VL + vro + 16);
                mma_bf16(oacc[ng], pa, vh);
                mma_bf16(oacc[ng], pa, vl);
                mma_bf16(oacc[ng], pb, vh);
            }
        }

        __syncthreads();   // all warps done with V buffer + K stage kt&1
        if (kt + 1 < nkt) fillV(kt + 1);   // overlaps next iter's QK+softmax
    }

    const float inv0 = 1.0f / l0, inv1 = 1.0f / l1;
    const int grow0 = b * SS + qb * 64 + wid * 16 + r4;
    #pragma unroll
    for (int ng = 0; ng < 16; ng++) {
        size_t o0 = (size_t)grow0 * DD + h * DHH + ng * 8 + k4 * 2;
        size_t o1 = o0 + (size_t)8 * DD;
        float v0 = oacc[ng][0] * inv0, v1 = oacc[ng][1] * inv0;
        float v2 = oacc[ng][2] * inv1, v3 = oacc[ng][3] * inv1;
        __nv_bfloat16 h0, l0b, h1, l1b, h2, l2b, h3, l3b;
        split2(v0, h0, l0b); split2(v1, h1, l1b);
        split2(v2, h2, l2b); split2(v3, h3, l3b);
        *(uint32_t*)(attn_hi + o0) = packbf(h0, h1);
        *(uint32_t*)(attn_lo + o0) = packbf(l0b, l1b);
        *(uint32_t*)(attn_hi + o1) = packbf(h2, h3);
        *(uint32_t*)(attn_lo + o1) = packbf(l2b, l3b);
    }
}

// ---------------------------------------------------------------------------
// kernel_launch: inputs = [positions, hidden_states, w_qkv, w_out]
// ---------------------------------------------------------------------------
extern "C" void kernel_launch(void* const* d_in, const int* in_sizes, int n_in,
                              void* d_out, int out_size) {
    const float* hidden = (const float*)d_in[1];
    const float* w_qkv  = (const float*)d_in[2];
    const float* w_out  = (const float*)d_in[3];
    float* out = (float*)d_out;

    __nv_bfloat16 *xh, *xl, *wqh, *wql, *woh, *wol, *ah, *al;
    __nv_bfloat16 *qh, *ql, *kh, *kl, *vth, *vtl;
    float* qkv;
    cudaGetSymbolAddress((void**)&xh,  g_xln_hi);
    cudaGetSymbolAddress((void**)&xl,  g_xln_lo);
    cudaGetSymbolAddress((void**)&qkv, g_qkv);
    cudaGetSymbolAddress((void**)&wqh, g_wqkvT_hi);
    cudaGetSymbolAddress((void**)&wql, g_wqkvT_lo);
    cudaGetSymbolAddress((void**)&woh, g_woutT_hi);
    cudaGetSymbolAddress((void**)&wol, g_woutT_lo);
    cudaGetSymbolAddress((void**)&ah,  g_attn_hi);
    cudaGetSymbolAddress((void**)&al,  g_attn_lo);
    cudaGetSymbolAddress((void**)&qh,  g_qh);
    cudaGetSymbolAddress((void**)&ql,  g_ql);
    cudaGetSymbolAddress((void**)&kh,  g_kh);
    cudaGetSymbolAddress((void**)&kl,  g_kl);
    cudaGetSymbolAddress((void**)&vth, g_vth);
    cudaGetSymbolAddress((void**)&vtl, g_vtl);

    // 1) LayerNorm -> split bf16
    ln_kernel<<<NTOK, 256>>>(hidden, xh, xl);

    // 2) Weight transpose+split
    dim3 tb(32, 8);
    transpose_split<<<dim3(QKV_N / 32, DD / 32), tb>>>(w_qkv, wqh, wql, DD, QKV_N);
    transpose_split<<<dim3(DD / 32, DD / 32), tb>>>(w_out, woh, wol, DD, DD);

    // 3) QKV projection (tensor cores via mma.sync)
    cudaFuncSetAttribute(gemm_mma, cudaFuncAttributeMaxDynamicSharedMemorySize, GEMM_SMEM);
    gemm_mma<<<dim3(QKV_N / BN, NTOK / BM), 256, GEMM_SMEM>>>(
        xh, xl, wqh, wql, qkv, NTOK, QKV_N, DD);

    // 4) RoPE + split Q,K; transpose + split V
    rope_split<<<NTOK, 256>>>(qkv, qh, ql, kh, kl);
    v_split_transpose<<<dim3(SS / 64, HH, BB), 256>>>(qkv, vth, vtl);

    // 5) Causal flash attention v6 (reg-resident Q, double-buffered K,
    //    prefetched V, 2 CTAs/SM)
    cudaFuncSetAttribute(flash6_kernel, cudaFuncAttributeMaxDynamicSharedMemorySize,
                         FLASH6_SMEM);
    flash6_kernel<<<dim3(SS / 64, HH, BB), 128, FLASH6_SMEM>>>(
        qh, ql, kh, kl, vth, vtl, ah, al);

    // 6) Output projection (tensor cores via mma.sync)
    gemm_mma<<<dim3(DD / BN, NTOK / BM), 256, GEMM_SMEM>>>(
        ah, al, woh, wol, out, NTOK, DD, DD);
}

// round 11
// speedup vs baseline: 1.3638x; 1.2889x over previous
#include <cuda_runtime.h>
#include <cuda_bf16.h>
#include <cuda_fp16.h>
#include <math.h>
#include <cstdint>

// ---------------------------------------------------------------------------
// Problem constants: B=2, S=2048, D=2048, H=16, DH=128
// ---------------------------------------------------------------------------
#define BB 2
#define SS 2048
#define DD 2048
#define HH 16
#define DHH 128
#define NTOK (BB * SS)          // 4096
#define QKV_N (3 * DD)          // 6144
#define LN_EPS 1e-5f

// ---------------------------------------------------------------------------
// Scratch (device globals; allocation forbidden)
// ---------------------------------------------------------------------------
__device__ __half        g_xh[(size_t)NTOK * DD];          // LN out hi (fp16)
__device__ __half        g_xl[(size_t)NTOK * DD];          // LN out lo (fp16)
__device__ float         g_qkv[(size_t)NTOK * QKV_N];      // 100.7 MB
__device__ __half        g_wqkvT[(size_t)QKV_N * DD];      // W_qkv^T (fp16)
__device__ __half        g_woutT[(size_t)DD * DD];         // W_out^T (fp16)
__device__ __half        g_ah[(size_t)NTOK * DD];          // attn hi (fp16)
__device__ __half        g_al[(size_t)NTOK * DD];          // attn lo (fp16)
// pre-split attention operands (bf16, proven path)
__device__ __nv_bfloat16 g_qh[(size_t)NTOK * DD];   // [b][h][s][d]
__device__ __nv_bfloat16 g_ql[(size_t)NTOK * DD];
__device__ __nv_bfloat16 g_kh[(size_t)NTOK * DD];
__device__ __nv_bfloat16 g_kl[(size_t)NTOK * DD];
__device__ __nv_bfloat16 g_vth[(size_t)NTOK * DD];  // [b][h][d][s]
__device__ __nv_bfloat16 g_vtl[(size_t)NTOK * DD];

// ---------------------------------------------------------------------------
// helpers
// ---------------------------------------------------------------------------
__device__ __forceinline__ uint32_t smem_u32(const void* p) {
    uint32_t a;
    asm("{ .reg .u64 t; cvta.to.shared.u64 t, %1; cvt.u32.u64 %0, t; }"
        : "=r"(a) : "l"(p));
    return a;
}

__device__ __forceinline__ void cpa16(uint32_t dst, const void* src) {
    asm volatile("cp.async.cg.shared.global [%0], [%1], 16;" :: "r"(dst), "l"(src) : "memory");
}
#define CP_COMMIT() asm volatile("cp.async.commit_group;" ::: "memory")
#define CP_WAIT1()  asm volatile("cp.async.wait_group 1;" ::: "memory")
#define CP_WAIT0()  asm volatile("cp.async.wait_group 0;" ::: "memory")

// bf16 MMA (attention path)
__device__ __forceinline__ void mma_bf16(float* c, const uint32_t* a, const uint32_t* b) {
    asm volatile(
        "mma.sync.aligned.m16n8k16.row.col.f32.bf16.bf16.f32 "
        "{%0,%1,%2,%3}, {%4,%5,%6,%7}, {%8,%9}, {%0,%1,%2,%3};"
        : "+f"(c[0]), "+f"(c[1]), "+f"(c[2]), "+f"(c[3])
        : "r"(a[0]), "r"(a[1]), "r"(a[2]), "r"(a[3]), "r"(b[0]), "r"(b[1]));
}

// fp16 MMA (GEMM path) — identical fragment layout, different type
__device__ __forceinline__ void mma_f16(float* c, const uint32_t* a, const uint32_t* b) {
    asm volatile(
        "mma.sync.aligned.m16n8k16.row.col.f32.f16.f16.f32 "
        "{%0,%1,%2,%3}, {%4,%5,%6,%7}, {%8,%9}, {%0,%1,%2,%3};"
        : "+f"(c[0]), "+f"(c[1]), "+f"(c[2]), "+f"(c[3])
        : "r"(a[0]), "r"(a[1]), "r"(a[2]), "r"(a[3]), "r"(b[0]), "r"(b[1]));
}

__device__ __forceinline__ void ldm_x4(uint32_t* r, uint32_t addr) {
    asm volatile("ldmatrix.sync.aligned.m8n8.x4.shared.b16 {%0,%1,%2,%3}, [%4];"
        : "=r"(r[0]), "=r"(r[1]), "=r"(r[2]), "=r"(r[3]) : "r"(addr));
}

__device__ __forceinline__ void split2(float v, __nv_bfloat16& h, __nv_bfloat16& l) {
    h = __float2bfloat16(v);
    l = __float2bfloat16(v - __bfloat162float(h));
}
__device__ __forceinline__ void split2h(float v, __half& h, __half& l) {
    h = __float2half_rn(v);
    l = __float2half_rn(v - __half2float(h));
}

__device__ __forceinline__ uint32_t packbf(__nv_bfloat16 a, __nv_bfloat16 b) {
    __nv_bfloat162 t(a, b);   // a = low element
    return *(uint32_t*)&t;
}
__device__ __forceinline__ uint32_t packh(__half a, __half b) {
    __half2 t(a, b);          // a = low element
    return *(uint32_t*)&t;
}

// ---------------------------------------------------------------------------
// LayerNorm -> fp16 hi/lo split outputs (A operand of QKV GEMM)
// ---------------------------------------------------------------------------
__global__ __launch_bounds__(256) void ln_kernel(const float* __restrict__ x,
                                                 __half* __restrict__ yh,
                                                 __half* __restrict__ yl) {
    __shared__ float red_s[8], red_ss[8];
    __shared__ float sh_mu, sh_rstd;
    const int row = blockIdx.x;
    const int tid = threadIdx.x;
    const float* xr = x + (size_t)row * DD;

    float4 a = *(const float4*)(xr + tid * 4);
    float4 b = *(const float4*)(xr + 1024 + tid * 4);
    float s  = a.x + a.y + a.z + a.w + b.x + b.y + b.z + b.w;
    float ss = a.x*a.x + a.y*a.y + a.z*a.z + a.w*a.w
             + b.x*b.x + b.y*b.y + b.z*b.z + b.w*b.w;
    #pragma unroll
    for (int o = 16; o > 0; o >>= 1) {
        s  += __shfl_xor_sync(0xffffffffu, s, o);
        ss += __shfl_xor_sync(0xffffffffu, ss, o);
    }
    const int wid = tid >> 5, lane = tid & 31;
    if (lane == 0) { red_s[wid] = s; red_ss[wid] = ss; }
    __syncthreads();
    if (tid == 0) {
        float S = 0.f, SSq = 0.f;
        #pragma unroll
        for (int w = 0; w < 8; w++) { S += red_s[w]; SSq += red_ss[w]; }
        float mu = S * (1.0f / DD);
        float var = SSq * (1.0f / DD) - mu * mu;
        sh_mu = mu;
        sh_rstd = rsqrtf(var + LN_EPS);
    }
    __syncthreads();
    const float mu = sh_mu, rstd = sh_rstd;
    float va[8] = {a.x, a.y, a.z, a.w, b.x, b.y, b.z, b.w};
    #pragma unroll
    for (int e = 0; e < 8; e++) {
        float v = (va[e] - mu) * rstd;
        __half h, l;
        split2h(v, h, l);
        size_t col = (e < 4) ? (tid * 4 + e) : (1024 + tid * 4 + e - 4);
        yh[(size_t)row * DD + col] = h;
        yl[(size_t)row * DD + col] = l;
    }
}

// ---------------------------------------------------------------------------
// Transpose + round: W[K][N] fp32 -> fp16 [N][K] (single array)
// ---------------------------------------------------------------------------
__global__ __launch_bounds__(256) void transpose_h(const float* __restrict__ W,
                                                   __half* __restrict__ out,
                                                   int K, int N) {
    __shared__ float t[32][33];
    int n = blockIdx.x * 32 + threadIdx.x;
    int k = blockIdx.y * 32 + threadIdx.y;
    #pragma unroll
    for (int i = 0; i < 4; i++)
        t[threadIdx.y + 8 * i][threadIdx.x] = W[(size_t)(k + 8 * i) * N + n];
    __syncthreads();
    int ko = blockIdx.y * 32 + threadIdx.x;
    int no = blockIdx.x * 32 + threadIdx.y;
    #pragma unroll
    for (int i = 0; i < 4; i++) {
        float v = t[threadIdx.x][threadIdx.y + 8 * i];
        out[(size_t)(no + 8 * i) * K + ko] = __float2half_rn(v);
    }
}

// ---------------------------------------------------------------------------
// fp16 2-term GEMM: C[M,N] fp32 = (Ahi+Alo)[M,K] @ B[N,K]^T
// CTA 128x256, BK=32, 8 warps 64x64, ldmatrix, 3-stage cp.async ring.
// Structure identical to the proven split-bf16 GEMM; B is single-operand.
// ---------------------------------------------------------------------------
#define BM 128
#define BN 256
#define BKC 32
#define ROWB 80
#define A_TILE (128 * ROWB)                  // 10240
#define B_TILE (256 * ROWB)                  // 20480
#define STAGE_B (2 * A_TILE + B_TILE)        // 40960
#define NSTAGE 3
#define GEMM_SMEM (NSTAGE * STAGE_B)         // 122880

__global__ __launch_bounds__(256, 1) void gemm_f16(
    const __half* __restrict__ Ahi, const __half* __restrict__ Alo,
    const __half* __restrict__ Bm,
    float* __restrict__ C, int M, int N, int K)
{
    extern __shared__ __align__(16) char smem[];
    const uint32_t sb = smem_u32(smem);
    const int tid = threadIdx.x;
    const int wid = tid >> 5;
    const int lane = tid & 31;
    const int m0 = blockIdx.y * BM;
    const int n0 = blockIdx.x * BN;
    const int wm = (wid & 1) * 64;
    const int wn = (wid >> 1) * 64;

    float acc[4][8][4];
    #pragma unroll
    for (int mi = 0; mi < 4; mi++)
        #pragma unroll
        for (int ni = 0; ni < 8; ni++)
            #pragma unroll
            for (int e = 0; e < 4; e++) acc[mi][ni][e] = 0.f;

    // stage fill: 2048 x 16B chunks (A hi/lo 2x128 rows x4, B 256 rows x4)
    auto fill = [&](int stage, int k0) {
        const uint32_t sbase = sb + stage * STAGE_B;
        #pragma unroll
        for (int it = 0; it < 8; it++) {
            int i = it * 256 + tid;
            const __half* src;
            uint32_t dst;
            if (i < 1024) {
                int op = i >> 9, r = (i >> 2) & 127, c = i & 3;
                src = (op ? Alo : Ahi) + (size_t)(m0 + r) * K + k0 + c * 8;
                dst = sbase + op * A_TILE + r * ROWB + c * 16;
            } else {
                int j = i - 1024;
                int r = (j >> 2) & 255, c = j & 3;
                src = Bm + (size_t)(n0 + r) * K + k0 + c * 8;
                dst = sbase + 2 * A_TILE + r * ROWB + c * 16;
            }
            cpa16(dst, src);
        }
        CP_COMMIT();
    };

    const int nch = K / BKC;
    fill(0, 0);
    fill(1, BKC);

    const int lg = lane >> 3;
    const int lr = lane & 7;

    for (int c = 0; c < nch; c++) {
        if (c + 1 < nch) CP_WAIT1(); else CP_WAIT0();
        __syncthreads();

        if (c + 2 < nch) fill((c + 2) % NSTAGE, (c + 2) * BKC);

        const uint32_t sbase = sb + (c % NSTAGE) * STAGE_B;
        const uint32_t aHi = sbase;
        const uint32_t aLo = sbase + A_TILE;
        const uint32_t bT  = sbase + 2 * A_TILE;

        #pragma unroll
        for (int ks = 0; ks < 2; ks++) {
            const uint32_t koff = ks * 32;

            const uint32_t aoff = (lg & 1) * 8 * ROWB + (lg >> 1) * 16 + lr * ROWB + koff;
            uint32_t ah[4][4], al[4][4];
            #pragma unroll
            for (int mi = 0; mi < 4; mi++) {
                uint32_t ro = (wm + mi * 16) * ROWB + aoff;
                ldm_x4(ah[mi], aHi + ro);
                ldm_x4(al[mi], aLo + ro);
            }
            const uint32_t boff = (lg >> 1) * 8 * ROWB + (lg & 1) * 16 + lr * ROWB + koff;
            uint32_t bh[8][2];
            #pragma unroll
            for (int np = 0; np < 4; np++) {
                uint32_t ro = (wn + np * 16) * ROWB + boff;
                uint32_t t4[4];
                ldm_x4(t4, bT + ro);
                bh[2 * np][0] = t4[0]; bh[2 * np][1] = t4[1];
                bh[2 * np + 1][0] = t4[2]; bh[2 * np + 1][1] = t4[3];
            }

            // term-major: all Ah*B, then all Al*B
            #pragma unroll
            for (int mi = 0; mi < 4; mi++)
                #pragma unroll
                for (int ni = 0; ni < 8; ni++)
                    mma_f16(acc[mi][ni], ah[mi], bh[ni]);
            #pragma unroll
            for (int mi = 0; mi < 4; mi++)
                #pragma unroll
                for (int ni = 0; ni < 8; ni++)
                    mma_f16(acc[mi][ni], al[mi], bh[ni]);
        }
    }

    const int r4 = lane >> 2;
    const int k4 = lane & 3;
    #pragma unroll
    for (int mi = 0; mi < 4; mi++) {
        int r0 = m0 + wm + mi * 16 + r4;
        #pragma unroll
        for (int ni = 0; ni < 8; ni++) {
            int cc = n0 + wn + ni * 8 + k4 * 2;
            float2 v0 = {acc[mi][ni][0], acc[mi][ni][1]};
            float2 v1 = {acc[mi][ni][2], acc[mi][ni][3]};
            *(float2*)(C + (size_t)r0 * N + cc) = v0;
            *(float2*)(C + (size_t)(r0 + 8) * N + cc) = v1;
        }
    }
}

// ---------------------------------------------------------------------------
// RoPE + split for Q,K: fp32 qkv -> per-head K-major bf16 hi/lo [b][h][s][d]
// ---------------------------------------------------------------------------
__global__ __launch_bounds__(256) void rope_split(const float* __restrict__ qkv,
                                                  __nv_bfloat16* __restrict__ qh,
                                                  __nv_bfloat16* __restrict__ ql,
                                                  __nv_bfloat16* __restrict__ kh,
                                                  __nv_bfloat16* __restrict__ kl) {
    const int t = blockIdx.x;            // token
    const int b = t / SS, s = t % SS;
    const int tid = threadIdx.x;

    #pragma unroll
    for (int w = 0; w < 4; w++) {
        int idx = w * 256 + tid;          // (h, dpair)
        int h = idx >> 6, dp = idx & 63;

        float inv_freq = powf(10000.0f, -(float)dp * (1.0f / 64.0f));
        float ang = (float)s * inv_freq;
        float c = cosf(ang), sn = sinf(ang);

        const float* src = qkv + (size_t)t * QKV_N + h * DHH;
        size_t obase = ((size_t)(b * HH + h) * SS + s) * DHH;
        __nv_bfloat16 hh, ll;

        // q
        float x1 = src[dp], x2 = src[dp + 64];
        float r1 = x1 * c - x2 * sn;
        float r2 = x2 * c + x1 * sn;
        split2(r1, hh, ll); qh[obase + dp] = hh;      ql[obase + dp] = ll;
        split2(r2, hh, ll); qh[obase + dp + 64] = hh; ql[obase + dp + 64] = ll;

        // k
        x1 = src[DD + dp]; x2 = src[DD + dp + 64];
        r1 = x1 * c - x2 * sn;
        r2 = x2 * c + x1 * sn;
        split2(r1, hh, ll); kh[obase + dp] = hh;      kl[obase + dp] = ll;
        split2(r2, hh, ll); kh[obase + dp + 64] = hh; kl[obase + dp + 64] = ll;
    }
}

// ---------------------------------------------------------------------------
// V transpose + split: fp32 qkv v-slice -> [b][h][d][s] bf16 hi/lo
// ---------------------------------------------------------------------------
__global__ __launch_bounds__(256) void v_split_transpose(const float* __restrict__ qkv,
                                                         __nv_bfloat16* __restrict__ vth,
                                                         __nv_bfloat16* __restrict__ vtl) {
    __shared__ float sm[64 * 132];
    const int s0 = blockIdx.x * 64;
    const int h  = blockIdx.y;
    const int b  = blockIdx.z;
    const int tid = threadIdx.x;

    #pragma unroll
    for (int i = 0; i < 32; i++) {
        int idx = i * 256 + tid;
        int sl = idx >> 7, d = idx & 127;
        sm[sl * 132 + d] = qkv[((size_t)(b * SS + s0 + sl)) * QKV_N + 2 * DD + h * DHH + d];
    }
    __syncthreads();

    const int d = tid >> 1;
    const int sh = (tid & 1) * 32;
    size_t row = ((size_t)(b * HH + h) * DHH + d) * SS + s0 + sh;
    #pragma unroll
    for (int j = 0; j < 32; j += 2) {
        float v0 = sm[(sh + j) * 132 + d];
        float v1 = sm[(sh + j + 1) * 132 + d];
        __nv_bfloat16 h0, l0, h1, l1;
        split2(v0, h0, l0); split2(v1, h1, l1);
        *(uint32_t*)(vth + row + j) = packbf(h0, h1);
        *(uint32_t*)(vtl + row + j) = packbf(l0, l1);
    }
}

// ---------------------------------------------------------------------------
// Flash attention v6 (proven): reg-resident Q, double-buffered K, prefetched V.
// Epilogue now emits fp16 hi/lo for the out-proj GEMM.
// ---------------------------------------------------------------------------
#define QROW 272
#define VROW 144
#define F6_KST(s) ((s) * 34816)            // K stage s: KH at +0, KL at +17408
#define F6_KL_OFF 17408
#define F6_VH (2 * 34816)                  // 69632
#define F6_VL (F6_VH + 128 * VROW)         // 88064
#define FLASH6_SMEM (F6_VL + 128 * VROW)   // 106496 bytes -> 2 CTAs/SM

__global__ __launch_bounds__(128) void flash6_kernel(
    const __nv_bfloat16* __restrict__ qh, const __nv_bfloat16* __restrict__ ql,
    const __nv_bfloat16* __restrict__ kh, const __nv_bfloat16* __restrict__ kl,
    const __nv_bfloat16* __restrict__ vth, const __nv_bfloat16* __restrict__ vtl,
    __half* __restrict__ attn_hi, __half* __restrict__ attn_lo)
{
    extern __shared__ __align__(16) char smem[];
    const uint32_t sb = smem_u32(smem);

    const int qb = blockIdx.x;
    const int h  = blockIdx.y;
    const int b  = blockIdx.z;
    const int tid = threadIdx.x;
    const int wid = tid >> 5;
    const int lane = tid & 31;
    const int r4 = lane >> 2;
    const int k4 = lane & 3;

    const size_t bh = (size_t)(b * HH + h);
    const __nv_bfloat16* qhp = qh + (bh * SS + qb * 64) * DHH;
    const __nv_bfloat16* qlp = ql + (bh * SS + qb * 64) * DHH;

    // ---- prologue: stage Q (64x128 hi/lo) into K-stage area, read frags ----
    for (int i = tid; i < 2048; i += 128) {
        int op = i >> 10, j = i & 1023;
        int row = j >> 4, c = j & 15;
        const __nv_bfloat16* src = (op ? qlp : qhp) + row * DHH + c * 8;
        uint4 v = *(const uint4*)src;
        *(uint4*)(smem + op * 17408 + row * QROW + c * 16) = v;
    }
    __syncthreads();

    const int arow = wid * 16 + r4;
    uint32_t qah[8][4], qal[8][4];
    #pragma unroll
    for (int kb = 0; kb < 8; kb++) {
        const uint32_t koff = kb * 32 + k4 * 4;
        qah[kb][0] = *(const uint32_t*)(smem + arow * QROW + koff);
        qah[kb][1] = *(const uint32_t*)(smem + (arow + 8) * QROW + koff);
        qah[kb][2] = *(const uint32_t*)(smem + arow * QROW + koff + 16);
        qah[kb][3] = *(const uint32_t*)(smem + (arow + 8) * QROW + koff + 16);
        qal[kb][0] = *(const uint32_t*)(smem + 17408 + arow * QROW + koff);
        qal[kb][1] = *(const uint32_t*)(smem + 17408 + (arow + 8) * QROW + koff);
        qal[kb][2] = *(const uint32_t*)(smem + 17408 + arow * QROW + koff + 16);
        qal[kb][3] = *(const uint32_t*)(smem + 17408 + (arow + 8) * QROW + koff + 16);
    }
    __syncthreads();   // Q fully consumed before cp.async overwrites the area

    auto fillK = [&](int s, int kt) {
        const __nv_bfloat16* khp = kh + (bh * SS + kt * 64) * DHH;
        const __nv_bfloat16* klp = kl + (bh * SS + kt * 64) * DHH;
        const uint32_t kbase = sb + F6_KST(s);
        #pragma unroll
        for (int it = 0; it < 16; it++) {
            int i = it * 128 + tid;
            int op = i >> 10, j = i & 1023;
            int row = j >> 4, c = j & 15;
            cpa16(kbase + op * F6_KL_OFF + row * QROW + c * 16,
                  (op ? klp : khp) + row * DHH + c * 8);
        }
        CP_COMMIT();
    };
    auto fillV = [&](int kt) {
        const __nv_bfloat16* vhp = vth + bh * DHH * SS + kt * 64;
        const __nv_bfloat16* vlp = vtl + bh * DHH * SS + kt * 64;
        #pragma unroll
        for (int it = 0; it < 16; it++) {
            int i = it * 128 + tid;
            int op = i >> 10, j = i & 1023;
            int d = j >> 3, c = j & 7;
            cpa16(sb + (op ? F6_VL : F6_VH) + d * VROW + c * 16,
                  (op ? vlp : vhp) + (size_t)d * SS + c * 8);
        }
        CP_COMMIT();
    };

    float oacc[16][4];
    #pragma unroll
    for (int n = 0; n < 16; n++)
        #pragma unroll
        for (int e = 0; e < 4; e++) oacc[n][e] = 0.f;

    float m0 = -1e30f, m1 = -1e30f, l0 = 0.f, l1 = 0.f;
    const float scale = 0.088388347648318447f;
    const int nkt = qb + 1;

    fillK(0, 0);
    fillV(0);

    for (int kt = 0; kt < nkt; kt++) {
        if (kt + 1 < nkt) {
            fillK((kt + 1) & 1, kt + 1);
            CP_WAIT1();
        } else {
            CP_WAIT0();
        }
        __syncthreads();

        const char* kst = smem + F6_KST(kt & 1);

        float sacc[8][4];
        #pragma unroll
        for (int n = 0; n < 8; n++)
            #pragma unroll
            for (int e = 0; e < 4; e++) sacc[n][e] = 0.f;

        #pragma unroll
        for (int kb = 0; kb < 8; kb++) {
            const uint32_t koff = kb * 32 + k4 * 4;
            #pragma unroll
            for (int ng = 0; ng < 8; ng++) {
                const uint32_t bro = (ng * 8 + r4) * QROW + koff;
                uint32_t bh2[2], bl2[2];
                bh2[0] = *(const uint32_t*)(kst + bro);
                bh2[1] = *(const uint32_t*)(kst + bro + 16);
                bl2[0] = *(const uint32_t*)(kst + F6_KL_OFF + bro);
                bl2[1] = *(const uint32_t*)(kst + F6_KL_OFF + bro + 16);
                mma_bf16(sacc[ng], qah[kb], bh2);
                mma_bf16(sacc[ng], qah[kb], bl2);
                mma_bf16(sacc[ng], qal[kb], bh2);
            }
        }

        const int row0 = qb * 64 + wid * 16 + r4;
        if (kt == qb) {
            #pragma unroll
            for (int ng = 0; ng < 8; ng++) {
                int colb = kt * 64 + ng * 8 + k4 * 2;
                sacc[ng][0] = (colb     > row0)     ? -1e30f : sacc[ng][0] * scale;
                sacc[ng][1] = (colb + 1 > row0)     ? -1e30f : sacc[ng][1] * scale;
                sacc[ng][2] = (colb     > row0 + 8) ? -1e30f : sacc[ng][2] * scale;
                sacc[ng][3] = (colb + 1 > row0 + 8) ? -1e30f : sacc[ng][3] * scale;
            }
        } else {
            #pragma unroll
            for (int ng = 0; ng < 8; ng++)
                #pragma unroll
                for (int e = 0; e < 4; e++) sacc[ng][e] *= scale;
        }

        float mx0 = -1e30f, mx1 = -1e30f;
        #pragma unroll
        for (int ng = 0; ng < 8; ng++) {
            mx0 = fmaxf(mx0, fmaxf(sacc[ng][0], sacc[ng][1]));
            mx1 = fmaxf(mx1, fmaxf(sacc[ng][2], sacc[ng][3]));
        }
        mx0 = fmaxf(mx0, __shfl_xor_sync(0xffffffffu, mx0, 1));
        mx0 = fmaxf(mx0, __shfl_xor_sync(0xffffffffu, mx0, 2));
        mx1 = fmaxf(mx1, __shfl_xor_sync(0xffffffffu, mx1, 1));
        mx1 = fmaxf(mx1, __shfl_xor_sync(0xffffffffu, mx1, 2));

        float mn0 = fmaxf(m0, mx0), mn1 = fmaxf(m1, mx1);
        float c0 = __expf(m0 - mn0), c1 = __expf(m1 - mn1);
        m0 = mn0; m1 = mn1;

        float sum0 = 0.f, sum1 = 0.f;
        uint32_t ph2[8][2], pl2[8][2];
        #pragma unroll
        for (int ng = 0; ng < 8; ng++) {
            float p0 = __expf(sacc[ng][0] - m0);
            float p1 = __expf(sacc[ng][1] - m0);
            float p2 = __expf(sacc[ng][2] - m1);
            float p3 = __expf(sacc[ng][3] - m1);
            sum0 += p0 + p1; sum1 += p2 + p3;
            __nv_bfloat16 a, bq, cc, dd2, la, lb, lc, ld;
            split2(p0, a, la); split2(p1, bq, lb);
            split2(p2, cc, lc); split2(p3, dd2, ld);
            ph2[ng][0] = packbf(a, bq);  ph2[ng][1] = packbf(cc, dd2);
            pl2[ng][0] = packbf(la, lb); pl2[ng][1] = packbf(lc, ld);
        }
        sum0 += __shfl_xor_sync(0xffffffffu, sum0, 1);
        sum0 += __shfl_xor_sync(0xffffffffu, sum0, 2);
        sum1 += __shfl_xor_sync(0xffffffffu, sum1, 1);
        sum1 += __shfl_xor_sync(0xffffffffu, sum1, 2);
        l0 = l0 * c0 + sum0;
        l1 = l1 * c1 + sum1;

        #pragma unroll
        for (int n = 0; n < 16; n++) {
            oacc[n][0] *= c0; oacc[n][1] *= c0;
            oacc[n][2] *= c1; oacc[n][3] *= c1;
        }

        #pragma unroll
        for (int kb = 0; kb < 4; kb++) {
            uint32_t pa[4] = {ph2[2*kb][0], ph2[2*kb][1], ph2[2*kb+1][0], ph2[2*kb+1][1]};
            uint32_t pb[4] = {pl2[2*kb][0], pl2[2*kb][1], pl2[2*kb+1][0], pl2[2*kb+1][1]};
            const uint32_t koff = kb * 32 + k4 * 4;
            #pragma unroll
            for (int ng = 0; ng < 16; ng++) {
                const uint32_t vro = (ng * 8 + r4) * VROW + koff;
                uint32_t vh[2], vl[2];
                vh[0] = *(const uint32_t*)(smem + F6_VH + vro);
                vh[1] = *(const uint32_t*)(smem + F6_VH + vro + 16);
                vl[0] = *(const uint32_t*)(smem + F6_VL + vro);
                vl[1] = *(const uint32_t*)(smem + F6_VL + vro + 16);
                mma_bf16(oacc[ng], pa, vh);
                mma_bf16(oacc[ng], pa, vl);
                mma_bf16(oacc[ng], pb, vh);
            }
        }

        __syncthreads();
        if (kt + 1 < nkt) fillV(kt + 1);
    }

    // ---- epilogue: normalize, fp16-split, store for out-proj ----
    const float inv0 = 1.0f / l0, inv1 = 1.0f / l1;
    const int grow0 = b * SS + qb * 64 + wid * 16 + r4;
    #pragma unroll
    for (int ng = 0; ng < 16; ng++) {
        size_t o0 = (size_t)grow0 * DD + h * DHH + ng * 8 + k4 * 2;
        size_t o1 = o0 + (size_t)8 * DD;
        float v0 = oacc[ng][0] * inv0, v1 = oacc[ng][1] * inv0;
        float v2 = oacc[ng][2] * inv1, v3 = oacc[ng][3] * inv1;
        __half h0, l0b, h1, l1b, h2, l2b, h3, l3b;
        split2h(v0, h0, l0b); split2h(v1, h1, l1b);
        split2h(v2, h2, l2b); split2h(v3, h3, l3b);
        *(uint32_t*)(attn_hi + o0) = packh(h0, h1);
        *(uint32_t*)(attn_lo + o0) = packh(l0b, l1b);
        *(uint32_t*)(attn_hi + o1) = packh(h2, h3);
        *(uint32_t*)(attn_lo + o1) = packh(l2b, l3b);
    }
}

// ---------------------------------------------------------------------------
// kernel_launch: inputs = [positions, hidden_states, w_qkv, w_out]
// ---------------------------------------------------------------------------
extern "C" void kernel_launch(void* const* d_in, const int* in_sizes, int n_in,
                              void* d_out, int out_size) {
    const float* hidden = (const float*)d_in[1];
    const float* w_qkv  = (const float*)d_in[2];
    const float* w_out  = (const float*)d_in[3];
    float* out = (float*)d_out;

    __half *xh, *xl, *wqT, *woT, *ah, *al;
    __nv_bfloat16 *qh, *ql, *kh, *kl, *vth, *vtl;
    float* qkv;
    cudaGetSymbolAddress((void**)&xh,  g_xh);
    cudaGetSymbolAddress((void**)&xl,  g_xl);
    cudaGetSymbolAddress((void**)&qkv, g_qkv);
    cudaGetSymbolAddress((void**)&wqT, g_wqkvT);
    cudaGetSymbolAddress((void**)&woT, g_woutT);
    cudaGetSymbolAddress((void**)&ah,  g_ah);
    cudaGetSymbolAddress((void**)&al,  g_al);
    cudaGetSymbolAddress((void**)&qh,  g_qh);
    cudaGetSymbolAddress((void**)&ql,  g_ql);
    cudaGetSymbolAddress((void**)&kh,  g_kh);
    cudaGetSymbolAddress((void**)&kl,  g_kl);
    cudaGetSymbolAddress((void**)&vth, g_vth);
    cudaGetSymbolAddress((void**)&vtl, g_vtl);

    // 1) LayerNorm -> fp16 hi/lo
    ln_kernel<<<NTOK, 256>>>(hidden, xh, xl);

    // 2) Weight transpose -> fp16 (single)
    dim3 tb(32, 8);
    transpose_h<<<dim3(QKV_N / 32, DD / 32), tb>>>(w_qkv, wqT, DD, QKV_N);
    transpose_h<<<dim3(DD / 32, DD / 32), tb>>>(w_out, woT, DD, DD);

    // 3) QKV projection: fp16 2-term GEMM
    cudaFuncSetAttribute(gemm_f16, cudaFuncAttributeMaxDynamicSharedMemorySize, GEMM_SMEM);
    gemm_f16<<<dim3(QKV_N / BN, NTOK / BM), 256, GEMM_SMEM>>>(
        xh, xl, wqT, qkv, NTOK, QKV_N, DD);

    // 4) RoPE + split Q,K; transpose + split V (bf16, proven)
    rope_split<<<NTOK, 256>>>(qkv, qh, ql, kh, kl);
    v_split_transpose<<<dim3(SS / 64, HH, BB), 256>>>(qkv, vth, vtl);

    // 5) Causal flash attention v6 (proven core), fp16 hi/lo epilogue
    cudaFuncSetAttribute(flash6_kernel, cudaFuncAttributeMaxDynamicSharedMemorySize,
                         FLASH6_SMEM);
    flash6_kernel<<<dim3(SS / 64, HH, BB), 128, FLASH6_SMEM>>>(
        qh, ql, kh, kl, vth, vtl, ah, al);

    // 6) Output projection: fp16 2-term GEMM
    gemm_f16<<<dim3(DD / BN, NTOK / BM), 256, GEMM_SMEM>>>(
        ah, al, woT, out, NTOK, DD, DD);
}

// round 12
// speedup vs baseline: 1.5476x; 1.1348x over previous
#include <cuda_runtime.h>
#include <cuda_bf16.h>
#include <cuda_fp16.h>
#include <math.h>
#include <cstdint>

// ---------------------------------------------------------------------------
// Problem constants: B=2, S=2048, D=2048, H=16, DH=128
// ---------------------------------------------------------------------------
#define BB 2
#define SS 2048
#define DD 2048
#define HH 16
#define DHH 128
#define NTOK (BB * SS)          // 4096
#define QKV_N (3 * DD)          // 6144
#define LN_EPS 1e-5f

// ---------------------------------------------------------------------------
// Scratch (device globals; allocation forbidden)
// ---------------------------------------------------------------------------
__device__ __half g_xh[(size_t)NTOK * DD];          // LN out hi (fp16)
__device__ __half g_xl[(size_t)NTOK * DD];          // LN out lo (fp16)
__device__ float  g_qkv[(size_t)NTOK * QKV_N];      // 100.7 MB
__device__ __half g_wqkvT[(size_t)QKV_N * DD];      // W_qkv^T (fp16)
__device__ __half g_woutT[(size_t)DD * DD];         // W_out^T (fp16)
__device__ __half g_ah[(size_t)NTOK * DD];          // attn hi (fp16)
__device__ __half g_al[(size_t)NTOK * DD];          // attn lo (fp16)
// pre-split attention operands (fp16 2-term scheme)
__device__ __half g_qhh[(size_t)NTOK * DD];   // Q hi [b][h][s][d]
__device__ __half g_qll[(size_t)NTOK * DD];   // Q lo
__device__ __half g_kk[(size_t)NTOK * DD];    // K single fp16
__device__ __half g_vt[(size_t)NTOK * DD];    // V^T single fp16 [b][h][d][s]

// ---------------------------------------------------------------------------
// helpers
// ---------------------------------------------------------------------------
__device__ __forceinline__ uint32_t smem_u32(const void* p) {
    uint32_t a;
    asm("{ .reg .u64 t; cvta.to.shared.u64 t, %1; cvt.u32.u64 %0, t; }"
        : "=r"(a) : "l"(p));
    return a;
}

__device__ __forceinline__ void cpa16(uint32_t dst, const void* src) {
    asm volatile("cp.async.cg.shared.global [%0], [%1], 16;" :: "r"(dst), "l"(src) : "memory");
}
#define CP_COMMIT() asm volatile("cp.async.commit_group;" ::: "memory")
#define CP_WAIT1()  asm volatile("cp.async.wait_group 1;" ::: "memory")
#define CP_WAIT0()  asm volatile("cp.async.wait_group 0;" ::: "memory")

__device__ __forceinline__ void mma_f16(float* c, const uint32_t* a, const uint32_t* b) {
    asm volatile(
        "mma.sync.aligned.m16n8k16.row.col.f32.f16.f16.f32 "
        "{%0,%1,%2,%3}, {%4,%5,%6,%7}, {%8,%9}, {%0,%1,%2,%3};"
        : "+f"(c[0]), "+f"(c[1]), "+f"(c[2]), "+f"(c[3])
        : "r"(a[0]), "r"(a[1]), "r"(a[2]), "r"(a[3]), "r"(b[0]), "r"(b[1]));
}

__device__ __forceinline__ void ldm_x4(uint32_t* r, uint32_t addr) {
    asm volatile("ldmatrix.sync.aligned.m8n8.x4.shared.b16 {%0,%1,%2,%3}, [%4];"
        : "=r"(r[0]), "=r"(r[1]), "=r"(r[2]), "=r"(r[3]) : "r"(addr));
}

__device__ __forceinline__ void split2h(float v, __half& h, __half& l) {
    h = __float2half_rn(v);
    l = __float2half_rn(v - __half2float(h));
}

__device__ __forceinline__ uint32_t packh(__half a, __half b) {
    __half2 t(a, b);          // a = low element
    return *(uint32_t*)&t;
}

// ---------------------------------------------------------------------------
// LayerNorm -> fp16 hi/lo split outputs (A operand of QKV GEMM)
// ---------------------------------------------------------------------------
__global__ __launch_bounds__(256) void ln_kernel(const float* __restrict__ x,
                                                 __half* __restrict__ yh,
                                                 __half* __restrict__ yl) {
    __shared__ float red_s[8], red_ss[8];
    __shared__ float sh_mu, sh_rstd;
    const int row = blockIdx.x;
    const int tid = threadIdx.x;
    const float* xr = x + (size_t)row * DD;

    float4 a = *(const float4*)(xr + tid * 4);
    float4 b = *(const float4*)(xr + 1024 + tid * 4);
    float s  = a.x + a.y + a.z + a.w + b.x + b.y + b.z + b.w;
    float ss = a.x*a.x + a.y*a.y + a.z*a.z + a.w*a.w
             + b.x*b.x + b.y*b.y + b.z*b.z + b.w*b.w;
    #pragma unroll
    for (int o = 16; o > 0; o >>= 1) {
        s  += __shfl_xor_sync(0xffffffffu, s, o);
        ss += __shfl_xor_sync(0xffffffffu, ss, o);
    }
    const int wid = tid >> 5, lane = tid & 31;
    if (lane == 0) { red_s[wid] = s; red_ss[wid] = ss; }
    __syncthreads();
    if (tid == 0) {
        float S = 0.f, SSq = 0.f;
        #pragma unroll
        for (int w = 0; w < 8; w++) { S += red_s[w]; SSq += red_ss[w]; }
        float mu = S * (1.0f / DD);
        float var = SSq * (1.0f / DD) - mu * mu;
        sh_mu = mu;
        sh_rstd = rsqrtf(var + LN_EPS);
    }
    __syncthreads();
    const float mu = sh_mu, rstd = sh_rstd;
    float va[8] = {a.x, a.y, a.z, a.w, b.x, b.y, b.z, b.w};
    #pragma unroll
    for (int e = 0; e < 8; e++) {
        float v = (va[e] - mu) * rstd;
        __half h, l;
        split2h(v, h, l);
        size_t col = (e < 4) ? (tid * 4 + e) : (1024 + tid * 4 + e - 4);
        yh[(size_t)row * DD + col] = h;
        yl[(size_t)row * DD + col] = l;
    }
}

// ---------------------------------------------------------------------------
// Transpose + round: W[K][N] fp32 -> fp16 [N][K]
// ---------------------------------------------------------------------------
__global__ __launch_bounds__(256) void transpose_h(const float* __restrict__ W,
                                                   __half* __restrict__ out,
                                                   int K, int N) {
    __shared__ float t[32][33];
    int n = blockIdx.x * 32 + threadIdx.x;
    int k = blockIdx.y * 32 + threadIdx.y;
    #pragma unroll
    for (int i = 0; i < 4; i++)
        t[threadIdx.y + 8 * i][threadIdx.x] = W[(size_t)(k + 8 * i) * N + n];
    __syncthreads();
    int ko = blockIdx.y * 32 + threadIdx.x;
    int no = blockIdx.x * 32 + threadIdx.y;
    #pragma unroll
    for (int i = 0; i < 4; i++) {
        float v = t[threadIdx.x][threadIdx.y + 8 * i];
        out[(size_t)(no + 8 * i) * K + ko] = __float2half_rn(v);
    }
}

// ---------------------------------------------------------------------------
// fp16 2-term GEMM (unchanged from round 11 — proven)
// ---------------------------------------------------------------------------
#define BM 128
#define BN 256
#define BKC 32
#define ROWB 80
#define A_TILE (128 * ROWB)
#define B_TILE (256 * ROWB)
#define STAGE_B (2 * A_TILE + B_TILE)
#define NSTAGE 3
#define GEMM_SMEM (NSTAGE * STAGE_B)

__global__ __launch_bounds__(256, 1) void gemm_f16(
    const __half* __restrict__ Ahi, const __half* __restrict__ Alo,
    const __half* __restrict__ Bm,
    float* __restrict__ C, int M, int N, int K)
{
    extern __shared__ __align__(16) char smem[];
    const uint32_t sb = smem_u32(smem);
    const int tid = threadIdx.x;
    const int wid = tid >> 5;
    const int lane = tid & 31;
    const int m0 = blockIdx.y * BM;
    const int n0 = blockIdx.x * BN;
    const int wm = (wid & 1) * 64;
    const int wn = (wid >> 1) * 64;

    float acc[4][8][4];
    #pragma unroll
    for (int mi = 0; mi < 4; mi++)
        #pragma unroll
        for (int ni = 0; ni < 8; ni++)
            #pragma unroll
            for (int e = 0; e < 4; e++) acc[mi][ni][e] = 0.f;

    auto fill = [&](int stage, int k0) {
        const uint32_t sbase = sb + stage * STAGE_B;
        #pragma unroll
        for (int it = 0; it < 8; it++) {
            int i = it * 256 + tid;
            const __half* src;
            uint32_t dst;
            if (i < 1024) {
                int op = i >> 9, r = (i >> 2) & 127, c = i & 3;
                src = (op ? Alo : Ahi) + (size_t)(m0 + r) * K + k0 + c * 8;
                dst = sbase + op * A_TILE + r * ROWB + c * 16;
            } else {
                int j = i - 1024;
                int r = (j >> 2) & 255, c = j & 3;
                src = Bm + (size_t)(n0 + r) * K + k0 + c * 8;
                dst = sbase + 2 * A_TILE + r * ROWB + c * 16;
            }
            cpa16(dst, src);
        }
        CP_COMMIT();
    };

    const int nch = K / BKC;
    fill(0, 0);
    fill(1, BKC);

    const int lg = lane >> 3;
    const int lr = lane & 7;

    for (int c = 0; c < nch; c++) {
        if (c + 1 < nch) CP_WAIT1(); else CP_WAIT0();
        __syncthreads();

        if (c + 2 < nch) fill((c + 2) % NSTAGE, (c + 2) * BKC);

        const uint32_t sbase = sb + (c % NSTAGE) * STAGE_B;
        const uint32_t aHi = sbase;
        const uint32_t aLo = sbase + A_TILE;
        const uint32_t bT  = sbase + 2 * A_TILE;

        #pragma unroll
        for (int ks = 0; ks < 2; ks++) {
            const uint32_t koff = ks * 32;

            const uint32_t aoff = (lg & 1) * 8 * ROWB + (lg >> 1) * 16 + lr * ROWB + koff;
            uint32_t ah[4][4], al[4][4];
            #pragma unroll
            for (int mi = 0; mi < 4; mi++) {
                uint32_t ro = (wm + mi * 16) * ROWB + aoff;
                ldm_x4(ah[mi], aHi + ro);
                ldm_x4(al[mi], aLo + ro);
            }
            const uint32_t boff = (lg >> 1) * 8 * ROWB + (lg & 1) * 16 + lr * ROWB + koff;
            uint32_t bh[8][2];
            #pragma unroll
            for (int np = 0; np < 4; np++) {
                uint32_t ro = (wn + np * 16) * ROWB + boff;
                uint32_t t4[4];
                ldm_x4(t4, bT + ro);
                bh[2 * np][0] = t4[0]; bh[2 * np][1] = t4[1];
                bh[2 * np + 1][0] = t4[2]; bh[2 * np + 1][1] = t4[3];
            }

            #pragma unroll
            for (int mi = 0; mi < 4; mi++)
                #pragma unroll
                for (int ni = 0; ni < 8; ni++)
                    mma_f16(acc[mi][ni], ah[mi], bh[ni]);
            #pragma unroll
            for (int mi = 0; mi < 4; mi++)
                #pragma unroll
                for (int ni = 0; ni < 8; ni++)
                    mma_f16(acc[mi][ni], al[mi], bh[ni]);
        }
    }

    const int r4 = lane >> 2;
    const int k4 = lane & 3;
    #pragma unroll
    for (int mi = 0; mi < 4; mi++) {
        int r0 = m0 + wm + mi * 16 + r4;
        #pragma unroll
        for (int ni = 0; ni < 8; ni++) {
            int cc = n0 + wn + ni * 8 + k4 * 2;
            float2 v0 = {acc[mi][ni][0], acc[mi][ni][1]};
            float2 v1 = {acc[mi][ni][2], acc[mi][ni][3]};
            *(float2*)(C + (size_t)r0 * N + cc) = v0;
            *(float2*)(C + (size_t)(r0 + 8) * N + cc) = v1;
        }
    }
}

// ---------------------------------------------------------------------------
// RoPE + split: fp32 qkv -> Q fp16 hi/lo, K fp16 single, [b][h][s][d]
// ---------------------------------------------------------------------------
__global__ __launch_bounds__(256) void rope_split(const float* __restrict__ qkv,
                                                  __half* __restrict__ qh,
                                                  __half* __restrict__ ql,
                                                  __half* __restrict__ kk) {
    const int t = blockIdx.x;            // token
    const int b = t / SS, s = t % SS;
    const int tid = threadIdx.x;

    #pragma unroll
    for (int w = 0; w < 4; w++) {
        int idx = w * 256 + tid;          // (h, dpair)
        int h = idx >> 6, dp = idx & 63;

        float inv_freq = powf(10000.0f, -(float)dp * (1.0f / 64.0f));
        float ang = (float)s * inv_freq;
        float c = cosf(ang), sn = sinf(ang);

        const float* src = qkv + (size_t)t * QKV_N + h * DHH;
        size_t obase = ((size_t)(b * HH + h) * SS + s) * DHH;
        __half hh, ll;

        // q (split hi/lo)
        float x1 = src[dp], x2 = src[dp + 64];
        float r1 = x1 * c - x2 * sn;
        float r2 = x2 * c + x1 * sn;
        split2h(r1, hh, ll); qh[obase + dp] = hh;      ql[obase + dp] = ll;
        split2h(r2, hh, ll); qh[obase + dp + 64] = hh; ql[obase + dp + 64] = ll;

        // k (single fp16)
        x1 = src[DD + dp]; x2 = src[DD + dp + 64];
        r1 = x1 * c - x2 * sn;
        r2 = x2 * c + x1 * sn;
        kk[obase + dp]      = __float2half_rn(r1);
        kk[obase + dp + 64] = __float2half_rn(r2);
    }
}

// ---------------------------------------------------------------------------
// V transpose: fp32 qkv v-slice -> [b][h][d][s] fp16 single
// ---------------------------------------------------------------------------
__global__ __launch_bounds__(256) void v_transpose_h(const float* __restrict__ qkv,
                                                     __half* __restrict__ vt) {
    __shared__ float sm[64 * 132];
    const int s0 = blockIdx.x * 64;
    const int h  = blockIdx.y;
    const int b  = blockIdx.z;
    const int tid = threadIdx.x;

    #pragma unroll
    for (int i = 0; i < 32; i++) {
        int idx = i * 256 + tid;
        int sl = idx >> 7, d = idx & 127;
        sm[sl * 132 + d] = qkv[((size_t)(b * SS + s0 + sl)) * QKV_N + 2 * DD + h * DHH + d];
    }
    __syncthreads();

    const int d = tid >> 1;
    const int sh = (tid & 1) * 32;
    size_t row = ((size_t)(b * HH + h) * DHH + d) * SS + s0 + sh;
    #pragma unroll
    for (int j = 0; j < 32; j += 2) {
        float v0 = sm[(sh + j) * 132 + d];
        float v1 = sm[(sh + j + 1) * 132 + d];
        *(uint32_t*)(vt + row + j) = packh(__float2half_rn(v0), __float2half_rn(v1));
    }
}

// ---------------------------------------------------------------------------
// Flash attention v7: fp16 2-term (Q hi/lo + K single, P hi/lo + V single).
// Reg-resident Q, double-buffered K, prefetched V, 2 CTAs/SM.
// Pipeline/wait structure identical to proven flash6.
// ---------------------------------------------------------------------------
#define QROW 272
#define VROW 144
#define F7_KST(s) ((s) * 17408)            // K stage s (single fp16)
#define F7_V (2 * 17408)                   // 34816
#define FLASH7_SMEM (F7_V + 128 * VROW)    // 53248 bytes

__global__ __launch_bounds__(128) void flash7_kernel(
    const __half* __restrict__ qh, const __half* __restrict__ ql,
    const __half* __restrict__ kk, const __half* __restrict__ vt,
    __half* __restrict__ attn_hi, __half* __restrict__ attn_lo)
{
    extern __shared__ __align__(16) char smem[];
    const uint32_t sb = smem_u32(smem);

    const int qb = blockIdx.x;
    const int h  = blockIdx.y;
    const int b  = blockIdx.z;
    const int tid = threadIdx.x;
    const int wid = tid >> 5;
    const int lane = tid & 31;
    const int r4 = lane >> 2;
    const int k4 = lane & 3;

    const size_t bh = (size_t)(b * HH + h);
    const __half* qhp = qh + (bh * SS + qb * 64) * DHH;
    const __half* qlp = ql + (bh * SS + qb * 64) * DHH;

    // ---- prologue: stage Q hi/lo into K-stage area, read frags to regs ----
    for (int i = tid; i < 2048; i += 128) {
        int op = i >> 10, j = i & 1023;
        int row = j >> 4, c = j & 15;
        const __half* src = (op ? qlp : qhp) + row * DHH + c * 8;
        uint4 v = *(const uint4*)src;
        *(uint4*)(smem + op * 17408 + row * QROW + c * 16) = v;
    }
    __syncthreads();

    const int arow = wid * 16 + r4;
    uint32_t qah[8][4], qal[8][4];
    #pragma unroll
    for (int kb = 0; kb < 8; kb++) {
        const uint32_t koff = kb * 32 + k4 * 4;
        qah[kb][0] = *(const uint32_t*)(smem + arow * QROW + koff);
        qah[kb][1] = *(const uint32_t*)(smem + (arow + 8) * QROW + koff);
        qah[kb][2] = *(const uint32_t*)(smem + arow * QROW + koff + 16);
        qah[kb][3] = *(const uint32_t*)(smem + (arow + 8) * QROW + koff + 16);
        qal[kb][0] = *(const uint32_t*)(smem + 17408 + arow * QROW + koff);
        qal[kb][1] = *(const uint32_t*)(smem + 17408 + (arow + 8) * QROW + koff);
        qal[kb][2] = *(const uint32_t*)(smem + 17408 + arow * QROW + koff + 16);
        qal[kb][3] = *(const uint32_t*)(smem + 17408 + (arow + 8) * QROW + koff + 16);
    }
    __syncthreads();   // Q consumed before cp.async overwrites the area

    auto fillK = [&](int s, int kt) {
        const __half* khp = kk + (bh * SS + kt * 64) * DHH;
        const uint32_t kbase = sb + F7_KST(s);
        #pragma unroll
        for (int it = 0; it < 8; it++) {
            int i = it * 128 + tid;       // 1024 x 16B
            int row = i >> 4, c = i & 15;
            cpa16(kbase + row * QROW + c * 16, khp + row * DHH + c * 8);
        }
        CP_COMMIT();
    };
    auto fillV = [&](int kt) {
        const __half* vhp = vt + bh * DHH * SS + kt * 64;
        #pragma unroll
        for (int it = 0; it < 8; it++) {
            int i = it * 128 + tid;       // 1024 x 16B
            int d = i >> 3, c = i & 7;
            cpa16(sb + F7_V + d * VROW + c * 16, vhp + (size_t)d * SS + c * 8);
        }
        CP_COMMIT();
    };

    float oacc[16][4];
    #pragma unroll
    for (int n = 0; n < 16; n++)
        #pragma unroll
        for (int e = 0; e < 4; e++) oacc[n][e] = 0.f;

    float m0 = -1e30f, m1 = -1e30f, l0 = 0.f, l1 = 0.f;
    const float scale = 0.088388347648318447f;
    const int nkt = qb + 1;

    fillK(0, 0);
    fillV(0);

    for (int kt = 0; kt < nkt; kt++) {
        if (kt + 1 < nkt) {
            fillK((kt + 1) & 1, kt + 1);
            CP_WAIT1();
        } else {
            CP_WAIT0();
        }
        __syncthreads();

        const char* kst = smem + F7_KST(kt & 1);

        // ---- S = Q K^T (fp16 2-term) ----
        float sacc[8][4];
        #pragma unroll
        for (int n = 0; n < 8; n++)
            #pragma unroll
            for (int e = 0; e < 4; e++) sacc[n][e] = 0.f;

        #pragma unroll
        for (int kb = 0; kb < 8; kb++) {
            const uint32_t koff = kb * 32 + k4 * 4;
            #pragma unroll
            for (int ng = 0; ng < 8; ng++) {
                const uint32_t bro = (ng * 8 + r4) * QROW + koff;
                uint32_t bh2[2];
                bh2[0] = *(const uint32_t*)(kst + bro);
                bh2[1] = *(const uint32_t*)(kst + bro + 16);
                mma_f16(sacc[ng], qah[kb], bh2);
                mma_f16(sacc[ng], qal[kb], bh2);
            }
        }

        const int row0 = qb * 64 + wid * 16 + r4;
        if (kt == qb) {
            #pragma unroll
            for (int ng = 0; ng < 8; ng++) {
                int colb = kt * 64 + ng * 8 + k4 * 2;
                sacc[ng][0] = (colb     > row0)     ? -1e30f : sacc[ng][0] * scale;
                sacc[ng][1] = (colb + 1 > row0)     ? -1e30f : sacc[ng][1] * scale;
                sacc[ng][2] = (colb     > row0 + 8) ? -1e30f : sacc[ng][2] * scale;
                sacc[ng][3] = (colb + 1 > row0 + 8) ? -1e30f : sacc[ng][3] * scale;
            }
        } else {
            #pragma unroll
            for (int ng = 0; ng < 8; ng++)
                #pragma unroll
                for (int e = 0; e < 4; e++) sacc[ng][e] *= scale;
        }

        float mx0 = -1e30f, mx1 = -1e30f;
        #pragma unroll
        for (int ng = 0; ng < 8; ng++) {
            mx0 = fmaxf(mx0, fmaxf(sacc[ng][0], sacc[ng][1]));
            mx1 = fmaxf(mx1, fmaxf(sacc[ng][2], sacc[ng][3]));
        }
        mx0 = fmaxf(mx0, __shfl_xor_sync(0xffffffffu, mx0, 1));
        mx0 = fmaxf(mx0, __shfl_xor_sync(0xffffffffu, mx0, 2));
        mx1 = fmaxf(mx1, __shfl_xor_sync(0xffffffffu, mx1, 1));
        mx1 = fmaxf(mx1, __shfl_xor_sync(0xffffffffu, mx1, 2));

        float mn0 = fmaxf(m0, mx0), mn1 = fmaxf(m1, mx1);
        float c0 = __expf(m0 - mn0), c1 = __expf(m1 - mn1);
        m0 = mn0; m1 = mn1;

        float sum0 = 0.f, sum1 = 0.f;
        uint32_t ph2[8][2], pl2[8][2];
        #pragma unroll
        for (int ng = 0; ng < 8; ng++) {
            float p0 = __expf(sacc[ng][0] - m0);
            float p1 = __expf(sacc[ng][1] - m0);
            float p2 = __expf(sacc[ng][2] - m1);
            float p3 = __expf(sacc[ng][3] - m1);
            sum0 += p0 + p1; sum1 += p2 + p3;
            __half a, bq, cc, dd2, la, lb, lc, ld;
            split2h(p0, a, la); split2h(p1, bq, lb);
            split2h(p2, cc, lc); split2h(p3, dd2, ld);
            ph2[ng][0] = packh(a, bq);  ph2[ng][1] = packh(cc, dd2);
            pl2[ng][0] = packh(la, lb); pl2[ng][1] = packh(lc, ld);
        }
        sum0 += __shfl_xor_sync(0xffffffffu, sum0, 1);
        sum0 += __shfl_xor_sync(0xffffffffu, sum0, 2);
        sum1 += __shfl_xor_sync(0xffffffffu, sum1, 1);
        sum1 += __shfl_xor_sync(0xffffffffu, sum1, 2);
        l0 = l0 * c0 + sum0;
        l1 = l1 * c1 + sum1;

        #pragma unroll
        for (int n = 0; n < 16; n++) {
            oacc[n][0] *= c0; oacc[n][1] *= c0;
            oacc[n][2] *= c1; oacc[n][3] *= c1;
        }

        // ---- O += P V (fp16 2-term, V single) ----
        #pragma unroll
        for (int kb = 0; kb < 4; kb++) {
            uint32_t pa[4] = {ph2[2*kb][0], ph2[2*kb][1], ph2[2*kb+1][0], ph2[2*kb+1][1]};
            uint32_t pb[4] = {pl2[2*kb][0], pl2[2*kb][1], pl2[2*kb+1][0], pl2[2*kb+1][1]};
            const uint32_t koff = kb * 32 + k4 * 4;
            #pragma unroll
            for (int ng = 0; ng < 16; ng++) {
                const uint32_t vro = (ng * 8 + r4) * VROW + koff;
                uint32_t vh[2];
                vh[0] = *(const uint32_t*)(smem + F7_V + vro);
                vh[1] = *(const uint32_t*)(smem + F7_V + vro + 16);
                mma_f16(oacc[ng], pa, vh);
                mma_f16(oacc[ng], pb, vh);
            }
        }

        __syncthreads();   // all warps done with V buffer + K stage kt&1
        if (kt + 1 < nkt) fillV(kt + 1);   // overlaps next iter's QK+softmax
    }

    // ---- epilogue: normalize, fp16-split, store for out-proj ----
    const float inv0 = 1.0f / l0, inv1 = 1.0f / l1;
    const int grow0 = b * SS + qb * 64 + wid * 16 + r4;
    #pragma unroll
    for (int ng = 0; ng < 16; ng++) {
        size_t o0 = (size_t)grow0 * DD + h * DHH + ng * 8 + k4 * 2;
        size_t o1 = o0 + (size_t)8 * DD;
        float v0 = oacc[ng][0] * inv0, v1 = oacc[ng][1] * inv0;
        float v2 = oacc[ng][2] * inv1, v3 = oacc[ng][3] * inv1;
        __half h0, l0b, h1, l1b, h2, l2b, h3, l3b;
        split2h(v0, h0, l0b); split2h(v1, h1, l1b);
        split2h(v2, h2, l2b); split2h(v3, h3, l3b);
        *(uint32_t*)(attn_hi + o0) = packh(h0, h1);
        *(uint32_t*)(attn_lo + o0) = packh(l0b, l1b);
        *(uint32_t*)(attn_hi + o1) = packh(h2, h3);
        *(uint32_t*)(attn_lo + o1) = packh(l2b, l3b);
    }
}

// ---------------------------------------------------------------------------
// kernel_launch: inputs = [positions, hidden_states, w_qkv, w_out]
// ---------------------------------------------------------------------------
extern "C" void kernel_launch(void* const* d_in, const int* in_sizes, int n_in,
                              void* d_out, int out_size) {
    const float* hidden = (const float*)d_in[1];
    const float* w_qkv  = (const float*)d_in[2];
    const float* w_out  = (const float*)d_in[3];
    float* out = (float*)d_out;

    __half *xh, *xl, *wqT, *woT, *ah, *al, *qhh, *qll, *kk, *vt;
    float* qkv;
    cudaGetSymbolAddress((void**)&xh,  g_xh);
    cudaGetSymbolAddress((void**)&xl,  g_xl);
    cudaGetSymbolAddress((void**)&qkv, g_qkv);
    cudaGetSymbolAddress((void**)&wqT, g_wqkvT);
    cudaGetSymbolAddress((void**)&woT, g_woutT);
    cudaGetSymbolAddress((void**)&ah,  g_ah);
    cudaGetSymbolAddress((void**)&al,  g_al);
    cudaGetSymbolAddress((void**)&qhh, g_qhh);
    cudaGetSymbolAddress((void**)&qll, g_qll);
    cudaGetSymbolAddress((void**)&kk,  g_kk);
    cudaGetSymbolAddress((void**)&vt,  g_vt);

    // 1) LayerNorm -> fp16 hi/lo
    ln_kernel<<<NTOK, 256>>>(hidden, xh, xl);

    // 2) Weight transpose -> fp16
    dim3 tb(32, 8);
    transpose_h<<<dim3(QKV_N / 32, DD / 32), tb>>>(w_qkv, wqT, DD, QKV_N);
    transpose_h<<<dim3(DD / 32, DD / 32), tb>>>(w_out, woT, DD, DD);

    // 3) QKV projection: fp16 2-term GEMM
    cudaFuncSetAttribute(gemm_f16, cudaFuncAttributeMaxDynamicSharedMemorySize, GEMM_SMEM);
    gemm_f16<<<dim3(QKV_N / BN, NTOK / BM), 256, GEMM_SMEM>>>(
        xh, xl, wqT, qkv, NTOK, QKV_N, DD);

    // 4) RoPE + split Q (hi/lo) / K (single); V transpose (single)
    rope_split<<<NTOK, 256>>>(qkv, qhh, qll, kk);
    v_transpose_h<<<dim3(SS / 64, HH, BB), 256>>>(qkv, vt);

    // 5) Causal flash attention v7 (fp16 2-term)
    cudaFuncSetAttribute(flash7_kernel, cudaFuncAttributeMaxDynamicSharedMemorySize,
                         FLASH7_SMEM);
    flash7_kernel<<<dim3(SS / 64, HH, BB), 128, FLASH7_SMEM>>>(
        qhh, qll, kk, vt, ah, al);

    // 6) Output projection: fp16 2-term GEMM
    gemm_f16<<<dim3(DD / BN, NTOK / BM), 256, GEMM_SMEM>>>(
        ah, al, woT, out, NTOK, DD, DD);
}

// round 13
// speedup vs baseline: 2.1155x; 1.3669x over previous
#include <cuda_runtime.h>
#include <cuda_bf16.h>
#include <cuda_fp16.h>
#include <math.h>
#include <cstdint>

// ---------------------------------------------------------------------------
// Problem constants: B=2, S=2048, D=2048, H=16, DH=128
// ---------------------------------------------------------------------------
#define BB 2
#define SS 2048
#define DD 2048
#define HH 16
#define DHH 128
#define NTOK (BB * SS)          // 4096
#define QKV_N (3 * DD)          // 6144
#define LN_EPS 1e-5f

// ---------------------------------------------------------------------------
// Scratch (device globals; allocation forbidden)
// ---------------------------------------------------------------------------
__device__ __half g_x16[(size_t)NTOK * DD];         // LN out (fp16)
__device__ float  g_qkv[(size_t)NTOK * QKV_N];      // 100.7 MB
__device__ __half g_wqkvT[(size_t)QKV_N * DD];      // W_qkv^T (fp16)
__device__ __half g_woutT[(size_t)DD * DD];         // W_out^T (fp16)
__device__ __half g_attn[(size_t)NTOK * DD];        // attn out (fp16)
// pre-split attention operands (fp16 2-term scheme, proven)
__device__ __half g_qhh[(size_t)NTOK * DD];   // Q hi [b][h][s][d]
__device__ __half g_qll[(size_t)NTOK * DD];   // Q lo
__device__ __half g_kk[(size_t)NTOK * DD];    // K single fp16
__device__ __half g_vt[(size_t)NTOK * DD];    // V^T single fp16 [b][h][d][s]

// ---------------------------------------------------------------------------
// helpers
// ---------------------------------------------------------------------------
__device__ __forceinline__ uint32_t smem_u32(const void* p) {
    uint32_t a;
    asm("{ .reg .u64 t; cvta.to.shared.u64 t, %1; cvt.u32.u64 %0, t; }"
        : "=r"(a) : "l"(p));
    return a;
}

__device__ __forceinline__ void cpa16(uint32_t dst, const void* src) {
    asm volatile("cp.async.cg.shared.global [%0], [%1], 16;" :: "r"(dst), "l"(src) : "memory");
}
#define CP_COMMIT() asm volatile("cp.async.commit_group;" ::: "memory")
#define CP_WAIT1()  asm volatile("cp.async.wait_group 1;" ::: "memory")
#define CP_WAIT0()  asm volatile("cp.async.wait_group 0;" ::: "memory")

__device__ __forceinline__ void mma_f16(float* c, const uint32_t* a, const uint32_t* b) {
    asm volatile(
        "mma.sync.aligned.m16n8k16.row.col.f32.f16.f16.f32 "
        "{%0,%1,%2,%3}, {%4,%5,%6,%7}, {%8,%9}, {%0,%1,%2,%3};"
        : "+f"(c[0]), "+f"(c[1]), "+f"(c[2]), "+f"(c[3])
        : "r"(a[0]), "r"(a[1]), "r"(a[2]), "r"(a[3]), "r"(b[0]), "r"(b[1]));
}

__device__ __forceinline__ void ldm_x4(uint32_t* r, uint32_t addr) {
    asm volatile("ldmatrix.sync.aligned.m8n8.x4.shared.b16 {%0,%1,%2,%3}, [%4];"
        : "=r"(r[0]), "=r"(r[1]), "=r"(r[2]), "=r"(r[3]) : "r"(addr));
}

__device__ __forceinline__ void split2h(float v, __half& h, __half& l) {
    h = __float2half_rn(v);
    l = __float2half_rn(v - __half2float(h));
}

__device__ __forceinline__ uint32_t packh(__half a, __half b) {
    __half2 t(a, b);          // a = low element
    return *(uint32_t*)&t;
}

// ---------------------------------------------------------------------------
// LayerNorm -> fp16 output (A operand of QKV GEMM, single term)
// ---------------------------------------------------------------------------
__global__ __launch_bounds__(256) void ln_kernel(const float* __restrict__ x,
                                                 __half* __restrict__ y) {
    __shared__ float red_s[8], red_ss[8];
    __shared__ float sh_mu, sh_rstd;
    const int row = blockIdx.x;
    const int tid = threadIdx.x;
    const float* xr = x + (size_t)row * DD;

    float4 a = *(const float4*)(xr + tid * 4);
    float4 b = *(const float4*)(xr + 1024 + tid * 4);
    float s  = a.x + a.y + a.z + a.w + b.x + b.y + b.z + b.w;
    float ss = a.x*a.x + a.y*a.y + a.z*a.z + a.w*a.w
             + b.x*b.x + b.y*b.y + b.z*b.z + b.w*b.w;
    #pragma unroll
    for (int o = 16; o > 0; o >>= 1) {
        s  += __shfl_xor_sync(0xffffffffu, s, o);
        ss += __shfl_xor_sync(0xffffffffu, ss, o);
    }
    const int wid = tid >> 5, lane = tid & 31;
    if (lane == 0) { red_s[wid] = s; red_ss[wid] = ss; }
    __syncthreads();
    if (tid == 0) {
        float S = 0.f, SSq = 0.f;
        #pragma unroll
        for (int w = 0; w < 8; w++) { S += red_s[w]; SSq += red_ss[w]; }
        float mu = S * (1.0f / DD);
        float var = SSq * (1.0f / DD) - mu * mu;
        sh_mu = mu;
        sh_rstd = rsqrtf(var + LN_EPS);
    }
    __syncthreads();
    const float mu = sh_mu, rstd = sh_rstd;
    float va[8] = {a.x, a.y, a.z, a.w, b.x, b.y, b.z, b.w};
    #pragma unroll
    for (int e = 0; e < 8; e++) {
        float v = (va[e] - mu) * rstd;
        size_t col = (e < 4) ? (tid * 4 + e) : (1024 + tid * 4 + e - 4);
        y[(size_t)row * DD + col] = __float2half_rn(v);
    }
}

// ---------------------------------------------------------------------------
// Transpose + round: W[K][N] fp32 -> fp16 [N][K]
// ---------------------------------------------------------------------------
__global__ __launch_bounds__(256) void transpose_h(const float* __restrict__ W,
                                                   __half* __restrict__ out,
                                                   int K, int N) {
    __shared__ float t[32][33];
    int n = blockIdx.x * 32 + threadIdx.x;
    int k = blockIdx.y * 32 + threadIdx.y;
    #pragma unroll
    for (int i = 0; i < 4; i++)
        t[threadIdx.y + 8 * i][threadIdx.x] = W[(size_t)(k + 8 * i) * N + n];
    __syncthreads();
    int ko = blockIdx.y * 32 + threadIdx.x;
    int no = blockIdx.x * 32 + threadIdx.y;
    #pragma unroll
    for (int i = 0; i < 4; i++) {
        float v = t[threadIdx.x][threadIdx.y + 8 * i];
        out[(size_t)(no + 8 * i) * K + ko] = __float2half_rn(v);
    }
}

// ---------------------------------------------------------------------------
// fp16 1-term GEMM: C[M,N] fp32 = A[M,K] @ B[N,K]^T
// CTA 128x256, BK=32, 8 warps 64x64, ldmatrix, 3-stage cp.async ring.
// Same structure as the proven 2-term kernel, single A operand.
// ---------------------------------------------------------------------------
#define BM 128
#define BN 256
#define BKC 32
#define ROWB 80
#define A_TILE (128 * ROWB)              // 10240
#define B_TILE (256 * ROWB)              // 20480
#define STAGE_B (A_TILE + B_TILE)        // 30720
#define NSTAGE 3
#define GEMM_SMEM (NSTAGE * STAGE_B)     // 92160

__global__ __launch_bounds__(256, 1) void gemm_f16(
    const __half* __restrict__ Am, const __half* __restrict__ Bm,
    float* __restrict__ C, int M, int N, int K)
{
    extern __shared__ __align__(16) char smem[];
    const uint32_t sb = smem_u32(smem);
    const int tid = threadIdx.x;
    const int wid = tid >> 5;
    const int lane = tid & 31;
    const int m0 = blockIdx.y * BM;
    const int n0 = blockIdx.x * BN;
    const int wm = (wid & 1) * 64;
    const int wn = (wid >> 1) * 64;

    float acc[4][8][4];
    #pragma unroll
    for (int mi = 0; mi < 4; mi++)
        #pragma unroll
        for (int ni = 0; ni < 8; ni++)
            #pragma unroll
            for (int e = 0; e < 4; e++) acc[mi][ni][e] = 0.f;

    // stage fill: 1536 x 16B chunks (A 128 rows x4, B 256 rows x4)
    auto fill = [&](int stage, int k0) {
        const uint32_t sbase = sb + stage * STAGE_B;
        #pragma unroll
        for (int it = 0; it < 6; it++) {
            int i = it * 256 + tid;
            const __half* src;
            uint32_t dst;
            if (i < 512) {
                int r = i >> 2, c = i & 3;
                src = Am + (size_t)(m0 + r) * K + k0 + c * 8;
                dst = sbase + r * ROWB + c * 16;
            } else {
                int j = i - 512;
                int r = j >> 2, c = j & 3;
                src = Bm + (size_t)(n0 + r) * K + k0 + c * 8;
                dst = sbase + A_TILE + r * ROWB + c * 16;
            }
            cpa16(dst, src);
        }
        CP_COMMIT();
    };

    const int nch = K / BKC;
    fill(0, 0);
    fill(1, BKC);

    const int lg = lane >> 3;
    const int lr = lane & 7;

    for (int c = 0; c < nch; c++) {
        if (c + 1 < nch) CP_WAIT1(); else CP_WAIT0();
        __syncthreads();

        if (c + 2 < nch) fill((c + 2) % NSTAGE, (c + 2) * BKC);

        const uint32_t sbase = sb + (c % NSTAGE) * STAGE_B;
        const uint32_t aT = sbase;
        const uint32_t bT = sbase + A_TILE;

        #pragma unroll
        for (int ks = 0; ks < 2; ks++) {
            const uint32_t koff = ks * 32;

            const uint32_t aoff = (lg & 1) * 8 * ROWB + (lg >> 1) * 16 + lr * ROWB + koff;
            uint32_t ah[4][4];
            #pragma unroll
            for (int mi = 0; mi < 4; mi++) {
                uint32_t ro = (wm + mi * 16) * ROWB + aoff;
                ldm_x4(ah[mi], aT + ro);
            }
            const uint32_t boff = (lg >> 1) * 8 * ROWB + (lg & 1) * 16 + lr * ROWB + koff;
            uint32_t bh[8][2];
            #pragma unroll
            for (int np = 0; np < 4; np++) {
                uint32_t ro = (wn + np * 16) * ROWB + boff;
                uint32_t t4[4];
                ldm_x4(t4, bT + ro);
                bh[2 * np][0] = t4[0]; bh[2 * np][1] = t4[1];
                bh[2 * np + 1][0] = t4[2]; bh[2 * np + 1][1] = t4[3];
            }

            #pragma unroll
            for (int mi = 0; mi < 4; mi++)
                #pragma unroll
                for (int ni = 0; ni < 8; ni++)
                    mma_f16(acc[mi][ni], ah[mi], bh[ni]);
        }
    }

    const int r4 = lane >> 2;
    const int k4 = lane & 3;
    #pragma unroll
    for (int mi = 0; mi < 4; mi++) {
        int r0 = m0 + wm + mi * 16 + r4;
        #pragma unroll
        for (int ni = 0; ni < 8; ni++) {
            int cc = n0 + wn + ni * 8 + k4 * 2;
            float2 v0 = {acc[mi][ni][0], acc[mi][ni][1]};
            float2 v1 = {acc[mi][ni][2], acc[mi][ni][3]};
            *(float2*)(C + (size_t)r0 * N + cc) = v0;
            *(float2*)(C + (size_t)(r0 + 8) * N + cc) = v1;
        }
    }
}

// ---------------------------------------------------------------------------
// RoPE + split: fp32 qkv -> Q fp16 hi/lo, K fp16 single, [b][h][s][d]
// ---------------------------------------------------------------------------
__global__ __launch_bounds__(256) void rope_split(const float* __restrict__ qkv,
                                                  __half* __restrict__ qh,
                                                  __half* __restrict__ ql,
                                                  __half* __restrict__ kk) {
    const int t = blockIdx.x;            // token
    const int b = t / SS, s = t % SS;
    const int tid = threadIdx.x;

    #pragma unroll
    for (int w = 0; w < 4; w++) {
        int idx = w * 256 + tid;          // (h, dpair)
        int h = idx >> 6, dp = idx & 63;

        float inv_freq = powf(10000.0f, -(float)dp * (1.0f / 64.0f));
        float ang = (float)s * inv_freq;
        float c = cosf(ang), sn = sinf(ang);

        const float* src = qkv + (size_t)t * QKV_N + h * DHH;
        size_t obase = ((size_t)(b * HH + h) * SS + s) * DHH;
        __half hh, ll;

        // q (split hi/lo)
        float x1 = src[dp], x2 = src[dp + 64];
        float r1 = x1 * c - x2 * sn;
        float r2 = x2 * c + x1 * sn;
        split2h(r1, hh, ll); qh[obase + dp] = hh;      ql[obase + dp] = ll;
        split2h(r2, hh, ll); qh[obase + dp + 64] = hh; ql[obase + dp + 64] = ll;

        // k (single fp16)
        x1 = src[DD + dp]; x2 = src[DD + dp + 64];
        r1 = x1 * c - x2 * sn;
        r2 = x2 * c + x1 * sn;
        kk[obase + dp]      = __float2half_rn(r1);
        kk[obase + dp + 64] = __float2half_rn(r2);
    }
}

// ---------------------------------------------------------------------------
// V transpose: fp32 qkv v-slice -> [b][h][d][s] fp16 single
// ---------------------------------------------------------------------------
__global__ __launch_bounds__(256) void v_transpose_h(const float* __restrict__ qkv,
                                                     __half* __restrict__ vt) {
    __shared__ float sm[64 * 132];
    const int s0 = blockIdx.x * 64;
    const int h  = blockIdx.y;
    const int b  = blockIdx.z;
    const int tid = threadIdx.x;

    #pragma unroll
    for (int i = 0; i < 32; i++) {
        int idx = i * 256 + tid;
        int sl = idx >> 7, d = idx & 127;
        sm[sl * 132 + d] = qkv[((size_t)(b * SS + s0 + sl)) * QKV_N + 2 * DD + h * DHH + d];
    }
    __syncthreads();

    const int d = tid >> 1;
    const int sh = (tid & 1) * 32;
    size_t row = ((size_t)(b * HH + h) * DHH + d) * SS + s0 + sh;
    #pragma unroll
    for (int j = 0; j < 32; j += 2) {
        float v0 = sm[(sh + j) * 132 + d];
        float v1 = sm[(sh + j + 1) * 132 + d];
        *(uint32_t*)(vt + row + j) = packh(__float2half_rn(v0), __float2half_rn(v1));
    }
}

// ---------------------------------------------------------------------------
// Flash attention v7 (proven fp16 2-term core); epilogue -> single fp16.
// ---------------------------------------------------------------------------
#define QROW 272
#define VROW 144
#define F7_KST(s) ((s) * 17408)            // K stage s (single fp16)
#define F7_V (2 * 17408)                   // 34816
#define FLASH7_SMEM (F7_V + 128 * VROW)    // 53248 bytes

__global__ __launch_bounds__(128) void flash7_kernel(
    const __half* __restrict__ qh, const __half* __restrict__ ql,
    const __half* __restrict__ kk, const __half* __restrict__ vt,
    __half* __restrict__ attn)
{
    extern __shared__ __align__(16) char smem[];
    const uint32_t sb = smem_u32(smem);

    const int qb = blockIdx.x;
    const int h  = blockIdx.y;
    const int b  = blockIdx.z;
    const int tid = threadIdx.x;
    const int wid = tid >> 5;
    const int lane = tid & 31;
    const int r4 = lane >> 2;
    const int k4 = lane & 3;

    const size_t bh = (size_t)(b * HH + h);
    const __half* qhp = qh + (bh * SS + qb * 64) * DHH;
    const __half* qlp = ql + (bh * SS + qb * 64) * DHH;

    // ---- prologue: stage Q hi/lo into K-stage area, read frags to regs ----
    for (int i = tid; i < 2048; i += 128) {
        int op = i >> 10, j = i & 1023;
        int row = j >> 4, c = j & 15;
        const __half* src = (op ? qlp : qhp) + row * DHH + c * 8;
        uint4 v = *(const uint4*)src;
        *(uint4*)(smem + op * 17408 + row * QROW + c * 16) = v;
    }
    __syncthreads();

    const int arow = wid * 16 + r4;
    uint32_t qah[8][4], qal[8][4];
    #pragma unroll
    for (int kb = 0; kb < 8; kb++) {
        const uint32_t koff = kb * 32 + k4 * 4;
        qah[kb][0] = *(const uint32_t*)(smem + arow * QROW + koff);
        qah[kb][1] = *(const uint32_t*)(smem + (arow + 8) * QROW + koff);
        qah[kb][2] = *(const uint32_t*)(smem + arow * QROW + koff + 16);
        qah[kb][3] = *(const uint32_t*)(smem + (arow + 8) * QROW + koff + 16);
        qal[kb][0] = *(const uint32_t*)(smem + 17408 + arow * QROW + koff);
        qal[kb][1] = *(const uint32_t*)(smem + 17408 + (arow + 8) * QROW + koff);
        qal[kb][2] = *(const uint32_t*)(smem + 17408 + arow * QROW + koff + 16);
        qal[kb][3] = *(const uint32_t*)(smem + 17408 + (arow + 8) * QROW + koff + 16);
    }
    __syncthreads();   // Q consumed before cp.async overwrites the area

    auto fillK = [&](int s, int kt) {
        const __half* khp = kk + (bh * SS + kt * 64) * DHH;
        const uint32_t kbase = sb + F7_KST(s);
        #pragma unroll
        for (int it = 0; it < 8; it++) {
            int i = it * 128 + tid;
            int row = i >> 4, c = i & 15;
            cpa16(kbase + row * QROW + c * 16, khp + row * DHH + c * 8);
        }
        CP_COMMIT();
    };
    auto fillV = [&](int kt) {
        const __half* vhp = vt + bh * DHH * SS + kt * 64;
        #pragma unroll
        for (int it = 0; it < 8; it++) {
            int i = it * 128 + tid;
            int d = i >> 3, c = i & 7;
            cpa16(sb + F7_V + d * VROW + c * 16, vhp + (size_t)d * SS + c * 8);
        }
        CP_COMMIT();
    };

    float oacc[16][4];
    #pragma unroll
    for (int n = 0; n < 16; n++)
        #pragma unroll
        for (int e = 0; e < 4; e++) oacc[n][e] = 0.f;

    float m0 = -1e30f, m1 = -1e30f, l0 = 0.f, l1 = 0.f;
    const float scale = 0.088388347648318447f;
    const int nkt = qb + 1;

    fillK(0, 0);
    fillV(0);

    for (int kt = 0; kt < nkt; kt++) {
        if (kt + 1 < nkt) {
            fillK((kt + 1) & 1, kt + 1);
            CP_WAIT1();
        } else {
            CP_WAIT0();
        }
        __syncthreads();

        const char* kst = smem + F7_KST(kt & 1);

        float sacc[8][4];
        #pragma unroll
        for (int n = 0; n < 8; n++)
            #pragma unroll
            for (int e = 0; e < 4; e++) sacc[n][e] = 0.f;

        #pragma unroll
        for (int kb = 0; kb < 8; kb++) {
            const uint32_t koff = kb * 32 + k4 * 4;
            #pragma unroll
            for (int ng = 0; ng < 8; ng++) {
                const uint32_t bro = (ng * 8 + r4) * QROW + koff;
                uint32_t bh2[2];
                bh2[0] = *(const uint32_t*)(kst + bro);
                bh2[1] = *(const uint32_t*)(kst + bro + 16);
                mma_f16(sacc[ng], qah[kb], bh2);
                mma_f16(sacc[ng], qal[kb], bh2);
            }
        }

        const int row0 = qb * 64 + wid * 16 + r4;
        if (kt == qb) {
            #pragma unroll
            for (int ng = 0; ng < 8; ng++) {
                int colb = kt * 64 + ng * 8 + k4 * 2;
                sacc[ng][0] = (colb     > row0)     ? -1e30f : sacc[ng][0] * scale;
                sacc[ng][1] = (colb + 1 > row0)     ? -1e30f : sacc[ng][1] * scale;
                sacc[ng][2] = (colb     > row0 + 8) ? -1e30f : sacc[ng][2] * scale;
                sacc[ng][3] = (colb + 1 > row0 + 8) ? -1e30f : sacc[ng][3] * scale;
            }
        } else {
            #pragma unroll
            for (int ng = 0; ng < 8; ng++)
                #pragma unroll
                for (int e = 0; e < 4; e++) sacc[ng][e] *= scale;
        }

        float mx0 = -1e30f, mx1 = -1e30f;
        #pragma unroll
        for (int ng = 0; ng < 8; ng++) {
            mx0 = fmaxf(mx0, fmaxf(sacc[ng][0], sacc[ng][1]));
            mx1 = fmaxf(mx1, fmaxf(sacc[ng][2], sacc[ng][3]));
        }
        mx0 = fmaxf(mx0, __shfl_xor_sync(0xffffffffu, mx0, 1));
        mx0 = fmaxf(mx0, __shfl_xor_sync(0xffffffffu, mx0, 2));
        mx1 = fmaxf(mx1, __shfl_xor_sync(0xffffffffu, mx1, 1));
        mx1 = fmaxf(mx1, __shfl_xor_sync(0xffffffffu, mx1, 2));

        float mn0 = fmaxf(m0, mx0), mn1 = fmaxf(m1, mx1);
        float c0 = __expf(m0 - mn0), c1 = __expf(m1 - mn1);
        m0 = mn0; m1 = mn1;

        float sum0 = 0.f, sum1 = 0.f;
        uint32_t ph2[8][2], pl2[8][2];
        #pragma unroll
        for (int ng = 0; ng < 8; ng++) {
            float p0 = __expf(sacc[ng][0] - m0);
            float p1 = __expf(sacc[ng][1] - m0);
            float p2 = __expf(sacc[ng][2] - m1);
            float p3 = __expf(sacc[ng][3] - m1);
            sum0 += p0 + p1; sum1 += p2 + p3;
            __half a, bq, cc, dd2, la, lb, lc, ld;
            split2h(p0, a, la); split2h(p1, bq, lb);
            split2h(p2, cc, lc); split2h(p3, dd2, ld);
            ph2[ng][0] = packh(a, bq);  ph2[ng][1] = packh(cc, dd2);
            pl2[ng][0] = packh(la, lb); pl2[ng][1] = packh(lc, ld);
        }
        sum0 += __shfl_xor_sync(0xffffffffu, sum0, 1);
        sum0 += __shfl_xor_sync(0xffffffffu, sum0, 2);
        sum1 += __shfl_xor_sync(0xffffffffu, sum1, 1);
        sum1 += __shfl_xor_sync(0xffffffffu, sum1, 2);
        l0 = l0 * c0 + sum0;
        l1 = l1 * c1 + sum1;

        #pragma unroll
        for (int n = 0; n < 16; n++) {
            oacc[n][0] *= c0; oacc[n][1] *= c0;
            oacc[n][2] *= c1; oacc[n][3] *= c1;
        }

        #pragma unroll
        for (int kb = 0; kb < 4; kb++) {
            uint32_t pa[4] = {ph2[2*kb][0], ph2[2*kb][1], ph2[2*kb+1][0], ph2[2*kb+1][1]};
            uint32_t pb[4] = {pl2[2*kb][0], pl2[2*kb][1], pl2[2*kb+1][0], pl2[2*kb+1][1]};
            const uint32_t koff = kb * 32 + k4 * 4;
            #pragma unroll
            for (int ng = 0; ng < 16; ng++) {
                const uint32_t vro = (ng * 8 + r4) * VROW + koff;
                uint32_t vh[2];
                vh[0] = *(const uint32_t*)(smem + F7_V + vro);
                vh[1] = *(const uint32_t*)(smem + F7_V + vro + 16);
                mma_f16(oacc[ng], pa, vh);
                mma_f16(oacc[ng], pb, vh);
            }
        }

        __syncthreads();
        if (kt + 1 < nkt) fillV(kt + 1);
    }

    // ---- epilogue: normalize, round to fp16 (single), store ----
    const float inv0 = 1.0f / l0, inv1 = 1.0f / l1;
    const int grow0 = b * SS + qb * 64 + wid * 16 + r4;
    #pragma unroll
    for (int ng = 0; ng < 16; ng++) {
        size_t o0 = (size_t)grow0 * DD + h * DHH + ng * 8 + k4 * 2;
        size_t o1 = o0 + (size_t)8 * DD;
        float v0 = oacc[ng][0] * inv0, v1 = oacc[ng][1] * inv0;
        float v2 = oacc[ng][2] * inv1, v3 = oacc[ng][3] * inv1;
        *(uint32_t*)(attn + o0) = packh(__float2half_rn(v0), __float2half_rn(v1));
        *(uint32_t*)(attn + o1) = packh(__float2half_rn(v2), __float2half_rn(v3));
    }
}

// ---------------------------------------------------------------------------
// kernel_launch: inputs = [positions, hidden_states, w_qkv, w_out]
// ---------------------------------------------------------------------------
extern "C" void kernel_launch(void* const* d_in, const int* in_sizes, int n_in,
                              void* d_out, int out_size) {
    const float* hidden = (const float*)d_in[1];
    const float* w_qkv  = (const float*)d_in[2];
    const float* w_out  = (const float*)d_in[3];
    float* out = (float*)d_out;

    __half *x16, *wqT, *woT, *attn, *qhh, *qll, *kk, *vt;
    float* qkv;
    cudaGetSymbolAddress((void**)&x16, g_x16);
    cudaGetSymbolAddress((void**)&qkv, g_qkv);
    cudaGetSymbolAddress((void**)&wqT, g_wqkvT);
    cudaGetSymbolAddress((void**)&woT, g_woutT);
    cudaGetSymbolAddress((void**)&attn, g_attn);
    cudaGetSymbolAddress((void**)&qhh, g_qhh);
    cudaGetSymbolAddress((void**)&qll, g_qll);
    cudaGetSymbolAddress((void**)&kk,  g_kk);
    cudaGetSymbolAddress((void**)&vt,  g_vt);

    // 1) LayerNorm -> fp16
    ln_kernel<<<NTOK, 256>>>(hidden, x16);

    // 2) Weight transpose -> fp16
    dim3 tb(32, 8);
    transpose_h<<<dim3(QKV_N / 32, DD / 32), tb>>>(w_qkv, wqT, DD, QKV_N);
    transpose_h<<<dim3(DD / 32, DD / 32), tb>>>(w_out, woT, DD, DD);

    // 3) QKV projection: fp16 1-term GEMM
    cudaFuncSetAttribute(gemm_f16, cudaFuncAttributeMaxDynamicSharedMemorySize, GEMM_SMEM);
    gemm_f16<<<dim3(QKV_N / BN, NTOK / BM), 256, GEMM_SMEM>>>(
        x16, wqT, qkv, NTOK, QKV_N, DD);

    // 4) RoPE + split Q (hi/lo) / K (single); V transpose (single)
    rope_split<<<NTOK, 256>>>(qkv, qhh, qll, kk);
    v_transpose_h<<<dim3(SS / 64, HH, BB), 256>>>(qkv, vt);

    // 5) Causal flash attention v7 (fp16 2-term core, single-fp16 output)
    cudaFuncSetAttribute(flash7_kernel, cudaFuncAttributeMaxDynamicSharedMemorySize,
                         FLASH7_SMEM);
    flash7_kernel<<<dim3(SS / 64, HH, BB), 128, FLASH7_SMEM>>>(
        qhh, qll, kk, vt, attn);

    // 6) Output projection: fp16 1-term GEMM
    gemm_f16<<<dim3(DD / BN, NTOK / BM), 256, GEMM_SMEM>>>(
        attn, woT, out, NTOK, DD, DD);
}

// round 14
// speedup vs baseline: 2.3827x; 1.1263x over previous
#include <cuda_runtime.h>
#include <cuda_bf16.h>
#include <cuda_fp16.h>
#include <math.h>
#include <cstdint>

// ---------------------------------------------------------------------------
// Problem constants: B=2, S=2048, D=2048, H=16, DH=128
// ---------------------------------------------------------------------------
#define BB 2
#define SS 2048
#define DD 2048
#define HH 16
#define DHH 128
#define NTOK (BB * SS)          // 4096
#define QKV_N (3 * DD)          // 6144
#define LN_EPS 1e-5f

// ---------------------------------------------------------------------------
// Scratch (device globals; allocation forbidden)
// ---------------------------------------------------------------------------
__device__ __half g_x16[(size_t)NTOK * DD];         // LN out (fp16)
__device__ float  g_qkv[(size_t)NTOK * QKV_N];      // 100.7 MB
__device__ __half g_wqkvT[(size_t)QKV_N * DD];      // W_qkv^T (fp16)
__device__ __half g_woutT[(size_t)DD * DD];         // W_out^T (fp16)
__device__ __half g_attn[(size_t)NTOK * DD];        // attn out (fp16)
// pre-split attention operands (fp16 2-term scheme, proven)
__device__ __half g_qhh[(size_t)NTOK * DD];   // Q hi [b][h][s][d]
__device__ __half g_qll[(size_t)NTOK * DD];   // Q lo
__device__ __half g_kk[(size_t)NTOK * DD];    // K single fp16
__device__ __half g_vt[(size_t)NTOK * DD];    // V^T single fp16 [b][h][d][s]

// ---------------------------------------------------------------------------
// helpers
// ---------------------------------------------------------------------------
__device__ __forceinline__ uint32_t smem_u32(const void* p) {
    uint32_t a;
    asm("{ .reg .u64 t; cvta.to.shared.u64 t, %1; cvt.u32.u64 %0, t; }"
        : "=r"(a) : "l"(p));
    return a;
}

__device__ __forceinline__ void cpa16(uint32_t dst, const void* src) {
    asm volatile("cp.async.cg.shared.global [%0], [%1], 16;" :: "r"(dst), "l"(src) : "memory");
}
#define CP_COMMIT() asm volatile("cp.async.commit_group;" ::: "memory")
#define CP_WAIT1()  asm volatile("cp.async.wait_group 1;" ::: "memory")
#define CP_WAIT0()  asm volatile("cp.async.wait_group 0;" ::: "memory")

__device__ __forceinline__ void mma_f16(float* c, const uint32_t* a, const uint32_t* b) {
    asm volatile(
        "mma.sync.aligned.m16n8k16.row.col.f32.f16.f16.f32 "
        "{%0,%1,%2,%3}, {%4,%5,%6,%7}, {%8,%9}, {%0,%1,%2,%3};"
        : "+f"(c[0]), "+f"(c[1]), "+f"(c[2]), "+f"(c[3])
        : "r"(a[0]), "r"(a[1]), "r"(a[2]), "r"(a[3]), "r"(b[0]), "r"(b[1]));
}

__device__ __forceinline__ void ldm_x4(uint32_t* r, uint32_t addr) {
    asm volatile("ldmatrix.sync.aligned.m8n8.x4.shared.b16 {%0,%1,%2,%3}, [%4];"
        : "=r"(r[0]), "=r"(r[1]), "=r"(r[2]), "=r"(r[3]) : "r"(addr));
}

__device__ __forceinline__ void split2h(float v, __half& h, __half& l) {
    h = __float2half_rn(v);
    l = __float2half_rn(v - __half2float(h));
}

__device__ __forceinline__ uint32_t packh(__half a, __half b) {
    __half2 t(a, b);          // a = low element
    return *(uint32_t*)&t;
}

// ---------------------------------------------------------------------------
// LayerNorm -> fp16 output
// ---------------------------------------------------------------------------
__global__ __launch_bounds__(256) void ln_kernel(const float* __restrict__ x,
                                                 __half* __restrict__ y) {
    __shared__ float red_s[8], red_ss[8];
    __shared__ float sh_mu, sh_rstd;
    const int row = blockIdx.x;
    const int tid = threadIdx.x;
    const float* xr = x + (size_t)row * DD;

    float4 a = *(const float4*)(xr + tid * 4);
    float4 b = *(const float4*)(xr + 1024 + tid * 4);
    float s  = a.x + a.y + a.z + a.w + b.x + b.y + b.z + b.w;
    float ss = a.x*a.x + a.y*a.y + a.z*a.z + a.w*a.w
             + b.x*b.x + b.y*b.y + b.z*b.z + b.w*b.w;
    #pragma unroll
    for (int o = 16; o > 0; o >>= 1) {
        s  += __shfl_xor_sync(0xffffffffu, s, o);
        ss += __shfl_xor_sync(0xffffffffu, ss, o);
    }
    const int wid = tid >> 5, lane = tid & 31;
    if (lane == 0) { red_s[wid] = s; red_ss[wid] = ss; }
    __syncthreads();
    if (tid == 0) {
        float S = 0.f, SSq = 0.f;
        #pragma unroll
        for (int w = 0; w < 8; w++) { S += red_s[w]; SSq += red_ss[w]; }
        float mu = S * (1.0f / DD);
        float var = SSq * (1.0f / DD) - mu * mu;
        sh_mu = mu;
        sh_rstd = rsqrtf(var + LN_EPS);
    }
    __syncthreads();
    const float mu = sh_mu, rstd = sh_rstd;
    float va[8] = {a.x, a.y, a.z, a.w, b.x, b.y, b.z, b.w};
    #pragma unroll
    for (int e = 0; e < 8; e++) {
        float v = (va[e] - mu) * rstd;
        size_t col = (e < 4) ? (tid * 4 + e) : (1024 + tid * 4 + e - 4);
        y[(size_t)row * DD + col] = __float2half_rn(v);
    }
}

// ---------------------------------------------------------------------------
// Transpose + round: W[K][N] fp32 -> fp16 [N][K]
// ---------------------------------------------------------------------------
__global__ __launch_bounds__(256) void transpose_h(const float* __restrict__ W,
                                                   __half* __restrict__ out,
                                                   int K, int N) {
    __shared__ float t[32][33];
    int n = blockIdx.x * 32 + threadIdx.x;
    int k = blockIdx.y * 32 + threadIdx.y;
    #pragma unroll
    for (int i = 0; i < 4; i++)
        t[threadIdx.y + 8 * i][threadIdx.x] = W[(size_t)(k + 8 * i) * N + n];
    __syncthreads();
    int ko = blockIdx.y * 32 + threadIdx.x;
    int no = blockIdx.x * 32 + threadIdx.y;
    #pragma unroll
    for (int i = 0; i < 4; i++) {
        float v = t[threadIdx.x][threadIdx.y + 8 * i];
        out[(size_t)(no + 8 * i) * K + ko] = __float2half_rn(v);
    }
}

// ---------------------------------------------------------------------------
// fp16 1-term GEMM v2: CTA 128x128, 8 warps (4m x 2n), warp tile 32x64.
// 3-stage cp.async ring. 2 CTAs/SM (regs capped at 128 via launch bounds).
// ---------------------------------------------------------------------------
#define BM 128
#define BN 128
#define BKC 32
#define ROWB 80
#define A_TILE (128 * ROWB)              // 10240
#define B_TILE (128 * ROWB)              // 10240
#define STAGE_B (A_TILE + B_TILE)        // 20480
#define NSTAGE 3
#define GEMM_SMEM (NSTAGE * STAGE_B)     // 61440 -> 2+ CTAs/SM

__global__ __launch_bounds__(256, 2) void gemm_f16(
    const __half* __restrict__ Am, const __half* __restrict__ Bm,
    float* __restrict__ C, int M, int N, int K)
{
    extern __shared__ __align__(16) char smem[];
    const uint32_t sb = smem_u32(smem);
    const int tid = threadIdx.x;
    const int wid = tid >> 5;
    const int lane = tid & 31;
    const int m0 = blockIdx.y * BM;
    const int n0 = blockIdx.x * BN;
    const int wm = (wid & 3) * 32;        // 4 m-warps
    const int wn = (wid >> 2) * 64;       // 2 n-warps

    float acc[2][8][4];
    #pragma unroll
    for (int mi = 0; mi < 2; mi++)
        #pragma unroll
        for (int ni = 0; ni < 8; ni++)
            #pragma unroll
            for (int e = 0; e < 4; e++) acc[mi][ni][e] = 0.f;

    // stage fill: 1024 x 16B chunks (A 128 rows x4, B 128 rows x4)
    auto fill = [&](int stage, int k0) {
        const uint32_t sbase = sb + stage * STAGE_B;
        #pragma unroll
        for (int it = 0; it < 4; it++) {
            int i = it * 256 + tid;
            const __half* src;
            uint32_t dst;
            if (i < 512) {
                int r = i >> 2, c = i & 3;
                src = Am + (size_t)(m0 + r) * K + k0 + c * 8;
                dst = sbase + r * ROWB + c * 16;
            } else {
                int j = i - 512;
                int r = j >> 2, c = j & 3;
                src = Bm + (size_t)(n0 + r) * K + k0 + c * 8;
                dst = sbase + A_TILE + r * ROWB + c * 16;
            }
            cpa16(dst, src);
        }
        CP_COMMIT();
    };

    const int nch = K / BKC;
    fill(0, 0);
    fill(1, BKC);

    const int lg = lane >> 3;
    const int lr = lane & 7;

    for (int c = 0; c < nch; c++) {
        if (c + 1 < nch) CP_WAIT1(); else CP_WAIT0();
        __syncthreads();

        if (c + 2 < nch) fill((c + 2) % NSTAGE, (c + 2) * BKC);

        const uint32_t sbase = sb + (c % NSTAGE) * STAGE_B;
        const uint32_t aT = sbase;
        const uint32_t bT = sbase + A_TILE;

        #pragma unroll
        for (int ks = 0; ks < 2; ks++) {
            const uint32_t koff = ks * 32;

            const uint32_t aoff = (lg & 1) * 8 * ROWB + (lg >> 1) * 16 + lr * ROWB + koff;
            uint32_t ah[2][4];
            #pragma unroll
            for (int mi = 0; mi < 2; mi++) {
                uint32_t ro = (wm + mi * 16) * ROWB + aoff;
                ldm_x4(ah[mi], aT + ro);
            }
            const uint32_t boff = (lg >> 1) * 8 * ROWB + (lg & 1) * 16 + lr * ROWB + koff;
            uint32_t bh[8][2];
            #pragma unroll
            for (int np = 0; np < 4; np++) {
                uint32_t ro = (wn + np * 16) * ROWB + boff;
                uint32_t t4[4];
                ldm_x4(t4, bT + ro);
                bh[2 * np][0] = t4[0]; bh[2 * np][1] = t4[1];
                bh[2 * np + 1][0] = t4[2]; bh[2 * np + 1][1] = t4[3];
            }

            #pragma unroll
            for (int mi = 0; mi < 2; mi++)
                #pragma unroll
                for (int ni = 0; ni < 8; ni++)
                    mma_f16(acc[mi][ni], ah[mi], bh[ni]);
        }
    }

    const int r4 = lane >> 2;
    const int k4 = lane & 3;
    #pragma unroll
    for (int mi = 0; mi < 2; mi++) {
        int r0 = m0 + wm + mi * 16 + r4;
        #pragma unroll
        for (int ni = 0; ni < 8; ni++) {
            int cc = n0 + wn + ni * 8 + k4 * 2;
            float2 v0 = {acc[mi][ni][0], acc[mi][ni][1]};
            float2 v1 = {acc[mi][ni][2], acc[mi][ni][3]};
            *(float2*)(C + (size_t)r0 * N + cc) = v0;
            *(float2*)(C + (size_t)(r0 + 8) * N + cc) = v1;
        }
    }
}

// ---------------------------------------------------------------------------
// RoPE + split: fp32 qkv -> Q fp16 hi/lo, K fp16 single, [b][h][s][d]
// ---------------------------------------------------------------------------
__global__ __launch_bounds__(256) void rope_split(const float* __restrict__ qkv,
                                                  __half* __restrict__ qh,
                                                  __half* __restrict__ ql,
                                                  __half* __restrict__ kk) {
    const int t = blockIdx.x;            // token
    const int b = t / SS, s = t % SS;
    const int tid = threadIdx.x;

    #pragma unroll
    for (int w = 0; w < 4; w++) {
        int idx = w * 256 + tid;          // (h, dpair)
        int h = idx >> 6, dp = idx & 63;

        float inv_freq = powf(10000.0f, -(float)dp * (1.0f / 64.0f));
        float ang = (float)s * inv_freq;
        float c = cosf(ang), sn = sinf(ang);

        const float* src = qkv + (size_t)t * QKV_N + h * DHH;
        size_t obase = ((size_t)(b * HH + h) * SS + s) * DHH;
        __half hh, ll;

        // q (split hi/lo)
        float x1 = src[dp], x2 = src[dp + 64];
        float r1 = x1 * c - x2 * sn;
        float r2 = x2 * c + x1 * sn;
        split2h(r1, hh, ll); qh[obase + dp] = hh;      ql[obase + dp] = ll;
        split2h(r2, hh, ll); qh[obase + dp + 64] = hh; ql[obase + dp + 64] = ll;

        // k (single fp16)
        x1 = src[DD + dp]; x2 = src[DD + dp + 64];
        r1 = x1 * c - x2 * sn;
        r2 = x2 * c + x1 * sn;
        kk[obase + dp]      = __float2half_rn(r1);
        kk[obase + dp + 64] = __float2half_rn(r2);
    }
}

// ---------------------------------------------------------------------------
// V transpose: fp32 qkv v-slice -> [b][h][d][s] fp16 single
// ---------------------------------------------------------------------------
__global__ __launch_bounds__(256) void v_transpose_h(const float* __restrict__ qkv,
                                                     __half* __restrict__ vt) {
    __shared__ float sm[64 * 132];
    const int s0 = blockIdx.x * 64;
    const int h  = blockIdx.y;
    const int b  = blockIdx.z;
    const int tid = threadIdx.x;

    #pragma unroll
    for (int i = 0; i < 32; i++) {
        int idx = i * 256 + tid;
        int sl = idx >> 7, d = idx & 127;
        sm[sl * 132 + d] = qkv[((size_t)(b * SS + s0 + sl)) * QKV_N + 2 * DD + h * DHH + d];
    }
    __syncthreads();

    const int d = tid >> 1;
    const int sh = (tid & 1) * 32;
    size_t row = ((size_t)(b * HH + h) * DHH + d) * SS + s0 + sh;
    #pragma unroll
    for (int j = 0; j < 32; j += 2) {
        float v0 = sm[(sh + j) * 132 + d];
        float v1 = sm[(sh + j + 1) * 132 + d];
        *(uint32_t*)(vt + row + j) = packh(__float2half_rn(v0), __float2half_rn(v1));
    }
}

// ---------------------------------------------------------------------------
// Flash attention v7 (proven fp16 2-term core); single-fp16 epilogue.
// ---------------------------------------------------------------------------
#define QROW 272
#define VROW 144
#define F7_KST(s) ((s) * 17408)            // K stage s (single fp16)
#define F7_V (2 * 17408)                   // 34816
#define FLASH7_SMEM (F7_V + 128 * VROW)    // 53248 bytes

__global__ __launch_bounds__(128) void flash7_kernel(
    const __half* __restrict__ qh, const __half* __restrict__ ql,
    const __half* __restrict__ kk, const __half* __restrict__ vt,
    __half* __restrict__ attn)
{
    extern __shared__ __align__(16) char smem[];
    const uint32_t sb = smem_u32(smem);

    const int qb = blockIdx.x;
    const int h  = blockIdx.y;
    const int b  = blockIdx.z;
    const int tid = threadIdx.x;
    const int wid = tid >> 5;
    const int lane = tid & 31;
    const int r4 = lane >> 2;
    const int k4 = lane & 3;

    const size_t bh = (size_t)(b * HH + h);
    const __half* qhp = qh + (bh * SS + qb * 64) * DHH;
    const __half* qlp = ql + (bh * SS + qb * 64) * DHH;

    for (int i = tid; i < 2048; i += 128) {
        int op = i >> 10, j = i & 1023;
        int row = j >> 4, c = j & 15;
        const __half* src = (op ? qlp : qhp) + row * DHH + c * 8;
        uint4 v = *(const uint4*)src;
        *(uint4*)(smem + op * 17408 + row * QROW + c * 16) = v;
    }
    __syncthreads();

    const int arow = wid * 16 + r4;
    uint32_t qah[8][4], qal[8][4];
    #pragma unroll
    for (int kb = 0; kb < 8; kb++) {
        const uint32_t koff = kb * 32 + k4 * 4;
        qah[kb][0] = *(const uint32_t*)(smem + arow * QROW + koff);
        qah[kb][1] = *(const uint32_t*)(smem + (arow + 8) * QROW + koff);
        qah[kb][2] = *(const uint32_t*)(smem + arow * QROW + koff + 16);
        qah[kb][3] = *(const uint32_t*)(smem + (arow + 8) * QROW + koff + 16);
        qal[kb][0] = *(const uint32_t*)(smem + 17408 + arow * QROW + koff);
        qal[kb][1] = *(const uint32_t*)(smem + 17408 + (arow + 8) * QROW + koff);
        qal[kb][2] = *(const uint32_t*)(smem + 17408 + arow * QROW + koff + 16);
        qal[kb][3] = *(const uint32_t*)(smem + 17408 + (arow + 8) * QROW + koff + 16);
    }
    __syncthreads();

    auto fillK = [&](int s, int kt) {
        const __half* khp = kk + (bh * SS + kt * 64) * DHH;
        const uint32_t kbase = sb + F7_KST(s);
        #pragma unroll
        for (int it = 0; it < 8; it++) {
            int i = it * 128 + tid;
            int row = i >> 4, c = i & 15;
            cpa16(kbase + row * QROW + c * 16, khp + row * DHH + c * 8);
        }
        CP_COMMIT();
    };
    auto fillV = [&](int kt) {
        const __half* vhp = vt + bh * DHH * SS + kt * 64;
        #pragma unroll
        for (int it = 0; it < 8; it++) {
            int i = it * 128 + tid;
            int d = i >> 3, c = i & 7;
            cpa16(sb + F7_V + d * VROW + c * 16, vhp + (size_t)d * SS + c * 8);
        }
        CP_COMMIT();
    };

    float oacc[16][4];
    #pragma unroll
    for (int n = 0; n < 16; n++)
        #pragma unroll
        for (int e = 0; e < 4; e++) oacc[n][e] = 0.f;

    float m0 = -1e30f, m1 = -1e30f, l0 = 0.f, l1 = 0.f;
    const float scale = 0.088388347648318447f;
    const int nkt = qb + 1;

    fillK(0, 0);
    fillV(0);

    for (int kt = 0; kt < nkt; kt++) {
        if (kt + 1 < nkt) {
            fillK((kt + 1) & 1, kt + 1);
            CP_WAIT1();
        } else {
            CP_WAIT0();
        }
        __syncthreads();

        const char* kst = smem + F7_KST(kt & 1);

        float sacc[8][4];
        #pragma unroll
        for (int n = 0; n < 8; n++)
            #pragma unroll
            for (int e = 0; e < 4; e++) sacc[n][e] = 0.f;

        #pragma unroll
        for (int kb = 0; kb < 8; kb++) {
            const uint32_t koff = kb * 32 + k4 * 4;
            #pragma unroll
            for (int ng = 0; ng < 8; ng++) {
                const uint32_t bro = (ng * 8 + r4) * QROW + koff;
                uint32_t bh2[2];
                bh2[0] = *(const uint32_t*)(kst + bro);
                bh2[1] = *(const uint32_t*)(kst + bro + 16);
                mma_f16(sacc[ng], qah[kb], bh2);
                mma_f16(sacc[ng], qal[kb], bh2);
            }
        }

        const int row0 = qb * 64 + wid * 16 + r4;
        if (kt == qb) {
            #pragma unroll
            for (int ng = 0; ng < 8; ng++) {
                int colb = kt * 64 + ng * 8 + k4 * 2;
                sacc[ng][0] = (colb     > row0)     ? -1e30f : sacc[ng][0] * scale;
                sacc[ng][1] = (colb + 1 > row0)     ? -1e30f : sacc[ng][1] * scale;
                sacc[ng][2] = (colb     > row0 + 8) ? -1e30f : sacc[ng][2] * scale;
                sacc[ng][3] = (colb + 1 > row0 + 8) ? -1e30f : sacc[ng][3] * scale;
            }
        } else {
            #pragma unroll
            for (int ng = 0; ng < 8; ng++)
                #pragma unroll
                for (int e = 0; e < 4; e++) sacc[ng][e] *= scale;
        }

        float mx0 = -1e30f, mx1 = -1e30f;
        #pragma unroll
        for (int ng = 0; ng < 8; ng++) {
            mx0 = fmaxf(mx0, fmaxf(sacc[ng][0], sacc[ng][1]));
            mx1 = fmaxf(mx1, fmaxf(sacc[ng][2], sacc[ng][3]));
        }
        mx0 = fmaxf(mx0, __shfl_xor_sync(0xffffffffu, mx0, 1));
        mx0 = fmaxf(mx0, __shfl_xor_sync(0xffffffffu, mx0, 2));
        mx1 = fmaxf(mx1, __shfl_xor_sync(0xffffffffu, mx1, 1));
        mx1 = fmaxf(mx1, __shfl_xor_sync(0xffffffffu, mx1, 2));

        float mn0 = fmaxf(m0, mx0), mn1 = fmaxf(m1, mx1);
        float c0 = __expf(m0 - mn0), c1 = __expf(m1 - mn1);
        m0 = mn0; m1 = mn1;

        float sum0 = 0.f, sum1 = 0.f;
        uint32_t ph2[8][2], pl2[8][2];
        #pragma unroll
        for (int ng = 0; ng < 8; ng++) {
            float p0 = __expf(sacc[ng][0] - m0);
            float p1 = __expf(sacc[ng][1] - m0);
            float p2 = __expf(sacc[ng][2] - m1);
            float p3 = __expf(sacc[ng][3] - m1);
            sum0 += p0 + p1; sum1 += p2 + p3;
            __half a, bq, cc, dd2, la, lb, lc, ld;
            split2h(p0, a, la); split2h(p1, bq, lb);
            split2h(p2, cc, lc); split2h(p3, dd2, ld);
            ph2[ng][0] = packh(a, bq);  ph2[ng][1] = packh(cc, dd2);
            pl2[ng][0] = packh(la, lb); pl2[ng][1] = packh(lc, ld);
        }
        sum0 += __shfl_xor_sync(0xffffffffu, sum0, 1);
        sum0 += __shfl_xor_sync(0xffffffffu, sum0, 2);
        sum1 += __shfl_xor_sync(0xffffffffu, sum1, 1);
        sum1 += __shfl_xor_sync(0xffffffffu, sum1, 2);
        l0 = l0 * c0 + sum0;
        l1 = l1 * c1 + sum1;

        #pragma unroll
        for (int n = 0; n < 16; n++) {
            oacc[n][0] *= c0; oacc[n][1] *= c0;
            oacc[n][2] *= c1; oacc[n][3] *= c1;
        }

        #pragma unroll
        for (int kb = 0; kb < 4; kb++) {
            uint32_t pa[4] = {ph2[2*kb][0], ph2[2*kb][1], ph2[2*kb+1][0], ph2[2*kb+1][1]};
            uint32_t pb[4] = {pl2[2*kb][0], pl2[2*kb][1], pl2[2*kb+1][0], pl2[2*kb+1][1]};
            const uint32_t koff = kb * 32 + k4 * 4;
            #pragma unroll
            for (int ng = 0; ng < 16; ng++) {
                const uint32_t vro = (ng * 8 + r4) * VROW + koff;
                uint32_t vh[2];
                vh[0] = *(const uint32_t*)(smem + F7_V + vro);
                vh[1] = *(const uint32_t*)(smem + F7_V + vro + 16);
                mma_f16(oacc[ng], pa, vh);
                mma_f16(oacc[ng], pb, vh);
            }
        }

        __syncthreads();
        if (kt + 1 < nkt) fillV(kt + 1);
    }

    const float inv0 = 1.0f / l0, inv1 = 1.0f / l1;
    const int grow0 = b * SS + qb * 64 + wid * 16 + r4;
    #pragma unroll
    for (int ng = 0; ng < 16; ng++) {
        size_t o0 = (size_t)grow0 * DD + h * DHH + ng * 8 + k4 * 2;
        size_t o1 = o0 + (size_t)8 * DD;
        float v0 = oacc[ng][0] * inv0, v1 = oacc[ng][1] * inv0;
        float v2 = oacc[ng][2] * inv1, v3 = oacc[ng][3] * inv1;
        *(uint32_t*)(attn + o0) = packh(__float2half_rn(v0), __float2half_rn(v1));
        *(uint32_t*)(attn + o1) = packh(__float2half_rn(v2), __float2half_rn(v3));
    }
}

// ---------------------------------------------------------------------------
// kernel_launch: inputs = [positions, hidden_states, w_qkv, w_out]
// ---------------------------------------------------------------------------
extern "C" void kernel_launch(void* const* d_in, const int* in_sizes, int n_in,
                              void* d_out, int out_size) {
    const float* hidden = (const float*)d_in[1];
    const float* w_qkv  = (const float*)d_in[2];
    const float* w_out  = (const float*)d_in[3];
    float* out = (float*)d_out;

    __half *x16, *wqT, *woT, *attn, *qhh, *qll, *kk, *vt;
    float* qkv;
    cudaGetSymbolAddress((void**)&x16, g_x16);
    cudaGetSymbolAddress((void**)&qkv, g_qkv);
    cudaGetSymbolAddress((void**)&wqT, g_wqkvT);
    cudaGetSymbolAddress((void**)&woT, g_woutT);
    cudaGetSymbolAddress((void**)&attn, g_attn);
    cudaGetSymbolAddress((void**)&qhh, g_qhh);
    cudaGetSymbolAddress((void**)&qll, g_qll);
    cudaGetSymbolAddress((void**)&kk,  g_kk);
    cudaGetSymbolAddress((void**)&vt,  g_vt);

    // 1) LayerNorm -> fp16
    ln_kernel<<<NTOK, 256>>>(hidden, x16);

    // 2) Weight transpose -> fp16
    dim3 tb(32, 8);
    transpose_h<<<dim3(QKV_N / 32, DD / 32), tb>>>(w_qkv, wqT, DD, QKV_N);
    transpose_h<<<dim3(DD / 32, DD / 32), tb>>>(w_out, woT, DD, DD);

    // 3) QKV projection: fp16 1-term GEMM, 2 CTAs/SM
    cudaFuncSetAttribute(gemm_f16, cudaFuncAttributeMaxDynamicSharedMemorySize, GEMM_SMEM);
    gemm_f16<<<dim3(QKV_N / BN, NTOK / BM), 256, GEMM_SMEM>>>(
        x16, wqT, qkv, NTOK, QKV_N, DD);

    // 4) RoPE + split Q (hi/lo) / K (single); V transpose (single)
    rope_split<<<NTOK, 256>>>(qkv, qhh, qll, kk);
    v_transpose_h<<<dim3(SS / 64, HH, BB), 256>>>(qkv, vt);

    // 5) Causal flash attention v7 (fp16 2-term core, single-fp16 output)
    cudaFuncSetAttribute(flash7_kernel, cudaFuncAttributeMaxDynamicSharedMemorySize,
                         FLASH7_SMEM);
    flash7_kernel<<<dim3(SS / 64, HH, BB), 128, FLASH7_SMEM>>>(
        qhh, qll, kk, vt, attn);

    // 6) Output projection: fp16 1-term GEMM, 2 CTAs/SM
    gemm_f16<<<dim3(DD / BN, NTOK / BM), 256, GEMM_SMEM>>>(
        attn, woT, out, NTOK, DD, DD);
}

// round 16
// speedup vs baseline: 2.4040x; 1.0090x over previous
#include <cuda_runtime.h>
#include <cuda_bf16.h>
#include <cuda_fp16.h>
#include <math.h>
#include <cstdint>

// ---------------------------------------------------------------------------
// Problem constants: B=2, S=2048, D=2048, H=16, DH=128
// ---------------------------------------------------------------------------
#define BB 2
#define SS 2048
#define DD 2048
#define HH 16
#define DHH 128
#define NTOK (BB * SS)          // 4096
#define QKV_N (3 * DD)          // 6144
#define LN_EPS 1e-5f

// ---------------------------------------------------------------------------
// Scratch (device globals; allocation forbidden)
// ---------------------------------------------------------------------------
__device__ __half g_x16[(size_t)NTOK * DD];         // LN out (fp16)
__device__ __half g_qkv16[(size_t)NTOK * QKV_N];    // qkv intermediate (fp16, 50 MB)
__device__ __half g_wqkvT[(size_t)QKV_N * DD];      // W_qkv^T (fp16)
__device__ __half g_woutT[(size_t)DD * DD];         // W_out^T (fp16)
__device__ __half g_attn[(size_t)NTOK * DD];        // attn out (fp16)
// attention operands
__device__ __half g_qq[(size_t)NTOK * DD];    // Q single fp16 [b][h][s][d]
__device__ __half g_kk[(size_t)NTOK * DD];    // K single fp16
__device__ __half g_vt[(size_t)NTOK * DD];    // V^T single fp16 [b][h][d][s]

// ---------------------------------------------------------------------------
// helpers
// ---------------------------------------------------------------------------
__device__ __forceinline__ uint32_t smem_u32(const void* p) {
    uint32_t a;
    asm("{ .reg .u64 t; cvta.to.shared.u64 t, %1; cvt.u32.u64 %0, t; }"
        : "=r"(a) : "l"(p));
    return a;
}

__device__ __forceinline__ void cpa16(uint32_t dst, const void* src) {
    asm volatile("cp.async.cg.shared.global [%0], [%1], 16;" :: "r"(dst), "l"(src) : "memory");
}
#define CP_COMMIT() asm volatile("cp.async.commit_group;" ::: "memory")
#define CP_WAIT1()  asm volatile("cp.async.wait_group 1;" ::: "memory")
#define CP_WAIT0()  asm volatile("cp.async.wait_group 0;" ::: "memory")

__device__ __forceinline__ void mma_f16(float* c, const uint32_t* a, const uint32_t* b) {
    asm volatile(
        "mma.sync.aligned.m16n8k16.row.col.f32.f16.f16.f32 "
        "{%0,%1,%2,%3}, {%4,%5,%6,%7}, {%8,%9}, {%0,%1,%2,%3};"
        : "+f"(c[0]), "+f"(c[1]), "+f"(c[2]), "+f"(c[3])
        : "r"(a[0]), "r"(a[1]), "r"(a[2]), "r"(a[3]), "r"(b[0]), "r"(b[1]));
}

__device__ __forceinline__ void ldm_x4(uint32_t* r, uint32_t addr) {
    asm volatile("ldmatrix.sync.aligned.m8n8.x4.shared.b16 {%0,%1,%2,%3}, [%4];"
        : "=r"(r[0]), "=r"(r[1]), "=r"(r[2]), "=r"(r[3]) : "r"(addr));
}

__device__ __forceinline__ void split2h(float v, __half& h, __half& l) {
    h = __float2half_rn(v);
    l = __float2half_rn(v - __half2float(h));
}

__device__ __forceinline__ uint32_t packh(__half a, __half b) {
    __half2 t(a, b);          // a = low element
    return *(uint32_t*)&t;
}

// ---------------------------------------------------------------------------
// LayerNorm -> fp16 output
// ---------------------------------------------------------------------------
__global__ __launch_bounds__(256) void ln_kernel(const float* __restrict__ x,
                                                 __half* __restrict__ y) {
    __shared__ float red_s[8], red_ss[8];
    __shared__ float sh_mu, sh_rstd;
    const int row = blockIdx.x;
    const int tid = threadIdx.x;
    const float* xr = x + (size_t)row * DD;

    float4 a = *(const float4*)(xr + tid * 4);
    float4 b = *(const float4*)(xr + 1024 + tid * 4);
    float s  = a.x + a.y + a.z + a.w + b.x + b.y + b.z + b.w;
    float ss = a.x*a.x + a.y*a.y + a.z*a.z + a.w*a.w
             + b.x*b.x + b.y*b.y + b.z*b.z + b.w*b.w;
    #pragma unroll
    for (int o = 16; o > 0; o >>= 1) {
        s  += __shfl_xor_sync(0xffffffffu, s, o);
        ss += __shfl_xor_sync(0xffffffffu, ss, o);
    }
    const int wid = tid >> 5, lane = tid & 31;
    if (lane == 0) { red_s[wid] = s; red_ss[wid] = ss; }
    __syncthreads();
    if (tid == 0) {
        float S = 0.f, SSq = 0.f;
        #pragma unroll
        for (int w = 0; w < 8; w++) { S += red_s[w]; SSq += red_ss[w]; }
        float mu = S * (1.0f / DD);
        float var = SSq * (1.0f / DD) - mu * mu;
        sh_mu = mu;
        sh_rstd = rsqrtf(var + LN_EPS);
    }
    __syncthreads();
    const float mu = sh_mu, rstd = sh_rstd;
    float va[8] = {a.x, a.y, a.z, a.w, b.x, b.y, b.z, b.w};
    #pragma unroll
    for (int e = 0; e < 8; e++) {
        float v = (va[e] - mu) * rstd;
        size_t col = (e < 4) ? (tid * 4 + e) : (1024 + tid * 4 + e - 4);
        y[(size_t)row * DD + col] = __float2half_rn(v);
    }
}

// ---------------------------------------------------------------------------
// Transpose + round: W[K][N] fp32 -> fp16 [N][K]
// ---------------------------------------------------------------------------
__global__ __launch_bounds__(256) void transpose_h(const float* __restrict__ W,
                                                   __half* __restrict__ out,
                                                   int K, int N) {
    __shared__ float t[32][33];
    int n = blockIdx.x * 32 + threadIdx.x;
    int k = blockIdx.y * 32 + threadIdx.y;
    #pragma unroll
    for (int i = 0; i < 4; i++)
        t[threadIdx.y + 8 * i][threadIdx.x] = W[(size_t)(k + 8 * i) * N + n];
    __syncthreads();
    int ko = blockIdx.y * 32 + threadIdx.x;
    int no = blockIdx.x * 32 + threadIdx.y;
    #pragma unroll
    for (int i = 0; i < 4; i++) {
        float v = t[threadIdx.x][threadIdx.y + 8 * i];
        out[(size_t)(no + 8 * i) * K + ko] = __float2half_rn(v);
    }
}

// ---------------------------------------------------------------------------
// fp16 1-term GEMM: CTA 128x128, 8 warps (4m x 2n), 3-stage ring, 2 CTAs/SM.
// OUT_HALF=1 stores fp16, else fp32.
// ---------------------------------------------------------------------------
#define BM 128
#define BN 128
#define BKC 32
#define ROWB 80
#define A_TILE (128 * ROWB)
#define B_TILE (128 * ROWB)
#define STAGE_B (A_TILE + B_TILE)
#define NSTAGE 3
#define GEMM_SMEM (NSTAGE * STAGE_B)     // 61440

template <int OUT_HALF>
__global__ __launch_bounds__(256, 2) void gemm_f16(
    const __half* __restrict__ Am, const __half* __restrict__ Bm,
    void* __restrict__ Cv, int M, int N, int K)
{
    extern __shared__ __align__(16) char smem[];
    const uint32_t sb = smem_u32(smem);
    const int tid = threadIdx.x;
    const int wid = tid >> 5;
    const int lane = tid & 31;
    const int m0 = blockIdx.y * BM;
    const int n0 = blockIdx.x * BN;
    const int wm = (wid & 3) * 32;
    const int wn = (wid >> 2) * 64;

    float acc[2][8][4];
    #pragma unroll
    for (int mi = 0; mi < 2; mi++)
        #pragma unroll
        for (int ni = 0; ni < 8; ni++)
            #pragma unroll
            for (int e = 0; e < 4; e++) acc[mi][ni][e] = 0.f;

    auto fill = [&](int stage, int k0) {
        const uint32_t sbase = sb + stage * STAGE_B;
        #pragma unroll
        for (int it = 0; it < 4; it++) {
            int i = it * 256 + tid;
            const __half* src;
            uint32_t dst;
            if (i < 512) {
                int r = i >> 2, c = i & 3;
                src = Am + (size_t)(m0 + r) * K + k0 + c * 8;
                dst = sbase + r * ROWB + c * 16;
            } else {
                int j = i - 512;
                int r = j >> 2, c = j & 3;
                src = Bm + (size_t)(n0 + r) * K + k0 + c * 8;
                dst = sbase + A_TILE + r * ROWB + c * 16;
            }
            cpa16(dst, src);
        }
        CP_COMMIT();
    };

    const int nch = K / BKC;
    fill(0, 0);
    fill(1, BKC);

    const int lg = lane >> 3;
    const int lr = lane & 7;

    for (int c = 0; c < nch; c++) {
        if (c + 1 < nch) CP_WAIT1(); else CP_WAIT0();
        __syncthreads();

        if (c + 2 < nch) fill((c + 2) % NSTAGE, (c + 2) * BKC);

        const uint32_t sbase = sb + (c % NSTAGE) * STAGE_B;
        const uint32_t aT = sbase;
        const uint32_t bT = sbase + A_TILE;

        #pragma unroll
        for (int ks = 0; ks < 2; ks++) {
            const uint32_t koff = ks * 32;

            const uint32_t aoff = (lg & 1) * 8 * ROWB + (lg >> 1) * 16 + lr * ROWB + koff;
            uint32_t ah[2][4];
            #pragma unroll
            for (int mi = 0; mi < 2; mi++) {
                uint32_t ro = (wm + mi * 16) * ROWB + aoff;
                ldm_x4(ah[mi], aT + ro);
            }
            const uint32_t boff = (lg >> 1) * 8 * ROWB + (lg & 1) * 16 + lr * ROWB + koff;
            uint32_t bh[8][2];
            #pragma unroll
            for (int np = 0; np < 4; np++) {
                uint32_t ro = (wn + np * 16) * ROWB + boff;
                uint32_t t4[4];
                ldm_x4(t4, bT + ro);
                bh[2 * np][0] = t4[0]; bh[2 * np][1] = t4[1];
                bh[2 * np + 1][0] = t4[2]; bh[2 * np + 1][1] = t4[3];
            }

            #pragma unroll
            for (int mi = 0; mi < 2; mi++)
                #pragma unroll
                for (int ni = 0; ni < 8; ni++)
                    mma_f16(acc[mi][ni], ah[mi], bh[ni]);
        }
    }

    const int r4 = lane >> 2;
    const int k4 = lane & 3;
    #pragma unroll
    for (int mi = 0; mi < 2; mi++) {
        int r0 = m0 + wm + mi * 16 + r4;
        #pragma unroll
        for (int ni = 0; ni < 8; ni++) {
            int cc = n0 + wn + ni * 8 + k4 * 2;
            if (OUT_HALF) {
                __half* C = (__half*)Cv;
                *(uint32_t*)(C + (size_t)r0 * N + cc) =
                    packh(__float2half_rn(acc[mi][ni][0]), __float2half_rn(acc[mi][ni][1]));
                *(uint32_t*)(C + (size_t)(r0 + 8) * N + cc) =
                    packh(__float2half_rn(acc[mi][ni][2]), __float2half_rn(acc[mi][ni][3]));
            } else {
                float* C = (float*)Cv;
                float2 v0 = {acc[mi][ni][0], acc[mi][ni][1]};
                float2 v1 = {acc[mi][ni][2], acc[mi][ni][3]};
                *(float2*)(C + (size_t)r0 * N + cc) = v0;
                *(float2*)(C + (size_t)(r0 + 8) * N + cc) = v1;
            }
        }
    }
}

// ---------------------------------------------------------------------------
// RoPE: fp16 qkv -> Q single fp16, K single fp16, [b][h][s][d]
// ---------------------------------------------------------------------------
__global__ __launch_bounds__(256) void rope_h(const __half* __restrict__ qkv16,
                                              __half* __restrict__ qq,
                                              __half* __restrict__ kk) {
    const int t = blockIdx.x;            // token
    const int b = t / SS, s = t % SS;
    const int tid = threadIdx.x;

    #pragma unroll
    for (int w = 0; w < 4; w++) {
        int idx = w * 256 + tid;          // (h, dpair)
        int h = idx >> 6, dp = idx & 63;

        float inv_freq = powf(10000.0f, -(float)dp * (1.0f / 64.0f));
        float ang = (float)s * inv_freq;
        float c = cosf(ang), sn = sinf(ang);

        const __half* src = qkv16 + (size_t)t * QKV_N + h * DHH;
        size_t obase = ((size_t)(b * HH + h) * SS + s) * DHH;

        // q
        float x1 = __half2float(src[dp]), x2 = __half2float(src[dp + 64]);
        qq[obase + dp]      = __float2half_rn(x1 * c - x2 * sn);
        qq[obase + dp + 64] = __float2half_rn(x2 * c + x1 * sn);

        // k
        x1 = __half2float(src[DD + dp]); x2 = __half2float(src[DD + dp + 64]);
        kk[obase + dp]      = __float2half_rn(x1 * c - x2 * sn);
        kk[obase + dp + 64] = __float2half_rn(x2 * c + x1 * sn);
    }
}

// ---------------------------------------------------------------------------
// V transpose: fp16 qkv v-slice -> [b][h][d][s] fp16
// ---------------------------------------------------------------------------
__global__ __launch_bounds__(256) void v_transpose_h(const __half* __restrict__ qkv16,
                                                     __half* __restrict__ vt) {
    __shared__ __half sm[64 * 136];
    const int s0 = blockIdx.x * 64;
    const int h  = blockIdx.y;
    const int b  = blockIdx.z;
    const int tid = threadIdx.x;

    #pragma unroll
    for (int i = 0; i < 32; i++) {
        int idx = i * 256 + tid;
        int sl = idx >> 7, d = idx & 127;
        sm[sl * 136 + d] = qkv16[((size_t)(b * SS + s0 + sl)) * QKV_N + 2 * DD + h * DHH + d];
    }
    __syncthreads();

    const int d = tid >> 1;
    const int sh = (tid & 1) * 32;
    size_t row = ((size_t)(b * HH + h) * DHH + d) * SS + s0 + sh;
    #pragma unroll
    for (int j = 0; j < 32; j += 2) {
        __half v0 = sm[(sh + j) * 136 + d];
        __half v1 = sm[(sh + j + 1) * 136 + d];
        *(uint32_t*)(vt + row + j) = packh(v0, v1);
    }
}

// ---------------------------------------------------------------------------
// Flash attention v8: Q single fp16 (1-term QK), P split + V single (2-term PV).
// Reg-resident Q, double-buffered K, prefetched V. Same pipeline as flash7.
// ---------------------------------------------------------------------------
#define QROW 272
#define VROW 144
#define F8_KST(s) ((s) * 17408)            // K stage s
#define F8_V (2 * 17408)                   // 34816
#define FLASH8_SMEM (F8_V + 128 * VROW)    // 53248 bytes

__global__ __launch_bounds__(128) void flash8_kernel(
    const __half* __restrict__ qq, const __half* __restrict__ kk,
    const __half* __restrict__ vt, __half* __restrict__ attn)
{
    extern __shared__ __align__(16) char smem[];
    const uint32_t sb = smem_u32(smem);

    const int qb = blockIdx.x;
    const int h  = blockIdx.y;
    const int b  = blockIdx.z;
    const int tid = threadIdx.x;
    const int wid = tid >> 5;
    const int lane = tid & 31;
    const int r4 = lane >> 2;
    const int k4 = lane & 3;

    const size_t bh = (size_t)(b * HH + h);
    const __half* qp = qq + (bh * SS + qb * 64) * DHH;

    // ---- prologue: stage Q into K-stage-0 area, read frags to registers ----
    for (int i = tid; i < 1024; i += 128) {
        int row = i >> 4, c = i & 15;
        uint4 v = *(const uint4*)(qp + row * DHH + c * 8);
        *(uint4*)(smem + row * QROW + c * 16) = v;
    }
    __syncthreads();

    const int arow = wid * 16 + r4;
    uint32_t qa[8][4];
    #pragma unroll
    for (int kb = 0; kb < 8; kb++) {
        const uint32_t koff = kb * 32 + k4 * 4;
        qa[kb][0] = *(const uint32_t*)(smem + arow * QROW + koff);
        qa[kb][1] = *(const uint32_t*)(smem + (arow + 8) * QROW + koff);
        qa[kb][2] = *(const uint32_t*)(smem + arow * QROW + koff + 16);
        qa[kb][3] = *(const uint32_t*)(smem + (arow + 8) * QROW + koff + 16);
    }
    __syncthreads();   // Q consumed before cp.async overwrites the area

    auto fillK = [&](int s, int kt) {
        const __half* khp = kk + (bh * SS + kt * 64) * DHH;
        const uint32_t kbase = sb + F8_KST(s);
        #pragma unroll
        for (int it = 0; it < 8; it++) {
            int i = it * 128 + tid;
            int row = i >> 4, c = i & 15;
            cpa16(kbase + row * QROW + c * 16, khp + row * DHH + c * 8);
        }
        CP_COMMIT();
    };
    auto fillV = [&](int kt) {
        const __half* vhp = vt + bh * DHH * SS + kt * 64;
        #pragma unroll
        for (int it = 0; it < 8; it++) {
            int i = it * 128 + tid;
            int d = i >> 3, c = i & 7;
            cpa16(sb + F8_V + d * VROW + c * 16, vhp + (size_t)d * SS + c * 8);
        }
        CP_COMMIT();
    };

    float oacc[16][4];
    #pragma unroll
    for (int n = 0; n < 16; n++)
        #pragma unroll
        for (int e = 0; e < 4; e++) oacc[n][e] = 0.f;

    float m0 = -1e30f, m1 = -1e30f, l0 = 0.f, l1 = 0.f;
    const float scale = 0.088388347648318447f;
    const int nkt = qb + 1;

    fillK(0, 0);
    fillV(0);

    for (int kt = 0; kt < nkt; kt++) {
        if (kt + 1 < nkt) {
            fillK((kt + 1) & 1, kt + 1);
            CP_WAIT1();
        } else {
            CP_WAIT0();
        }
        __syncthreads();

        const char* kst = smem + F8_KST(kt & 1);

        // ---- S = Q K^T (1-term fp16) ----
        float sacc[8][4];
        #pragma unroll
        for (int n = 0; n < 8; n++)
            #pragma unroll
            for (int e = 0; e < 4; e++) sacc[n][e] = 0.f;

        #pragma unroll
        for (int kb = 0; kb < 8; kb++) {
            const uint32_t koff = kb * 32 + k4 * 4;
            #pragma unroll
            for (int ng = 0; ng < 8; ng++) {
                const uint32_t bro = (ng * 8 + r4) * QROW + koff;
                uint32_t bh2[2];
                bh2[0] = *(const uint32_t*)(kst + bro);
                bh2[1] = *(const uint32_t*)(kst + bro + 16);
                mma_f16(sacc[ng], qa[kb], bh2);
            }
        }

        const int row0 = qb * 64 + wid * 16 + r4;
        if (kt == qb) {
            #pragma unroll
            for (int ng = 0; ng < 8; ng++) {
                int colb = kt * 64 + ng * 8 + k4 * 2;
                sacc[ng][0] = (colb     > row0)     ? -1e30f : sacc[ng][0] * scale;
                sacc[ng][1] = (colb + 1 > row0)     ? -1e30f : sacc[ng][1] * scale;
                sacc[ng][2] = (colb     > row0 + 8) ? -1e30f : sacc[ng][2] * scale;
                sacc[ng][3] = (colb + 1 > row0 + 8) ? -1e30f : sacc[ng][3] * scale;
            }
        } else {
            #pragma unroll
            for (int ng = 0; ng < 8; ng++)
                #pragma unroll
                for (int e = 0; e < 4; e++) sacc[ng][e] *= scale;
        }

        float mx0 = -1e30f, mx1 = -1e30f;
        #pragma unroll
        for (int ng = 0; ng < 8; ng++) {
            mx0 = fmaxf(mx0, fmaxf(sacc[ng][0], sacc[ng][1]));
            mx1 = fmaxf(mx1, fmaxf(sacc[ng][2], sacc[ng][3]));
        }
        mx0 = fmaxf(mx0, __shfl_xor_sync(0xffffffffu, mx0, 1));
        mx0 = fmaxf(mx0, __shfl_xor_sync(0xffffffffu, mx0, 2));
        mx1 = fmaxf(mx1, __shfl_xor_sync(0xffffffffu, mx1, 1));
        mx1 = fmaxf(mx1, __shfl_xor_sync(0xffffffffu, mx1, 2));

        float mn0 = fmaxf(m0, mx0), mn1 = fmaxf(m1, mx1);
        float c0 = __expf(m0 - mn0), c1 = __expf(m1 - mn1);
        m0 = mn0; m1 = mn1;

        float sum0 = 0.f, sum1 = 0.f;
        uint32_t ph2[8][2], pl2[8][2];
        #pragma unroll
        for (int ng = 0; ng < 8; ng++) {
            float p0 = __expf(sacc[ng][0] - m0);
            float p1 = __expf(sacc[ng][1] - m0);
            float p2 = __expf(sacc[ng][2] - m1);
            float p3 = __expf(sacc[ng][3] - m1);
            sum0 += p0 + p1; sum1 += p2 + p3;
            __half a, bq, cc, dd2, la, lb, lc, ld;
            split2h(p0, a, la); split2h(p1, bq, lb);
            split2h(p2, cc, lc); split2h(p3, dd2, ld);
            ph2[ng][0] = packh(a, bq);  ph2[ng][1] = packh(cc, dd2);
            pl2[ng][0] = packh(la, lb); pl2[ng][1] = packh(lc, ld);
        }
        sum0 += __shfl_xor_sync(0xffffffffu, sum0, 1);
        sum0 += __shfl_xor_sync(0xffffffffu, sum0, 2);
        sum1 += __shfl_xor_sync(0xffffffffu, sum1, 1);
        sum1 += __shfl_xor_sync(0xffffffffu, sum1, 2);
        l0 = l0 * c0 + sum0;
        l1 = l1 * c1 + sum1;

        #pragma unroll
        for (int n = 0; n < 16; n++) {
            oacc[n][0] *= c0; oacc[n][1] *= c0;
            oacc[n][2] *= c1; oacc[n][3] *= c1;
        }

        // ---- O += P V (P split 2-term, V single) ----
        #pragma unroll
        for (int kb = 0; kb < 4; kb++) {
            uint32_t pa[4] = {ph2[2*kb][0], ph2[2*kb][1], ph2[2*kb+1][0], ph2[2*kb+1][1]};
            uint32_t pb[4] = {pl2[2*kb][0], pl2[2*kb][1], pl2[2*kb+1][0], pl2[2*kb+1][1]};
            const uint32_t koff = kb * 32 + k4 * 4;
            #pragma unroll
            for (int ng = 0; ng < 16; ng++) {
                const uint32_t vro = (ng * 8 + r4) * VROW + koff;
                uint32_t vh[2];
                vh[0] = *(const uint32_t*)(smem + F8_V + vro);
                vh[1] = *(const uint32_t*)(smem + F8_V + vro + 16);
                mma_f16(oacc[ng], pa, vh);
                mma_f16(oacc[ng], pb, vh);
            }
        }

        __syncthreads();
        if (kt + 1 < nkt) fillV(kt + 1);
    }

    // ---- epilogue: normalize, round to fp16, store ----
    const float inv0 = 1.0f / l0, inv1 = 1.0f / l1;
    const int grow0 = b * SS + qb * 64 + wid * 16 + r4;
    #pragma unroll
    for (int ng = 0; ng < 16; ng++) {
        size_t o0 = (size_t)grow0 * DD + h * DHH + ng * 8 + k4 * 2;
        size_t o1 = o0 + (size_t)8 * DD;
        float v0 = oacc[ng][0] * inv0, v1 = oacc[ng][1] * inv0;
        float v2 = oacc[ng][2] * inv1, v3 = oacc[ng][3] * inv1;
        *(uint32_t*)(attn + o0) = packh(__float2half_rn(v0), __float2half_rn(v1));
        *(uint32_t*)(attn + o1) = packh(__float2half_rn(v2), __float2half_rn(v3));
    }
}

// ---------------------------------------------------------------------------
// kernel_launch: inputs = [positions, hidden_states, w_qkv, w_out]
// ---------------------------------------------------------------------------
extern "C" void kernel_launch(void* const* d_in, const int* in_sizes, int n_in,
                              void* d_out, int out_size) {
    const float* hidden = (const float*)d_in[1];
    const float* w_qkv  = (const float*)d_in[2];
    const float* w_out  = (const float*)d_in[3];
    float* out = (float*)d_out;

    __half *x16, *qkv16, *wqT, *woT, *attn, *qq, *kk, *vt;
    cudaGetSymbolAddress((void**)&x16,   g_x16);
    cudaGetSymbolAddress((void**)&qkv16, g_qkv16);
    cudaGetSymbolAddress((void**)&wqT,   g_wqkvT);
    cudaGetSymbolAddress((void**)&woT,   g_woutT);
    cudaGetSymbolAddress((void**)&attn,  g_attn);
    cudaGetSymbolAddress((void**)&qq,    g_qq);
    cudaGetSymbolAddress((void**)&kk,    g_kk);
    cudaGetSymbolAddress((void**)&vt,    g_vt);

    // 1) LayerNorm -> fp16
    ln_kernel<<<NTOK, 256>>>(hidden, x16);

    // 2) Weight transpose -> fp16
    dim3 tb(32, 8);
    transpose_h<<<dim3(QKV_N / 32, DD / 32), tb>>>(w_qkv, wqT, DD, QKV_N);
    transpose_h<<<dim3(DD / 32, DD / 32), tb>>>(w_out, woT, DD, DD);

    // 3) QKV projection: fp16 GEMM, fp16 output
    cudaFuncSetAttribute(gemm_f16<1>, cudaFuncAttributeMaxDynamicSharedMemorySize, GEMM_SMEM);
    cudaFuncSetAttribute(gemm_f16<0>, cudaFuncAttributeMaxDynamicSharedMemorySize, GEMM_SMEM);
    gemm_f16<1><<<dim3(QKV_N / BN, NTOK / BM), 256, GEMM_SMEM>>>(
        x16, wqT, qkv16, NTOK, QKV_N, DD);

    // 4) RoPE (Q, K single fp16); V transpose
    rope_h<<<NTOK, 256>>>(qkv16, qq, kk);
    v_transpose_h<<<dim3(SS / 64, HH, BB), 256>>>(qkv16, vt);

    // 5) Causal flash attention v8 (1-term QK, 2-term PV)
    cudaFuncSetAttribute(flash8_kernel, cudaFuncAttributeMaxDynamicSharedMemorySize,
                         FLASH8_SMEM);
    flash8_kernel<<<dim3(SS / 64, HH, BB), 128, FLASH8_SMEM>>>(qq, kk, vt, attn);

    // 6) Output projection: fp16 GEMM, fp32 output
    gemm_f16<0><<<dim3(DD / BN, NTOK / BM), 256, GEMM_SMEM>>>(
        attn, woT, out, NTOK, DD, DD);
}

// round 17
// speedup vs baseline: 2.5016x; 1.0406x over previous
#include <cuda_runtime.h>
#include <cuda_bf16.h>
#include <cuda_fp16.h>
#include <math.h>
#include <cstdint>

// ---------------------------------------------------------------------------
// Problem constants: B=2, S=2048, D=2048, H=16, DH=128
// ---------------------------------------------------------------------------
#define BB 2
#define SS 2048
#define DD 2048
#define HH 16
#define DHH 128
#define NTOK (BB * SS)          // 4096
#define QKV_N (3 * DD)          // 6144
#define LN_EPS 1e-5f

// ---------------------------------------------------------------------------
// Scratch (device globals; allocation forbidden)
// ---------------------------------------------------------------------------
__device__ __half g_x16[(size_t)NTOK * DD];         // LN out (fp16)
__device__ __half g_qkv16[(size_t)NTOK * QKV_N];    // qkv intermediate (fp16)
__device__ __half g_wqkvT[(size_t)QKV_N * DD];      // W_qkv^T (fp16)
__device__ __half g_woutT[(size_t)DD * DD];         // W_out^T (fp16)
__device__ __half g_attn[(size_t)NTOK * DD];        // attn out (fp16)
// attention operands
__device__ __half g_qq[(size_t)NTOK * DD];    // Q single fp16 [b][h][s][d]
__device__ __half g_kk[(size_t)NTOK * DD];    // K single fp16
__device__ __half g_vt[(size_t)NTOK * DD];    // V^T single fp16 [b][h][d][s]

// ---------------------------------------------------------------------------
// helpers
// ---------------------------------------------------------------------------
__device__ __forceinline__ uint32_t smem_u32(const void* p) {
    uint32_t a;
    asm("{ .reg .u64 t; cvta.to.shared.u64 t, %1; cvt.u32.u64 %0, t; }"
        : "=r"(a) : "l"(p));
    return a;
}

__device__ __forceinline__ void cpa16(uint32_t dst, const void* src) {
    asm volatile("cp.async.cg.shared.global [%0], [%1], 16;" :: "r"(dst), "l"(src) : "memory");
}
#define CP_COMMIT() asm volatile("cp.async.commit_group;" ::: "memory")
#define CP_WAIT1()  asm volatile("cp.async.wait_group 1;" ::: "memory")
#define CP_WAIT0()  asm volatile("cp.async.wait_group 0;" ::: "memory")

__device__ __forceinline__ void mma_f16(float* c, const uint32_t* a, const uint32_t* b) {
    asm volatile(
        "mma.sync.aligned.m16n8k16.row.col.f32.f16.f16.f32 "
        "{%0,%1,%2,%3}, {%4,%5,%6,%7}, {%8,%9}, {%0,%1,%2,%3};"
        : "+f"(c[0]), "+f"(c[1]), "+f"(c[2]), "+f"(c[3])
        : "r"(a[0]), "r"(a[1]), "r"(a[2]), "r"(a[3]), "r"(b[0]), "r"(b[1]));
}

__device__ __forceinline__ void ldm_x4(uint32_t* r, uint32_t addr) {
    asm volatile("ldmatrix.sync.aligned.m8n8.x4.shared.b16 {%0,%1,%2,%3}, [%4];"
        : "=r"(r[0]), "=r"(r[1]), "=r"(r[2]), "=r"(r[3]) : "r"(addr));
}

__device__ __forceinline__ void split2h(float v, __half& h, __half& l) {
    h = __float2half_rn(v);
    l = __float2half_rn(v - __half2float(h));
}

__device__ __forceinline__ uint32_t packh(__half a, __half b) {
    __half2 t(a, b);          // a = low element
    return *(uint32_t*)&t;
}

// ---------------------------------------------------------------------------
// LayerNorm -> fp16 output
// ---------------------------------------------------------------------------
__global__ __launch_bounds__(256) void ln_kernel(const float* __restrict__ x,
                                                 __half* __restrict__ y) {
    __shared__ float red_s[8], red_ss[8];
    __shared__ float sh_mu, sh_rstd;
    const int row = blockIdx.x;
    const int tid = threadIdx.x;
    const float* xr = x + (size_t)row * DD;

    float4 a = *(const float4*)(xr + tid * 4);
    float4 b = *(const float4*)(xr + 1024 + tid * 4);
    float s  = a.x + a.y + a.z + a.w + b.x + b.y + b.z + b.w;
    float ss = a.x*a.x + a.y*a.y + a.z*a.z + a.w*a.w
             + b.x*b.x + b.y*b.y + b.z*b.z + b.w*b.w;
    #pragma unroll
    for (int o = 16; o > 0; o >>= 1) {
        s  += __shfl_xor_sync(0xffffffffu, s, o);
        ss += __shfl_xor_sync(0xffffffffu, ss, o);
    }
    const int wid = tid >> 5, lane = tid & 31;
    if (lane == 0) { red_s[wid] = s; red_ss[wid] = ss; }
    __syncthreads();
    if (tid == 0) {
        float S = 0.f, SSq = 0.f;
        #pragma unroll
        for (int w = 0; w < 8; w++) { S += red_s[w]; SSq += red_ss[w]; }
        float mu = S * (1.0f / DD);
        float var = SSq * (1.0f / DD) - mu * mu;
        sh_mu = mu;
        sh_rstd = rsqrtf(var + LN_EPS);
    }
    __syncthreads();
    const float mu = sh_mu, rstd = sh_rstd;
    float va[8] = {a.x, a.y, a.z, a.w, b.x, b.y, b.z, b.w};
    #pragma unroll
    for (int e = 0; e < 8; e++) {
        float v = (va[e] - mu) * rstd;
        size_t col = (e < 4) ? (tid * 4 + e) : (1024 + tid * 4 + e - 4);
        y[(size_t)row * DD + col] = __float2half_rn(v);
    }
}

// ---------------------------------------------------------------------------
// Transpose + round: W[K][N] fp32 -> fp16 [N][K]
// ---------------------------------------------------------------------------
__global__ __launch_bounds__(256) void transpose_h(const float* __restrict__ W,
                                                   __half* __restrict__ out,
                                                   int K, int N) {
    __shared__ float t[32][33];
    int n = blockIdx.x * 32 + threadIdx.x;
    int k = blockIdx.y * 32 + threadIdx.y;
    #pragma unroll
    for (int i = 0; i < 4; i++)
        t[threadIdx.y + 8 * i][threadIdx.x] = W[(size_t)(k + 8 * i) * N + n];
    __syncthreads();
    int ko = blockIdx.y * 32 + threadIdx.x;
    int no = blockIdx.x * 32 + threadIdx.y;
    #pragma unroll
    for (int i = 0; i < 4; i++) {
        float v = t[threadIdx.x][threadIdx.y + 8 * i];
        out[(size_t)(no + 8 * i) * K + ko] = __float2half_rn(v);
    }
}

// ---------------------------------------------------------------------------
// fp16 1-term GEMM: CTA 128x128, BK=64, 8 warps (4m x 2n), 3-stage ring,
// 2 CTAs/SM. Half the barriers of the BK=32 version.
// OUT_HALF=1 stores fp16, else fp32.
// ---------------------------------------------------------------------------
#define BM 128
#define BN 128
#define BKC 64
#define ROWB 144                         // 64 halves = 128B data + 16B pad
#define A_TILE (128 * ROWB)              // 18432
#define B_TILE (128 * ROWB)              // 18432
#define STAGE_B (A_TILE + B_TILE)        // 36864
#define NSTAGE 3
#define GEMM_SMEM (NSTAGE * STAGE_B)     // 110592 -> 2 CTAs/SM (221184 <= 228KB)

template <int OUT_HALF>
__global__ __launch_bounds__(256, 2) void gemm_f16(
    const __half* __restrict__ Am, const __half* __restrict__ Bm,
    void* __restrict__ Cv, int M, int N, int K)
{
    extern __shared__ __align__(16) char smem[];
    const uint32_t sb = smem_u32(smem);
    const int tid = threadIdx.x;
    const int wid = tid >> 5;
    const int lane = tid & 31;
    const int m0 = blockIdx.y * BM;
    const int n0 = blockIdx.x * BN;
    const int wm = (wid & 3) * 32;
    const int wn = (wid >> 2) * 64;

    float acc[2][8][4];
    #pragma unroll
    for (int mi = 0; mi < 2; mi++)
        #pragma unroll
        for (int ni = 0; ni < 8; ni++)
            #pragma unroll
            for (int e = 0; e < 4; e++) acc[mi][ni][e] = 0.f;

    // stage fill: 2048 x 16B chunks (A 128 rows x8, B 128 rows x8)
    auto fill = [&](int stage, int k0) {
        const uint32_t sbase = sb + stage * STAGE_B;
        #pragma unroll
        for (int it = 0; it < 8; it++) {
            int i = it * 256 + tid;
            const __half* src;
            uint32_t dst;
            if (i < 1024) {
                int r = i >> 3, c = i & 7;
                src = Am + (size_t)(m0 + r) * K + k0 + c * 8;
                dst = sbase + r * ROWB + c * 16;
            } else {
                int j = i - 1024;
                int r = j >> 3, c = j & 7;
                src = Bm + (size_t)(n0 + r) * K + k0 + c * 8;
                dst = sbase + A_TILE + r * ROWB + c * 16;
            }
            cpa16(dst, src);
        }
        CP_COMMIT();
    };

    const int nch = K / BKC;   // 32
    fill(0, 0);
    fill(1, BKC);

    const int lg = lane >> 3;
    const int lr = lane & 7;

    for (int c = 0; c < nch; c++) {
        if (c + 1 < nch) CP_WAIT1(); else CP_WAIT0();
        __syncthreads();

        if (c + 2 < nch) fill((c + 2) % NSTAGE, (c + 2) * BKC);

        const uint32_t sbase = sb + (c % NSTAGE) * STAGE_B;
        const uint32_t aT = sbase;
        const uint32_t bT = sbase + A_TILE;

        #pragma unroll
        for (int ks = 0; ks < 4; ks++) {
            const uint32_t koff = ks * 32;

            const uint32_t aoff = (lg & 1) * 8 * ROWB + (lg >> 1) * 16 + lr * ROWB + koff;
            uint32_t ah[2][4];
            #pragma unroll
            for (int mi = 0; mi < 2; mi++) {
                uint32_t ro = (wm + mi * 16) * ROWB + aoff;
                ldm_x4(ah[mi], aT + ro);
            }
            const uint32_t boff = (lg >> 1) * 8 * ROWB + (lg & 1) * 16 + lr * ROWB + koff;
            uint32_t bh[8][2];
            #pragma unroll
            for (int np = 0; np < 4; np++) {
                uint32_t ro = (wn + np * 16) * ROWB + boff;
                uint32_t t4[4];
                ldm_x4(t4, bT + ro);
                bh[2 * np][0] = t4[0]; bh[2 * np][1] = t4[1];
                bh[2 * np + 1][0] = t4[2]; bh[2 * np + 1][1] = t4[3];
            }

            #pragma unroll
            for (int mi = 0; mi < 2; mi++)
                #pragma unroll
                for (int ni = 0; ni < 8; ni++)
                    mma_f16(acc[mi][ni], ah[mi], bh[ni]);
        }
    }

    const int r4 = lane >> 2;
    const int k4 = lane & 3;
    #pragma unroll
    for (int mi = 0; mi < 2; mi++) {
        int r0 = m0 + wm + mi * 16 + r4;
        #pragma unroll
        for (int ni = 0; ni < 8; ni++) {
            int cc = n0 + wn + ni * 8 + k4 * 2;
            if (OUT_HALF) {
                __half* C = (__half*)Cv;
                *(uint32_t*)(C + (size_t)r0 * N + cc) =
                    packh(__float2half_rn(acc[mi][ni][0]), __float2half_rn(acc[mi][ni][1]));
                *(uint32_t*)(C + (size_t)(r0 + 8) * N + cc) =
                    packh(__float2half_rn(acc[mi][ni][2]), __float2half_rn(acc[mi][ni][3]));
            } else {
                float* C = (float*)Cv;
                float2 v0 = {acc[mi][ni][0], acc[mi][ni][1]};
                float2 v1 = {acc[mi][ni][2], acc[mi][ni][3]};
                *(float2*)(C + (size_t)r0 * N + cc) = v0;
                *(float2*)(C + (size_t)(r0 + 8) * N + cc) = v1;
            }
        }
    }
}

// ---------------------------------------------------------------------------
// RoPE: fp16 qkv -> Q single fp16, K single fp16, [b][h][s][d]
// inv_freq via __expf (MUFU); sincosf kept for accuracy.
// ---------------------------------------------------------------------------
__global__ __launch_bounds__(256) void rope_h(const __half* __restrict__ qkv16,
                                              __half* __restrict__ qq,
                                              __half* __restrict__ kk) {
    const int t = blockIdx.x;            // token
    const int b = t / SS, s = t % SS;
    const int tid = threadIdx.x;

    #pragma unroll
    for (int w = 0; w < 4; w++) {
        int idx = w * 256 + tid;          // (h, dpair)
        int h = idx >> 6, dp = idx & 63;

        // inv_freq = 10000^(-dp/64) = exp(-dp * ln(10000)/64)
        float inv_freq = __expf((float)dp * -0.14391156831212787f);
        float ang = (float)s * inv_freq;
        float c, sn;
        sincosf(ang, &sn, &c);

        const __half* src = qkv16 + (size_t)t * QKV_N + h * DHH;
        size_t obase = ((size_t)(b * HH + h) * SS + s) * DHH;

        // q
        float x1 = __half2float(src[dp]), x2 = __half2float(src[dp + 64]);
        qq[obase + dp]      = __float2half_rn(x1 * c - x2 * sn);
        qq[obase + dp + 64] = __float2half_rn(x2 * c + x1 * sn);

        // k
        x1 = __half2float(src[DD + dp]); x2 = __half2float(src[DD + dp + 64]);
        kk[obase + dp]      = __float2half_rn(x1 * c - x2 * sn);
        kk[obase + dp + 64] = __float2half_rn(x2 * c + x1 * sn);
    }
}

// ---------------------------------------------------------------------------
// V transpose: fp16 qkv v-slice -> [b][h][d][s] fp16
// ---------------------------------------------------------------------------
__global__ __launch_bounds__(256) void v_transpose_h(const __half* __restrict__ qkv16,
                                                     __half* __restrict__ vt) {
    __shared__ __half sm[64 * 136];
    const int s0 = blockIdx.x * 64;
    const int h  = blockIdx.y;
    const int b  = blockIdx.z;
    const int tid = threadIdx.x;

    #pragma unroll
    for (int i = 0; i < 32; i++) {
        int idx = i * 256 + tid;
        int sl = idx >> 7, d = idx & 127;
        sm[sl * 136 + d] = qkv16[((size_t)(b * SS + s0 + sl)) * QKV_N + 2 * DD + h * DHH + d];
    }
    __syncthreads();

    const int d = tid >> 1;
    const int sh = (tid & 1) * 32;
    size_t row = ((size_t)(b * HH + h) * DHH + d) * SS + s0 + sh;
    #pragma unroll
    for (int j = 0; j < 32; j += 2) {
        __half v0 = sm[(sh + j) * 136 + d];
        __half v1 = sm[(sh + j + 1) * 136 + d];
        *(uint32_t*)(vt + row + j) = packh(v0, v1);
    }
}

// ---------------------------------------------------------------------------
// Flash attention v8 (proven): 1-term QK, 2-term PV, reg-resident Q,
// double-buffered K, prefetched V.
// ---------------------------------------------------------------------------
#define QROW 272
#define VROW 144
#define F8_KST(s) ((s) * 17408)            // K stage s
#define F8_V (2 * 17408)                   // 34816
#define FLASH8_SMEM (F8_V + 128 * VROW)    // 53248 bytes

__global__ __launch_bounds__(128) void flash8_kernel(
    const __half* __restrict__ qq, const __half* __restrict__ kk,
    const __half* __restrict__ vt, __half* __restrict__ attn)
{
    extern __shared__ __align__(16) char smem[];
    const uint32_t sb = smem_u32(smem);

    const int qb = blockIdx.x;
    const int h  = blockIdx.y;
    const int b  = blockIdx.z;
    const int tid = threadIdx.x;
    const int wid = tid >> 5;
    const int lane = tid & 31;
    const int r4 = lane >> 2;
    const int k4 = lane & 3;

    const size_t bh = (size_t)(b * HH + h);
    const __half* qp = qq + (bh * SS + qb * 64) * DHH;

    for (int i = tid; i < 1024; i += 128) {
        int row = i >> 4, c = i & 15;
        uint4 v = *(const uint4*)(qp + row * DHH + c * 8);
        *(uint4*)(smem + row * QROW + c * 16) = v;
    }
    __syncthreads();

    const int arow = wid * 16 + r4;
    uint32_t qa[8][4];
    #pragma unroll
    for (int kb = 0; kb < 8; kb++) {
        const uint32_t koff = kb * 32 + k4 * 4;
        qa[kb][0] = *(const uint32_t*)(smem + arow * QROW + koff);
        qa[kb][1] = *(const uint32_t*)(smem + (arow + 8) * QROW + koff);
        qa[kb][2] = *(const uint32_t*)(smem + arow * QROW + koff + 16);
        qa[kb][3] = *(const uint32_t*)(smem + (arow + 8) * QROW + koff + 16);
    }
    __syncthreads();

    auto fillK = [&](int s, int kt) {
        const __half* khp = kk + (bh * SS + kt * 64) * DHH;
        const uint32_t kbase = sb + F8_KST(s);
        #pragma unroll
        for (int it = 0; it < 8; it++) {
            int i = it * 128 + tid;
            int row = i >> 4, c = i & 15;
            cpa16(kbase + row * QROW + c * 16, khp + row * DHH + c * 8);
        }
        CP_COMMIT();
    };
    auto fillV = [&](int kt) {
        const __half* vhp = vt + bh * DHH * SS + kt * 64;
        #pragma unroll
        for (int it = 0; it < 8; it++) {
            int i = it * 128 + tid;
            int d = i >> 3, c = i & 7;
            cpa16(sb + F8_V + d * VROW + c * 16, vhp + (size_t)d * SS + c * 8);
        }
        CP_COMMIT();
    };

    float oacc[16][4];
    #pragma unroll
    for (int n = 0; n < 16; n++)
        #pragma unroll
        for (int e = 0; e < 4; e++) oacc[n][e] = 0.f;

    float m0 = -1e30f, m1 = -1e30f, l0 = 0.f, l1 = 0.f;
    const float scale = 0.088388347648318447f;
    const int nkt = qb + 1;

    fillK(0, 0);
    fillV(0);

    for (int kt = 0; kt < nkt; kt++) {
        if (kt + 1 < nkt) {
            fillK((kt + 1) & 1, kt + 1);
            CP_WAIT1();
        } else {
            CP_WAIT0();
        }
        __syncthreads();

        const char* kst = smem + F8_KST(kt & 1);

        float sacc[8][4];
        #pragma unroll
        for (int n = 0; n < 8; n++)
            #pragma unroll
            for (int e = 0; e < 4; e++) sacc[n][e] = 0.f;

        #pragma unroll
        for (int kb = 0; kb < 8; kb++) {
            const uint32_t koff = kb * 32 + k4 * 4;
            #pragma unroll
            for (int ng = 0; ng < 8; ng++) {
                const uint32_t bro = (ng * 8 + r4) * QROW + koff;
                uint32_t bh2[2];
                bh2[0] = *(const uint32_t*)(kst + bro);
                bh2[1] = *(const uint32_t*)(kst + bro + 16);
                mma_f16(sacc[ng], qa[kb], bh2);
            }
        }

        const int row0 = qb * 64 + wid * 16 + r4;
        if (kt == qb) {
            #pragma unroll
            for (int ng = 0; ng < 8; ng++) {
                int colb = kt * 64 + ng * 8 + k4 * 2;
                sacc[ng][0] = (colb     > row0)     ? -1e30f : sacc[ng][0] * scale;
                sacc[ng][1] = (colb + 1 > row0)     ? -1e30f : sacc[ng][1] * scale;
                sacc[ng][2] = (colb     > row0 + 8) ? -1e30f : sacc[ng][2] * scale;
                sacc[ng][3] = (colb + 1 > row0 + 8) ? -1e30f : sacc[ng][3] * scale;
            }
        } else {
            #pragma unroll
            for (int ng = 0; ng < 8; ng++)
                #pragma unroll
                for (int e = 0; e < 4; e++) sacc[ng][e] *= scale;
        }

        float mx0 = -1e30f, mx1 = -1e30f;
        #pragma unroll
        for (int ng = 0; ng < 8; ng++) {
            mx0 = fmaxf(mx0, fmaxf(sacc[ng][0], sacc[ng][1]));
            mx1 = fmaxf(mx1, fmaxf(sacc[ng][2], sacc[ng][3]));
        }
        mx0 = fmaxf(mx0, __shfl_xor_sync(0xffffffffu, mx0, 1));
        mx0 = fmaxf(mx0, __shfl_xor_sync(0xffffffffu, mx0, 2));
        mx1 = fmaxf(mx1, __shfl_xor_sync(0xffffffffu, mx1, 1));
        mx1 = fmaxf(mx1, __shfl_xor_sync(0xffffffffu, mx1, 2));

        float mn0 = fmaxf(m0, mx0), mn1 = fmaxf(m1, mx1);
        float c0 = __expf(m0 - mn0), c1 = __expf(m1 - mn1);
        m0 = mn0; m1 = mn1;

        float sum0 = 0.f, sum1 = 0.f;
        uint32_t ph2[8][2], pl2[8][2];
        #pragma unroll
        for (int ng = 0; ng < 8; ng++) {
            float p0 = __expf(sacc[ng][0] - m0);
            float p1 = __expf(sacc[ng][1] - m0);
            float p2 = __expf(sacc[ng][2] - m1);
            float p3 = __expf(sacc[ng][3] - m1);
            sum0 += p0 + p1; sum1 += p2 + p3;
            __half a, bq, cc, dd2, la, lb, lc, ld;
            split2h(p0, a, la); split2h(p1, bq, lb);
            split2h(p2, cc, lc); split2h(p3, dd2, ld);
            ph2[ng][0] = packh(a, bq);  ph2[ng][1] = packh(cc, dd2);
            pl2[ng][0] = packh(la, lb); pl2[ng][1] = packh(lc, ld);
        }
        sum0 += __shfl_xor_sync(0xffffffffu, sum0, 1);
        sum0 += __shfl_xor_sync(0xffffffffu, sum0, 2);
        sum1 += __shfl_xor_sync(0xffffffffu, sum1, 1);
        sum1 += __shfl_xor_sync(0xffffffffu, sum1, 2);
        l0 = l0 * c0 + sum0;
        l1 = l1 * c1 + sum1;

        #pragma unroll
        for (int n = 0; n < 16; n++) {
            oacc[n][0] *= c0; oacc[n][1] *= c0;
            oacc[n][2] *= c1; oacc[n][3] *= c1;
        }

        #pragma unroll
        for (int kb = 0; kb < 4; kb++) {
            uint32_t pa[4] = {ph2[2*kb][0], ph2[2*kb][1], ph2[2*kb+1][0], ph2[2*kb+1][1]};
            uint32_t pb[4] = {pl2[2*kb][0], pl2[2*kb][1], pl2[2*kb+1][0], pl2[2*kb+1][1]};
            const uint32_t koff = kb * 32 + k4 * 4;
            #pragma unroll
            for (int ng = 0; ng < 16; ng++) {
                const uint32_t vro = (ng * 8 + r4) * VROW + koff;
                uint32_t vh[2];
                vh[0] = *(const uint32_t*)(smem + F8_V + vro);
                vh[1] = *(const uint32_t*)(smem + F8_V + vro + 16);
                mma_f16(oacc[ng], pa, vh);
                mma_f16(oacc[ng], pb, vh);
            }
        }

        __syncthreads();
        if (kt + 1 < nkt) fillV(kt + 1);
    }

    const float inv0 = 1.0f / l0, inv1 = 1.0f / l1;
    const int grow0 = b * SS + qb * 64 + wid * 16 + r4;
    #pragma unroll
    for (int ng = 0; ng < 16; ng++) {
        size_t o0 = (size_t)grow0 * DD + h * DHH + ng * 8 + k4 * 2;
        size_t o1 = o0 + (size_t)8 * DD;
        float v0 = oacc[ng][0] * inv0, v1 = oacc[ng][1] * inv0;
        float v2 = oacc[ng][2] * inv1, v3 = oacc[ng][3] * inv1;
        *(uint32_t*)(attn + o0) = packh(__float2half_rn(v0), __float2half_rn(v1));
        *(uint32_t*)(attn + o1) = packh(__float2half_rn(v2), __float2half_rn(v3));
    }
}

// ---------------------------------------------------------------------------
// kernel_launch: inputs = [positions, hidden_states, w_qkv, w_out]
// ---------------------------------------------------------------------------
extern "C" void kernel_launch(void* const* d_in, const int* in_sizes, int n_in,
                              void* d_out, int out_size) {
    const float* hidden = (const float*)d_in[1];
    const float* w_qkv  = (const float*)d_in[2];
    const float* w_out  = (const float*)d_in[3];
    float* out = (float*)d_out;

    __half *x16, *qkv16, *wqT, *woT, *attn, *qq, *kk, *vt;
    cudaGetSymbolAddress((void**)&x16,   g_x16);
    cudaGetSymbolAddress((void**)&qkv16, g_qkv16);
    cudaGetSymbolAddress((void**)&wqT,   g_wqkvT);
    cudaGetSymbolAddress((void**)&woT,   g_woutT);
    cudaGetSymbolAddress((void**)&attn,  g_attn);
    cudaGetSymbolAddress((void**)&qq,    g_qq);
    cudaGetSymbolAddress((void**)&kk,    g_kk);
    cudaGetSymbolAddress((void**)&vt,    g_vt);

    // 1) LayerNorm -> fp16
    ln_kernel<<<NTOK, 256>>>(hidden, x16);

    // 2) Weight transpose -> fp16
    dim3 tb(32, 8);
    transpose_h<<<dim3(QKV_N / 32, DD / 32), tb>>>(w_qkv, wqT, DD, QKV_N);
    transpose_h<<<dim3(DD / 32, DD / 32), tb>>>(w_out, woT, DD, DD);

    // 3) QKV projection: fp16 GEMM (BK=64), fp16 output
    cudaFuncSetAttribute(gemm_f16<1>, cudaFuncAttributeMaxDynamicSharedMemorySize, GEMM_SMEM);
    cudaFuncSetAttribute(gemm_f16<0>, cudaFuncAttributeMaxDynamicSharedMemorySize, GEMM_SMEM);
    gemm_f16<1><<<dim3(QKV_N / BN, NTOK / BM), 256, GEMM_SMEM>>>(
        x16, wqT, qkv16, NTOK, QKV_N, DD);

    // 4) RoPE (Q, K single fp16); V transpose
    rope_h<<<NTOK, 256>>>(qkv16, qq, kk);
    v_transpose_h<<<dim3(SS / 64, HH, BB), 256>>>(qkv16, vt);

    // 5) Causal flash attention v8 (1-term QK, 2-term PV)
    cudaFuncSetAttribute(flash8_kernel, cudaFuncAttributeMaxDynamicSharedMemorySize,
                         FLASH8_SMEM);
    flash8_kernel<<<dim3(SS / 64, HH, BB), 128, FLASH8_SMEM>>>(qq, kk, vt, attn);

    // 6) Output projection: fp16 GEMM (BK=64), fp32 output
    gemm_f16<0><<<dim3(DD / BN, NTOK / BM), 256, GEMM_SMEM>>>(
        attn, woT, out, NTOK, DD, DD);
}